// round 7
// baseline (speedup 1.0000x reference)
#include <cuda_runtime.h>
#include <cuda_bf16.h>
#include <math_constants.h>
#include <cstdint>

// Problem constants
#define B_ 8
#define T_ 8192
#define L_ 256
#define D_ 512
#define H_ 8
// HD = 64, scale = 1/8

// ---------------- scratch (device globals; no allocs allowed) ----------------
__device__ __nv_bfloat16 g_qh [(size_t)B_ * L_ * D_],  g_ql [(size_t)B_ * L_ * D_];
__device__ __nv_bfloat16 g_kvh[(size_t)B_ * T_ * 2 * D_], g_kvl[(size_t)B_ * T_ * 2 * D_];
__device__ float         g_att[(size_t)B_ * L_ * D_];

__device__ __nv_bfloat16 g_wkv_h[1024 * 512], g_wkv_l[1024 * 512];   // Wkv^T split
__device__ __nv_bfloat16 g_wq_h [512 * 512],  g_wq_l [512 * 512];    // Wq^T split
__device__ __nv_bfloat16 g_wp_h [512 * 512],  g_wp_l [512 * 512];    // Wproj^T split

__device__ __forceinline__ uint32_t smem_u32(const void* p) {
    uint32_t a;
    asm("{ .reg .u64 t; cvta.to.shared.u64 t, %1; cvt.u32.u64 %0, t; }"
        : "=r"(a) : "l"(p));
    return a;
}

#define CP16(dst, src) \
    asm volatile("cp.async.cg.shared.global [%0], [%1], 16;" :: "r"(dst), "l"(src))
#define CP_COMMIT() asm volatile("cp.async.commit_group;" ::: "memory")
#define CP_WAIT(n)  asm volatile("cp.async.wait_group %0;" :: "n"(n) : "memory")

#define LDSM4(r, addr) \
    asm volatile("ldmatrix.sync.aligned.m8n8.x4.shared.b16 {%0,%1,%2,%3}, [%4];" \
        : "=r"((r)[0]), "=r"((r)[1]), "=r"((r)[2]), "=r"((r)[3]) : "r"(addr))
#define LDSM4T(r, addr) \
    asm volatile("ldmatrix.sync.aligned.m8n8.x4.trans.shared.b16 {%0,%1,%2,%3}, [%4];" \
        : "=r"((r)[0]), "=r"((r)[1]), "=r"((r)[2]), "=r"((r)[3]) : "r"(addr))

#define MMA16816(d, a, b0r, b1r) \
    asm volatile("mma.sync.aligned.m16n8k16.row.col.f32.bf16.bf16.f32 " \
        "{%0,%1,%2,%3}, {%4,%5,%6,%7}, {%8,%9}, {%0,%1,%2,%3};" \
        : "+f"((d)[0]), "+f"((d)[1]), "+f"((d)[2]), "+f"((d)[3]) \
        : "r"((a)[0]), "r"((a)[1]), "r"((a)[2]), "r"((a)[3]), "r"(b0r), "r"(b1r))

#define SWZ64(o)  ((o) ^ ((((o) >> 7) & 3) << 4))
#define SWZ128(o) ((o) ^ ((((o) >> 7) & 7) << 4))

// =============================================================================
// Weight split/transpose: W[K,N] fp32 -> Wt_hi/Wt_lo [N,K] bf16
// =============================================================================
__global__ void split_w(const float* __restrict__ W, __nv_bfloat16* __restrict__ Th,
                        __nv_bfloat16* __restrict__ Tl, int K, int N)
{
    int idx = blockIdx.x * blockDim.x + threadIdx.x;
    if (idx >= K * N) return;
    int k = idx / N, n = idx % N;
    float w = W[idx];
    __nv_bfloat16 h = __float2bfloat16_rn(w);
    float r = w - __bfloat162float(h);
    Th[(size_t)n * K + k] = h;
    Tl[(size_t)n * K + k] = __float2bfloat16_rn(r);
}

// =============================================================================
// HMMA GEMM: C[M,N] = A[M,K](fp32, split in-producer) @ Wt^T + bias
// CTA tile 128x256, 8 warps (2x4), warp tile 64x64. K-chunk 32.
// B (bf16 hi/lo) via 3-stage cp.async; A via LDG-prefetch + convert + STS (2 buf).
// smem: B stages @0/32K/64K (Bh 16K + Bl 16K each); A bufs @96K/112K (Ah 8K+Al 8K).
// mode 0: fp32 out. mode 1: bf16 hi/lo out, v = scale*(acc+bias).
// =============================================================================
#define GEMM_SMEM 131072

__global__ __launch_bounds__(256, 1)
void gemm2(const float* __restrict__ A,
           const __nv_bfloat16* __restrict__ Bth, const __nv_bfloat16* __restrict__ Btl,
           const float* __restrict__ bias, float* __restrict__ Cf,
           __nv_bfloat16* __restrict__ Ch, __nv_bfloat16* __restrict__ Cl,
           float scale, int M, int N, int K, int mode)
{
    extern __shared__ char smem[];
    const uint32_t sb = smem_u32(smem);
    const int tid = threadIdx.x, lane = tid & 31, warp = tid >> 5;
    const int wm = warp >> 2, wn = warp & 3;          // 2x4 warp grid, warp 64x64
    const int bm = blockIdx.y * 128, bn = blockIdx.x * 256;

    float acc[4][8][4];
    #pragma unroll
    for (int i = 0; i < 4; i++)
        #pragma unroll
        for (int j = 0; j < 8; j++)
            #pragma unroll
            for (int k = 0; k < 4; k++) acc[i][j][k] = 0.f;

    const int nchunk = K >> 5;

    // ---- B producer: cp.async, 8 CP16/thread/chunk ----
    auto produceB = [&](int c, int s) {
        const uint32_t base = sb + (uint32_t)s * 32768;
        #pragma unroll
        for (int i = 0; i < 4; i++) {
            int idx = tid + i * 256;              // 0..1023
            int r = idx >> 2, sg = idx & 3;
            uint32_t sw = SWZ64(r * 64 + sg * 16);
            const size_t gb = (size_t)(bn + r) * K + c * 32 + sg * 8;
            CP16(base + sw,         Bth + gb);
            CP16(base + 16384 + sw, Btl + gb);
        }
    };

    // ---- A producer: LDG fp32 prefetch -> convert -> STS ----
    float4 pa[4];
    auto loadA = [&](int c) {
        #pragma unroll
        for (int i = 0; i < 4; i++) {
            int idx = tid + i * 256;              // 0..1023
            int r = idx >> 3, k4 = idx & 7;
            pa[i] = *reinterpret_cast<const float4*>(
                A + (size_t)(bm + r) * K + c * 32 + k4 * 4);
        }
    };
    auto storeA = [&](int buf) {
        char* base = smem + 98304 + buf * 16384;
        #pragma unroll
        for (int i = 0; i < 4; i++) {
            int idx = tid + i * 256;
            int r = idx >> 3, k4 = idx & 7;
            uint32_t sw = SWZ64(r * 64 + k4 * 8);
            float4 v = pa[i];
            __nv_bfloat162 h01 = __floats2bfloat162_rn(v.x, v.y);
            __nv_bfloat162 h23 = __floats2bfloat162_rn(v.z, v.w);
            float2 f01 = __bfloat1622float2(h01);
            float2 f23 = __bfloat1622float2(h23);
            __nv_bfloat162 l01 = __floats2bfloat162_rn(v.x - f01.x, v.y - f01.y);
            __nv_bfloat162 l23 = __floats2bfloat162_rn(v.z - f23.x, v.w - f23.y);
            *reinterpret_cast<uint2*>(base + sw) =
                make_uint2(*(uint32_t*)&h01, *(uint32_t*)&h23);
            *reinterpret_cast<uint2*>(base + 8192 + sw) =
                make_uint2(*(uint32_t*)&l01, *(uint32_t*)&l23);
        }
    };

    // fragment addressing
    const uint32_t arow  = wm * 64 + (lane & 15);
    const uint32_t aoffb = arow * 64 + ((lane >> 4) << 4);
    const uint32_t axor  = ((arow >> 1) & 3) << 4;
    const uint32_t blrow = (lane & 7) + ((lane >> 4) << 3);
    const uint32_t bseg  = ((uint32_t)((lane >> 3) & 1)) << 4;

    auto compute = [&](int c) {
        const uint32_t sab = sb + (uint32_t)(c % 3) * 32768;
        const uint32_t saa = sb + 98304 + (uint32_t)(c & 1) * 16384;
        #pragma unroll
        for (int ks = 0; ks < 2; ks++) {
            uint32_t Ah[4][4], Al[4][4];
            #pragma unroll
            for (int mt = 0; mt < 4; mt++) {
                uint32_t addr = (saa + aoffb + mt * 1024 + ks * 32) ^ axor;
                LDSM4(Ah[mt], addr);
                LDSM4(Al[mt], addr + 8192);
            }
            uint32_t Bh[4][4], Bl[4][4];
            #pragma unroll
            for (int np = 0; np < 4; np++) {
                const uint32_t brow = wn * 64 + np * 16 + blrow;
                uint32_t off = brow * 64 + bseg + ks * 32;
                uint32_t addr = sab + (off ^ (((brow >> 1) & 3) << 4));
                LDSM4(Bh[np], addr);
                LDSM4(Bl[np], addr + 16384);
            }
            #pragma unroll
            for (int mt = 0; mt < 4; mt++)
                #pragma unroll
                for (int nt = 0; nt < 8; nt++) {
                    const int np = nt >> 1, bi = (nt & 1) * 2;
                    MMA16816(acc[mt][nt], Ah[mt], Bh[np][bi], Bh[np][bi + 1]);
                }
            #pragma unroll
            for (int mt = 0; mt < 4; mt++)
                #pragma unroll
                for (int nt = 0; nt < 8; nt++) {
                    const int np = nt >> 1, bi = (nt & 1) * 2;
                    MMA16816(acc[mt][nt], Ah[mt], Bl[np][bi], Bl[np][bi + 1]);
                }
            #pragma unroll
            for (int mt = 0; mt < 4; mt++)
                #pragma unroll
                for (int nt = 0; nt < 8; nt++) {
                    const int np = nt >> 1, bi = (nt & 1) * 2;
                    MMA16816(acc[mt][nt], Al[mt], Bh[np][bi], Bh[np][bi + 1]);
                }
        }
    };

    produceB(0, 0); CP_COMMIT();
    produceB(1, 1); CP_COMMIT();
    loadA(0);
    storeA(0);
    for (int c = 0; c < nchunk; c++) {
        CP_WAIT(1);
        __syncthreads();          // publishes A buf c&1; guards B stage & A buf reuse
        if (c + 2 < nchunk) { produceB(c + 2, (c + 2) % 3); CP_COMMIT(); }
        if (c + 1 < nchunk) loadA(c + 1);
        compute(c);
        if (c + 1 < nchunk) storeA((c + 1) & 1);
    }

    // ---- epilogue ----
    #pragma unroll
    for (int nt = 0; nt < 8; nt++) {
        const int ncol = bn + wn * 64 + nt * 8 + 2 * (lane & 3);
        const float2 bb = *reinterpret_cast<const float2*>(bias + ncol);
        #pragma unroll
        for (int mt = 0; mt < 4; mt++) {
            const int m0 = bm + wm * 64 + mt * 16 + (lane >> 2);
            float v0 = acc[mt][nt][0] + bb.x, v1 = acc[mt][nt][1] + bb.y;
            float v2 = acc[mt][nt][2] + bb.x, v3 = acc[mt][nt][3] + bb.y;
            if (mode == 0) {
                *reinterpret_cast<float2*>(Cf + (size_t)m0 * N + ncol) =
                    make_float2(v0, v1);
                *reinterpret_cast<float2*>(Cf + (size_t)(m0 + 8) * N + ncol) =
                    make_float2(v2, v3);
            } else {
                v0 *= scale; v1 *= scale; v2 *= scale; v3 *= scale;
                __nv_bfloat162 h01 = __floats2bfloat162_rn(v0, v1);
                __nv_bfloat162 h23 = __floats2bfloat162_rn(v2, v3);
                float2 f01 = __bfloat1622float2(h01);
                float2 f23 = __bfloat1622float2(h23);
                __nv_bfloat162 l01 = __floats2bfloat162_rn(v0 - f01.x, v1 - f01.y);
                __nv_bfloat162 l23 = __floats2bfloat162_rn(v2 - f23.x, v3 - f23.y);
                *reinterpret_cast<uint32_t*>(Ch + (size_t)m0 * N + ncol) = *(uint32_t*)&h01;
                *reinterpret_cast<uint32_t*>(Cl + (size_t)m0 * N + ncol) = *(uint32_t*)&l01;
                *reinterpret_cast<uint32_t*>(Ch + (size_t)(m0 + 8) * N + ncol) = *(uint32_t*)&h23;
                *reinterpret_cast<uint32_t*>(Cl + (size_t)(m0 + 8) * N + ncol) = *(uint32_t*)&l23;
            }
        }
    }
}

// =============================================================================
// HMMA flash attention (structure unchanged from R5/R6; epilogue -> fp32).
// =============================================================================
#define ATTN_SMEM 98304

__global__ __launch_bounds__(256, 1)
void attn2(const __nv_bfloat16* __restrict__ qsh, const __nv_bfloat16* __restrict__ qsl,
           const __nv_bfloat16* __restrict__ kvh, const __nv_bfloat16* __restrict__ kvl,
           float* __restrict__ attf)
{
    extern __shared__ char smem[];
    const uint32_t sb = smem_u32(smem);
    const int tid = threadIdx.x, lane = tid & 31, warp = tid >> 5;
    const int bid = blockIdx.x;
    const int lt = bid & 1;
    const int h  = (bid >> 1) & 7;
    const int b  = bid >> 4;
    const int l0 = lt * 128;

    #pragma unroll
    for (int i = 0; i < 4; i++) {
        int idx = tid + i * 256;
        int r = idx >> 3, sg = idx & 7;
        uint32_t sw = SWZ128(r * 128 + sg * 16);
        size_t g = (size_t)(b * L_ + l0 + r) * 512 + h * 64 + sg * 8;
        CP16(sb + 65536 + sw, qsh + g);
        CP16(sb + 81920 + sw, qsl + g);
    }
    CP_COMMIT();
    CP_WAIT(0);
    __syncthreads();

    uint32_t Qh[4][4], Ql[4][4];
    {
        const int arow = warp * 16 + (lane & 15);
        const uint32_t abase = sb + 65536 + arow * 128;
        const uint32_t axor = (arow & 7) << 4;
        #pragma unroll
        for (int kc = 0; kc < 4; kc++) {
            uint32_t o = ((((uint32_t)(lane >> 4) << 4) + kc * 32)) ^ axor;
            LDSM4(Qh[kc], abase + o);
            LDSM4(Ql[kc], abase + 16384 + o);
        }
    }
    __syncthreads();

    auto produce = [&](int c, int s) {
        const uint32_t base = sb + (uint32_t)s * 32768;
        #pragma unroll
        for (int i = 0; i < 2; i++) {
            int idx = tid + i * 256;
            int r = idx >> 3, sg = idx & 7;
            uint32_t sw = SWZ128(r * 128 + sg * 16);
            size_t g = (size_t)(b * T_ + c * 64 + r) * 1024 + h * 64 + sg * 8;
            CP16(base + sw,         kvh + g);
            CP16(base + 8192 + sw,  kvl + g);
            CP16(base + 16384 + sw, kvh + g + 512);
            CP16(base + 24576 + sw, kvl + g + 512);
        }
    };
    produce(0, 0); CP_COMMIT();
    produce(1, 1); CP_COMMIT();

    float mrow[2] = { -CUDART_INF_F, -CUDART_INF_F };
    float lsum[2] = { 0.f, 0.f };
    float O[8][4];
    #pragma unroll
    for (int i = 0; i < 8; i++)
        #pragma unroll
        for (int j = 0; j < 4; j++) O[i][j] = 0.f;

    const int klrow = (lane & 7) + ((lane >> 4) << 3);
    const uint32_t kseg = ((uint32_t)((lane >> 3) & 1)) << 4;
    const int vlrow = (lane & 7) + (((lane >> 3) & 1) << 3);
    const int vseg_half = lane >> 4;

    int bufc = 0;
    for (int c = 0; c < T_ / 64; c++) {
        CP_WAIT(1);
        __syncthreads();
        const uint32_t kb = sb + (uint32_t)bufc * 32768;

        float S[8][4];
        #pragma unroll
        for (int i = 0; i < 8; i++)
            #pragma unroll
            for (int j = 0; j < 4; j++) S[i][j] = 0.f;

        #pragma unroll
        for (int npp = 0; npp < 2; npp++) {
            #pragma unroll
            for (int kc = 0; kc < 4; kc++) {
                const int brow0 = (2 * npp) * 16 + klrow;
                const int brow1 = (2 * npp + 1) * 16 + klrow;
                uint32_t a0 = kb + brow0 * 128 + ((kseg + kc * 32) ^ ((brow0 & 7) << 4));
                uint32_t a1 = kb + brow1 * 128 + ((kseg + kc * 32) ^ ((brow1 & 7) << 4));
                uint32_t Bh0[4], Bl0[4], Bh1[4], Bl1[4];
                LDSM4(Bh0, a0); LDSM4(Bl0, a0 + 8192);
                LDSM4(Bh1, a1); LDSM4(Bl1, a1 + 8192);
                float* s0 = S[4 * npp];     float* s1 = S[4 * npp + 1];
                float* s2 = S[4 * npp + 2]; float* s3 = S[4 * npp + 3];
                MMA16816(s0, Qh[kc], Bh0[0], Bh0[1]);
                MMA16816(s1, Qh[kc], Bh0[2], Bh0[3]);
                MMA16816(s2, Qh[kc], Bh1[0], Bh1[1]);
                MMA16816(s3, Qh[kc], Bh1[2], Bh1[3]);
                MMA16816(s0, Qh[kc], Bl0[0], Bl0[1]);
                MMA16816(s1, Qh[kc], Bl0[2], Bl0[3]);
                MMA16816(s2, Qh[kc], Bl1[0], Bl1[1]);
                MMA16816(s3, Qh[kc], Bl1[2], Bl1[3]);
                MMA16816(s0, Ql[kc], Bh0[0], Bh0[1]);
                MMA16816(s1, Ql[kc], Bh0[2], Bh0[3]);
                MMA16816(s2, Ql[kc], Bh1[0], Bh1[1]);
                MMA16816(s3, Ql[kc], Bh1[2], Bh1[3]);
            }
        }

        float mxA = -CUDART_INF_F, mxB = -CUDART_INF_F;
        #pragma unroll
        for (int nt = 0; nt < 8; nt++) {
            mxA = fmaxf(mxA, fmaxf(S[nt][0], S[nt][1]));
            mxB = fmaxf(mxB, fmaxf(S[nt][2], S[nt][3]));
        }
        #pragma unroll
        for (int o = 1; o <= 2; o <<= 1) {
            mxA = fmaxf(mxA, __shfl_xor_sync(0xffffffffu, mxA, o));
            mxB = fmaxf(mxB, __shfl_xor_sync(0xffffffffu, mxB, o));
        }
        const float mnA = fmaxf(mrow[0], mxA);
        const float mnB = fmaxf(mrow[1], mxB);
        const float alphaA = exp2f(mrow[0] - mnA);
        const float alphaB = exp2f(mrow[1] - mnB);
        mrow[0] = mnA; mrow[1] = mnB;

        uint32_t Ph[4][4], Pl[4][4];
        float sumA = 0.f, sumB = 0.f;
        #pragma unroll
        for (int nt = 0; nt < 8; nt++) {
            float p0 = exp2f(S[nt][0] - mnA);
            float p1 = exp2f(S[nt][1] - mnA);
            float p2 = exp2f(S[nt][2] - mnB);
            float p3 = exp2f(S[nt][3] - mnB);
            sumA += p0 + p1; sumB += p2 + p3;
            __nv_bfloat162 hA = __floats2bfloat162_rn(p0, p1);
            __nv_bfloat162 hB = __floats2bfloat162_rn(p2, p3);
            float2 fA = __bfloat1622float2(hA);
            float2 fB = __bfloat1622float2(hB);
            __nv_bfloat162 lA = __floats2bfloat162_rn(p0 - fA.x, p1 - fA.y);
            __nv_bfloat162 lB = __floats2bfloat162_rn(p2 - fB.x, p3 - fB.y);
            const int kc = nt >> 1, ri = (nt & 1) * 2;
            Ph[kc][ri]     = *(uint32_t*)&hA;
            Ph[kc][ri + 1] = *(uint32_t*)&hB;
            Pl[kc][ri]     = *(uint32_t*)&lA;
            Pl[kc][ri + 1] = *(uint32_t*)&lB;
        }
        #pragma unroll
        for (int o = 1; o <= 2; o <<= 1) {
            sumA += __shfl_xor_sync(0xffffffffu, sumA, o);
            sumB += __shfl_xor_sync(0xffffffffu, sumB, o);
        }
        lsum[0] = lsum[0] * alphaA + sumA;
        lsum[1] = lsum[1] * alphaB + sumB;
        #pragma unroll
        for (int nt = 0; nt < 8; nt++) {
            O[nt][0] *= alphaA; O[nt][1] *= alphaA;
            O[nt][2] *= alphaB; O[nt][3] *= alphaB;
        }

        #pragma unroll
        for (int kc = 0; kc < 4; kc++) {
            const int vrow = kc * 16 + vlrow;
            const uint32_t vbase = kb + 16384 + vrow * 128;
            const uint32_t vxor = (vrow & 7) << 4;
            #pragma unroll
            for (int ngp = 0; ngp < 2; ngp++) {
                uint32_t o0 = ((uint32_t)((4 * ngp + vseg_half) << 4)) ^ vxor;
                uint32_t o1 = ((uint32_t)((4 * ngp + 2 + vseg_half) << 4)) ^ vxor;
                uint32_t Vh0[4], Vl0[4], Vh1[4], Vl1[4];
                LDSM4T(Vh0, vbase + o0); LDSM4T(Vl0, vbase + 8192 + o0);
                LDSM4T(Vh1, vbase + o1); LDSM4T(Vl1, vbase + 8192 + o1);
                float* d0 = O[4 * ngp];     float* d1 = O[4 * ngp + 1];
                float* d2 = O[4 * ngp + 2]; float* d3 = O[4 * ngp + 3];
                MMA16816(d0, Ph[kc], Vh0[0], Vh0[1]);
                MMA16816(d1, Ph[kc], Vh0[2], Vh0[3]);
                MMA16816(d2, Ph[kc], Vh1[0], Vh1[1]);
                MMA16816(d3, Ph[kc], Vh1[2], Vh1[3]);
                MMA16816(d0, Ph[kc], Vl0[0], Vl0[1]);
                MMA16816(d1, Ph[kc], Vl0[2], Vl0[3]);
                MMA16816(d2, Ph[kc], Vl1[0], Vl1[1]);
                MMA16816(d3, Ph[kc], Vl1[2], Vl1[3]);
                MMA16816(d0, Pl[kc], Vh0[0], Vh0[1]);
                MMA16816(d1, Pl[kc], Vh0[2], Vh0[3]);
                MMA16816(d2, Pl[kc], Vh1[0], Vh1[1]);
                MMA16816(d3, Pl[kc], Vh1[2], Vh1[3]);
            }
        }

        if (c + 2 < T_ / 64) produce(c + 2, (bufc + 2) % 3);
        CP_COMMIT();
        bufc = (bufc + 1) % 3;
    }
    CP_WAIT(0);

    const float invA = 1.0f / lsum[0];
    const float invB = 1.0f / lsum[1];
    const int rowA = b * L_ + l0 + warp * 16 + (lane >> 2);
    #pragma unroll
    for (int nt = 0; nt < 8; nt++) {
        const int col = h * 64 + nt * 8 + (lane & 3) * 2;
        *reinterpret_cast<float2*>(attf + (size_t)rowA * D_ + col) =
            make_float2(O[nt][0] * invA, O[nt][1] * invA);
        *reinterpret_cast<float2*>(attf + (size_t)(rowA + 8) * D_ + col) =
            make_float2(O[nt][2] * invB, O[nt][3] * invB);
    }
}

// =============================================================================
// launch
// =============================================================================
extern "C" void kernel_launch(void* const* d_in, const int* in_sizes, int n_in,
                              void* d_out, int out_size)
{
    const float* x     = (const float*)d_in[0];
    const float* query = (const float*)d_in[1];
    const float* Wq    = (const float*)d_in[2];
    const float* bq    = (const float*)d_in[3];
    const float* Wkv   = (const float*)d_in[4];
    const float* bkv   = (const float*)d_in[5];
    const float* Wproj = (const float*)d_in[6];
    const float* bproj = (const float*)d_in[7];
    float* out = (float*)d_out;

    __nv_bfloat16 *qh, *ql, *kvh, *kvl;
    float* att;
    __nv_bfloat16 *wkvh, *wkvl, *wqh, *wql, *wph, *wpl;
    cudaGetSymbolAddress((void**)&qh,  g_qh);   cudaGetSymbolAddress((void**)&ql,  g_ql);
    cudaGetSymbolAddress((void**)&kvh, g_kvh);  cudaGetSymbolAddress((void**)&kvl, g_kvl);
    cudaGetSymbolAddress((void**)&att, g_att);
    cudaGetSymbolAddress((void**)&wkvh, g_wkv_h); cudaGetSymbolAddress((void**)&wkvl, g_wkv_l);
    cudaGetSymbolAddress((void**)&wqh,  g_wq_h);  cudaGetSymbolAddress((void**)&wql,  g_wq_l);
    cudaGetSymbolAddress((void**)&wph,  g_wp_h);  cudaGetSymbolAddress((void**)&wpl,  g_wp_l);

    cudaFuncSetAttribute(gemm2, cudaFuncAttributeMaxDynamicSharedMemorySize, GEMM_SMEM);
    cudaFuncSetAttribute(attn2, cudaFuncAttributeMaxDynamicSharedMemorySize, ATTN_SMEM);

    const float cscale = 0.125f * 1.4426950408889634f;

    split_w<<<(512 * 1024 + 255) / 256, 256>>>(Wkv,   wkvh, wkvl, 512, 1024);
    split_w<<<(512 * 512  + 255) / 256, 256>>>(Wq,    wqh,  wql,  512, 512);
    split_w<<<(512 * 512  + 255) / 256, 256>>>(Wproj, wph,  wpl,  512, 512);

    // kv = x @ Wkv + bkv : [65536, 1024] -> bf16 hi/lo
    gemm2<<<dim3(1024 / 256, (B_ * T_) / 128), 256, GEMM_SMEM>>>(
        x, wkvh, wkvl, bkv, nullptr, kvh, kvl, 1.0f, B_ * T_, 2 * D_, D_, 1);
    // q = cscale*(query @ Wq + bq) : [2048, 512] -> bf16 hi/lo
    gemm2<<<dim3(D_ / 256, (B_ * L_) / 128), 256, GEMM_SMEM>>>(
        query, wqh, wql, bq, nullptr, qh, ql, cscale, B_ * L_, D_, D_, 1);
    // attention -> att fp32
    attn2<<<B_ * H_ * (L_ / 128), 256, ATTN_SMEM>>>(qh, ql, kvh, kvl, att);
    // out = att @ Wproj + bproj : [2048, 512] fp32
    gemm2<<<dim3(D_ / 256, (B_ * L_) / 128), 256, GEMM_SMEM>>>(
        att, wph, wpl, bproj, out, nullptr, nullptr, 1.0f, B_ * L_, D_, D_, 0);
}

// round 8
// speedup vs baseline: 1.0083x; 1.0083x over previous
#include <cuda_runtime.h>
#include <cuda_bf16.h>
#include <math_constants.h>
#include <cstdint>

// Problem constants
#define B_ 8
#define T_ 8192
#define L_ 256
#define D_ 512
#define H_ 8
// HD = 64, scale = 1/8

// ---------------- scratch (device globals; no allocs allowed) ----------------
__device__ __nv_bfloat16 g_xh [(size_t)B_ * T_ * D_],  g_xl [(size_t)B_ * T_ * D_];
__device__ __nv_bfloat16 g_qih[(size_t)B_ * L_ * D_],  g_qil[(size_t)B_ * L_ * D_];
__device__ __nv_bfloat16 g_qh [(size_t)B_ * L_ * D_],  g_ql [(size_t)B_ * L_ * D_];
__device__ __nv_bfloat16 g_kvh[(size_t)B_ * T_ * 2 * D_], g_kvl[(size_t)B_ * T_ * 2 * D_];
__device__ __nv_bfloat16 g_ath[(size_t)B_ * L_ * D_],  g_atl[(size_t)B_ * L_ * D_];

__device__ __nv_bfloat16 g_wkv_h[1024 * 512], g_wkv_l[1024 * 512];   // Wkv^T split
__device__ __nv_bfloat16 g_wq_h [512 * 512],  g_wq_l [512 * 512];    // Wq^T split
__device__ __nv_bfloat16 g_wp_h [512 * 512],  g_wp_l [512 * 512];    // Wproj^T split

__device__ __forceinline__ uint32_t smem_u32(const void* p) {
    uint32_t a;
    asm("{ .reg .u64 t; cvta.to.shared.u64 t, %1; cvt.u32.u64 %0, t; }"
        : "=r"(a) : "l"(p));
    return a;
}

#define CP16(dst, src) \
    asm volatile("cp.async.cg.shared.global [%0], [%1], 16;" :: "r"(dst), "l"(src))
#define CP_COMMIT() asm volatile("cp.async.commit_group;" ::: "memory")
#define CP_WAIT(n)  asm volatile("cp.async.wait_group %0;" :: "n"(n) : "memory")

#define LDSM4(r, addr) \
    asm volatile("ldmatrix.sync.aligned.m8n8.x4.shared.b16 {%0,%1,%2,%3}, [%4];" \
        : "=r"((r)[0]), "=r"((r)[1]), "=r"((r)[2]), "=r"((r)[3]) : "r"(addr))
#define LDSM4T(r, addr) \
    asm volatile("ldmatrix.sync.aligned.m8n8.x4.trans.shared.b16 {%0,%1,%2,%3}, [%4];" \
        : "=r"((r)[0]), "=r"((r)[1]), "=r"((r)[2]), "=r"((r)[3]) : "r"(addr))

#define MMA16816(d, a, b0r, b1r) \
    asm volatile("mma.sync.aligned.m16n8k16.row.col.f32.bf16.bf16.f32 " \
        "{%0,%1,%2,%3}, {%4,%5,%6,%7}, {%8,%9}, {%0,%1,%2,%3};" \
        : "+f"((d)[0]), "+f"((d)[1]), "+f"((d)[2]), "+f"((d)[3]) \
        : "r"((a)[0]), "r"((a)[1]), "r"((a)[2]), "r"((a)[3]), "r"(b0r), "r"(b1r))

#define SWZ64(o)  ((o) ^ ((((o) >> 7) & 3) << 4))
#define SWZ128(o) ((o) ^ ((((o) >> 7) & 7) << 4))

// =============================================================================
// Splits
// =============================================================================
__global__ void split_w(const float* __restrict__ W, __nv_bfloat16* __restrict__ Th,
                        __nv_bfloat16* __restrict__ Tl, int K, int N)
{
    int idx = blockIdx.x * blockDim.x + threadIdx.x;
    if (idx >= K * N) return;
    int k = idx / N, n = idx % N;
    float w = W[idx];
    __nv_bfloat16 h = __float2bfloat16_rn(w);
    float r = w - __bfloat162float(h);
    Th[(size_t)n * K + k] = h;
    Tl[(size_t)n * K + k] = __float2bfloat16_rn(r);
}

__global__ void split_a(const float* __restrict__ A, __nv_bfloat16* __restrict__ Ah,
                        __nv_bfloat16* __restrict__ Al, int n4)
{
    int i = blockIdx.x * blockDim.x + threadIdx.x;
    if (i >= n4) return;
    float4 v = reinterpret_cast<const float4*>(A)[i];
    __nv_bfloat162 h01 = __floats2bfloat162_rn(v.x, v.y);
    __nv_bfloat162 h23 = __floats2bfloat162_rn(v.z, v.w);
    float2 f01 = __bfloat1622float2(h01);
    float2 f23 = __bfloat1622float2(h23);
    __nv_bfloat162 l01 = __floats2bfloat162_rn(v.x - f01.x, v.y - f01.y);
    __nv_bfloat162 l23 = __floats2bfloat162_rn(v.z - f23.x, v.w - f23.y);
    reinterpret_cast<uint2*>(Ah)[i] = make_uint2(*(uint32_t*)&h01, *(uint32_t*)&h23);
    reinterpret_cast<uint2*>(Al)[i] = make_uint2(*(uint32_t*)&l01, *(uint32_t*)&l23);
}

// =============================================================================
// HMMA GEMM: C = A @ Wt^T + bias. All operands pre-split bf16 hi/lo.
// CTA 128x256, 8 warps (2x4), warp tile 64x64, K-chunk 32.
// 2-stage full cp.async (stage = Ah 8K | Al 8K | Bh 16K | Bl 16K = 48KB).
// mode 0: fp32 out. mode 1: bf16 hi/lo out, v = scale*(acc+bias).
// =============================================================================
#define GEMM_SMEM 98304

__global__ __launch_bounds__(256, 1)
void gemm2(const __nv_bfloat16* __restrict__ Ath, const __nv_bfloat16* __restrict__ Atl,
           const __nv_bfloat16* __restrict__ Bth, const __nv_bfloat16* __restrict__ Btl,
           const float* __restrict__ bias, float* __restrict__ Cf,
           __nv_bfloat16* __restrict__ Ch, __nv_bfloat16* __restrict__ Cl,
           float scale, int M, int N, int K, int mode)
{
    extern __shared__ char smem[];
    const uint32_t sb = smem_u32(smem);
    const int tid = threadIdx.x, lane = tid & 31, warp = tid >> 5;
    const int wm = warp >> 2, wn = warp & 3;          // 2x4 warp grid, warp 64x64
    const int bm = blockIdx.y * 128, bn = blockIdx.x * 256;

    float acc[4][8][4];
    #pragma unroll
    for (int i = 0; i < 4; i++)
        #pragma unroll
        for (int j = 0; j < 8; j++)
            #pragma unroll
            for (int k = 0; k < 4; k++) acc[i][j][k] = 0.f;

    const int nchunk = K >> 5;

    auto produce = [&](int c, int s) {
        const uint32_t base = sb + (uint32_t)s * 49152;
        #pragma unroll
        for (int i = 0; i < 2; i++) {
            int idx = tid + i * 256;              // 0..511 (A: 128 rows x 4 segs)
            int r = idx >> 2, sg = idx & 3;
            uint32_t sw = SWZ64(r * 64 + sg * 16);
            const size_t ga = (size_t)(bm + r) * K + c * 32 + sg * 8;
            CP16(base + sw,        Ath + ga);
            CP16(base + 8192 + sw, Atl + ga);
        }
        #pragma unroll
        for (int i = 0; i < 4; i++) {
            int idx = tid + i * 256;              // 0..1023 (B: 256 rows x 4 segs)
            int r = idx >> 2, sg = idx & 3;
            uint32_t sw = SWZ64(r * 64 + sg * 16);
            const size_t gb = (size_t)(bn + r) * K + c * 32 + sg * 8;
            CP16(base + 16384 + sw, Bth + gb);
            CP16(base + 32768 + sw, Btl + gb);
        }
    };

    // fragment addressing
    const uint32_t arow  = wm * 64 + (lane & 15);
    const uint32_t aoffb = arow * 64 + ((lane >> 4) << 4);
    const uint32_t axor  = ((arow >> 1) & 3) << 4;
    const uint32_t blrow = (lane & 7) + ((lane >> 4) << 3);
    const uint32_t bseg  = ((uint32_t)((lane >> 3) & 1)) << 4;

    auto compute = [&](int s) {
        const uint32_t base = sb + (uint32_t)s * 49152;
        #pragma unroll
        for (int ks = 0; ks < 2; ks++) {
            uint32_t Ah[4][4], Al[4][4];
            #pragma unroll
            for (int mt = 0; mt < 4; mt++) {
                uint32_t addr = (base + aoffb + mt * 1024 + ks * 32) ^ axor;
                LDSM4(Ah[mt], addr);
                LDSM4(Al[mt], addr + 8192);
            }
            #pragma unroll
            for (int np = 0; np < 4; np++) {
                const uint32_t brow = wn * 64 + np * 16 + blrow;
                uint32_t off = brow * 64 + bseg + ks * 32;
                uint32_t addr = base + 16384 + (off ^ (((brow >> 1) & 3) << 4));
                uint32_t Bh[4], Bl[4];
                LDSM4(Bh, addr);
                LDSM4(Bl, addr + 16384);
                // three term passes; same-acc RAW distance = 8
                #pragma unroll
                for (int mt = 0; mt < 4; mt++) {
                    MMA16816(acc[mt][2 * np],     Ah[mt], Bh[0], Bh[1]);
                    MMA16816(acc[mt][2 * np + 1], Ah[mt], Bh[2], Bh[3]);
                }
                #pragma unroll
                for (int mt = 0; mt < 4; mt++) {
                    MMA16816(acc[mt][2 * np],     Ah[mt], Bl[0], Bl[1]);
                    MMA16816(acc[mt][2 * np + 1], Ah[mt], Bl[2], Bl[3]);
                }
                #pragma unroll
                for (int mt = 0; mt < 4; mt++) {
                    MMA16816(acc[mt][2 * np],     Al[mt], Bh[0], Bh[1]);
                    MMA16816(acc[mt][2 * np + 1], Al[mt], Bh[2], Bh[3]);
                }
            }
        }
    };

    produce(0, 0); CP_COMMIT();
    produce(1, 1); CP_COMMIT();
    for (int c = 0; c < nchunk; c++) {
        CP_WAIT(1);
        __syncthreads();
        compute(c & 1);
        __syncthreads();
        if (c + 2 < nchunk) { produce(c + 2, c & 1); CP_COMMIT(); }
    }

    // ---- epilogue ----
    #pragma unroll
    for (int nt = 0; nt < 8; nt++) {
        const int ncol = bn + wn * 64 + nt * 8 + 2 * (lane & 3);
        const float2 bb = *reinterpret_cast<const float2*>(bias + ncol);
        #pragma unroll
        for (int mt = 0; mt < 4; mt++) {
            const int m0 = bm + wm * 64 + mt * 16 + (lane >> 2);
            float v0 = acc[mt][nt][0] + bb.x, v1 = acc[mt][nt][1] + bb.y;
            float v2 = acc[mt][nt][2] + bb.x, v3 = acc[mt][nt][3] + bb.y;
            if (mode == 0) {
                *reinterpret_cast<float2*>(Cf + (size_t)m0 * N + ncol) =
                    make_float2(v0, v1);
                *reinterpret_cast<float2*>(Cf + (size_t)(m0 + 8) * N + ncol) =
                    make_float2(v2, v3);
            } else {
                v0 *= scale; v1 *= scale; v2 *= scale; v3 *= scale;
                __nv_bfloat162 h01 = __floats2bfloat162_rn(v0, v1);
                __nv_bfloat162 h23 = __floats2bfloat162_rn(v2, v3);
                float2 f01 = __bfloat1622float2(h01);
                float2 f23 = __bfloat1622float2(h23);
                __nv_bfloat162 l01 = __floats2bfloat162_rn(v0 - f01.x, v1 - f01.y);
                __nv_bfloat162 l23 = __floats2bfloat162_rn(v2 - f23.x, v3 - f23.y);
                *reinterpret_cast<uint32_t*>(Ch + (size_t)m0 * N + ncol) = *(uint32_t*)&h01;
                *reinterpret_cast<uint32_t*>(Cl + (size_t)m0 * N + ncol) = *(uint32_t*)&l01;
                *reinterpret_cast<uint32_t*>(Ch + (size_t)(m0 + 8) * N + ncol) = *(uint32_t*)&h23;
                *reinterpret_cast<uint32_t*>(Cl + (size_t)(m0 + 8) * N + ncol) = *(uint32_t*)&l23;
            }
        }
    }
}

// =============================================================================
// HMMA flash attention. QK = (Qh+Ql)*Kh (2-term; Kl never loaded — halves K
// smem traffic; logit error ~4e-4, softmax-safe). PV = 3-term. Stage = 24KB
// (Kh 8K | Vh 8K | Vl 8K), 3-stage ring; Q (hi 16K + lo 16K) at 72K.
// =============================================================================
#define ATTN_SMEM 106496

__global__ __launch_bounds__(256, 1)
void attn2(const __nv_bfloat16* __restrict__ qsh, const __nv_bfloat16* __restrict__ qsl,
           const __nv_bfloat16* __restrict__ kvh, const __nv_bfloat16* __restrict__ kvl,
           __nv_bfloat16* __restrict__ atth, __nv_bfloat16* __restrict__ attl)
{
    extern __shared__ char smem[];
    const uint32_t sb = smem_u32(smem);
    const int tid = threadIdx.x, lane = tid & 31, warp = tid >> 5;
    const int bid = blockIdx.x;
    const int lt = bid & 1;
    const int h  = (bid >> 1) & 7;
    const int b  = bid >> 4;
    const int l0 = lt * 128;

    // Q staging: hi @72K, lo @88K
    #pragma unroll
    for (int i = 0; i < 4; i++) {
        int idx = tid + i * 256;
        int r = idx >> 3, sg = idx & 7;
        uint32_t sw = SWZ128(r * 128 + sg * 16);
        size_t g = (size_t)(b * L_ + l0 + r) * 512 + h * 64 + sg * 8;
        CP16(sb + 73728 + sw, qsh + g);
        CP16(sb + 90112 + sw, qsl + g);
    }
    CP_COMMIT();
    CP_WAIT(0);
    __syncthreads();

    uint32_t Qh[4][4], Ql[4][4];
    {
        const int arow = warp * 16 + (lane & 15);
        const uint32_t abase = sb + 73728 + arow * 128;
        const uint32_t axor = (arow & 7) << 4;
        #pragma unroll
        for (int kc = 0; kc < 4; kc++) {
            uint32_t o = ((((uint32_t)(lane >> 4) << 4) + kc * 32)) ^ axor;
            LDSM4(Qh[kc], abase + o);
            LDSM4(Ql[kc], abase + 16384 + o);
        }
    }
    __syncthreads();

    auto produce = [&](int c, int s) {
        const uint32_t base = sb + (uint32_t)s * 24576;
        #pragma unroll
        for (int i = 0; i < 2; i++) {
            int idx = tid + i * 256;
            int r = idx >> 3, sg = idx & 7;
            uint32_t sw = SWZ128(r * 128 + sg * 16);
            size_t g = (size_t)(b * T_ + c * 64 + r) * 1024 + h * 64 + sg * 8;
            CP16(base + sw,         kvh + g);          // Kh
            CP16(base + 8192 + sw,  kvh + g + 512);    // Vh
            CP16(base + 16384 + sw, kvl + g + 512);    // Vl
        }
    };
    produce(0, 0); CP_COMMIT();
    produce(1, 1); CP_COMMIT();

    float mrow[2] = { -CUDART_INF_F, -CUDART_INF_F };
    float lsum[2] = { 0.f, 0.f };
    float O[8][4];
    #pragma unroll
    for (int i = 0; i < 8; i++)
        #pragma unroll
        for (int j = 0; j < 4; j++) O[i][j] = 0.f;

    const int klrow = (lane & 7) + ((lane >> 4) << 3);
    const uint32_t kseg = ((uint32_t)((lane >> 3) & 1)) << 4;
    const int vlrow = (lane & 7) + (((lane >> 3) & 1) << 3);
    const int vseg_half = lane >> 4;

    int bufc = 0;
    for (int c = 0; c < T_ / 64; c++) {
        CP_WAIT(1);
        __syncthreads();
        const uint32_t kb = sb + (uint32_t)bufc * 24576;

        // ---- S = (Qh + Ql) * Kh  (2-term) ----
        float S[8][4];
        #pragma unroll
        for (int i = 0; i < 8; i++)
            #pragma unroll
            for (int j = 0; j < 4; j++) S[i][j] = 0.f;

        #pragma unroll
        for (int npp = 0; npp < 2; npp++) {
            #pragma unroll
            for (int kc = 0; kc < 4; kc++) {
                const int brow0 = (2 * npp) * 16 + klrow;
                const int brow1 = (2 * npp + 1) * 16 + klrow;
                uint32_t a0 = kb + brow0 * 128 + ((kseg + kc * 32) ^ ((brow0 & 7) << 4));
                uint32_t a1 = kb + brow1 * 128 + ((kseg + kc * 32) ^ ((brow1 & 7) << 4));
                uint32_t Bh0[4], Bh1[4];
                LDSM4(Bh0, a0);
                LDSM4(Bh1, a1);
                float* s0 = S[4 * npp];     float* s1 = S[4 * npp + 1];
                float* s2 = S[4 * npp + 2]; float* s3 = S[4 * npp + 3];
                MMA16816(s0, Qh[kc], Bh0[0], Bh0[1]);
                MMA16816(s1, Qh[kc], Bh0[2], Bh0[3]);
                MMA16816(s2, Qh[kc], Bh1[0], Bh1[1]);
                MMA16816(s3, Qh[kc], Bh1[2], Bh1[3]);
                MMA16816(s0, Ql[kc], Bh0[0], Bh0[1]);
                MMA16816(s1, Ql[kc], Bh0[2], Bh0[3]);
                MMA16816(s2, Ql[kc], Bh1[0], Bh1[1]);
                MMA16816(s3, Ql[kc], Bh1[2], Bh1[3]);
            }
        }

        // ---- online softmax ----
        float mxA = -CUDART_INF_F, mxB = -CUDART_INF_F;
        #pragma unroll
        for (int nt = 0; nt < 8; nt++) {
            mxA = fmaxf(mxA, fmaxf(S[nt][0], S[nt][1]));
            mxB = fmaxf(mxB, fmaxf(S[nt][2], S[nt][3]));
        }
        #pragma unroll
        for (int o = 1; o <= 2; o <<= 1) {
            mxA = fmaxf(mxA, __shfl_xor_sync(0xffffffffu, mxA, o));
            mxB = fmaxf(mxB, __shfl_xor_sync(0xffffffffu, mxB, o));
        }
        const float mnA = fmaxf(mrow[0], mxA);
        const float mnB = fmaxf(mrow[1], mxB);
        const float alphaA = exp2f(mrow[0] - mnA);
        const float alphaB = exp2f(mrow[1] - mnB);
        mrow[0] = mnA; mrow[1] = mnB;

        uint32_t Ph[4][4], Pl[4][4];
        float sumA = 0.f, sumB = 0.f;
        #pragma unroll
        for (int nt = 0; nt < 8; nt++) {
            float p0 = exp2f(S[nt][0] - mnA);
            float p1 = exp2f(S[nt][1] - mnA);
            float p2 = exp2f(S[nt][2] - mnB);
            float p3 = exp2f(S[nt][3] - mnB);
            sumA += p0 + p1; sumB += p2 + p3;
            __nv_bfloat162 hA = __floats2bfloat162_rn(p0, p1);
            __nv_bfloat162 hB = __floats2bfloat162_rn(p2, p3);
            float2 fA = __bfloat1622float2(hA);
            float2 fB = __bfloat1622float2(hB);
            __nv_bfloat162 lA = __floats2bfloat162_rn(p0 - fA.x, p1 - fA.y);
            __nv_bfloat162 lB = __floats2bfloat162_rn(p2 - fB.x, p3 - fB.y);
            const int kc = nt >> 1, ri = (nt & 1) * 2;
            Ph[kc][ri]     = *(uint32_t*)&hA;
            Ph[kc][ri + 1] = *(uint32_t*)&hB;
            Pl[kc][ri]     = *(uint32_t*)&lA;
            Pl[kc][ri + 1] = *(uint32_t*)&lB;
        }
        #pragma unroll
        for (int o = 1; o <= 2; o <<= 1) {
            sumA += __shfl_xor_sync(0xffffffffu, sumA, o);
            sumB += __shfl_xor_sync(0xffffffffu, sumB, o);
        }
        lsum[0] = lsum[0] * alphaA + sumA;
        lsum[1] = lsum[1] * alphaB + sumB;
        #pragma unroll
        for (int nt = 0; nt < 8; nt++) {
            O[nt][0] *= alphaA; O[nt][1] *= alphaA;
            O[nt][2] *= alphaB; O[nt][3] *= alphaB;
        }

        // ---- O += P V (3-term), V via ldmatrix.trans (Vh @+8192, Vl @+16384) ----
        #pragma unroll
        for (int kc = 0; kc < 4; kc++) {
            const int vrow = kc * 16 + vlrow;
            const uint32_t vbase = kb + 8192 + vrow * 128;
            const uint32_t vxor = (vrow & 7) << 4;
            #pragma unroll
            for (int ngp = 0; ngp < 2; ngp++) {
                uint32_t o0 = ((uint32_t)((4 * ngp + vseg_half) << 4)) ^ vxor;
                uint32_t o1 = ((uint32_t)((4 * ngp + 2 + vseg_half) << 4)) ^ vxor;
                uint32_t Vh0[4], Vl0[4], Vh1[4], Vl1[4];
                LDSM4T(Vh0, vbase + o0); LDSM4T(Vl0, vbase + 8192 + o0);
                LDSM4T(Vh1, vbase + o1); LDSM4T(Vl1, vbase + 8192 + o1);
                float* d0 = O[4 * ngp];     float* d1 = O[4 * ngp + 1];
                float* d2 = O[4 * ngp + 2]; float* d3 = O[4 * ngp + 3];
                MMA16816(d0, Ph[kc], Vh0[0], Vh0[1]);
                MMA16816(d1, Ph[kc], Vh0[2], Vh0[3]);
                MMA16816(d2, Ph[kc], Vh1[0], Vh1[1]);
                MMA16816(d3, Ph[kc], Vh1[2], Vh1[3]);
                MMA16816(d0, Ph[kc], Vl0[0], Vl0[1]);
                MMA16816(d1, Ph[kc], Vl0[2], Vl0[3]);
                MMA16816(d2, Ph[kc], Vl1[0], Vl1[1]);
                MMA16816(d3, Ph[kc], Vl1[2], Vl1[3]);
                MMA16816(d0, Pl[kc], Vh0[0], Vh0[1]);
                MMA16816(d1, Pl[kc], Vh0[2], Vh0[3]);
                MMA16816(d2, Pl[kc], Vh1[0], Vh1[1]);
                MMA16816(d3, Pl[kc], Vh1[2], Vh1[3]);
            }
        }

        if (c + 2 < T_ / 64) produce(c + 2, (bufc + 2) % 3);
        CP_COMMIT();
        bufc = (bufc + 1) % 3;
    }
    CP_WAIT(0);

    // ---- epilogue: normalize, split hi/lo, store bf16 ----
    const float invA = 1.0f / lsum[0];
    const float invB = 1.0f / lsum[1];
    const int rowA = b * L_ + l0 + warp * 16 + (lane >> 2);
    #pragma unroll
    for (int nt = 0; nt < 8; nt++) {
        const int col = h * 64 + nt * 8 + (lane & 3) * 2;
        float v0 = O[nt][0] * invA, v1 = O[nt][1] * invA;
        float v2 = O[nt][2] * invB, v3 = O[nt][3] * invB;
        __nv_bfloat162 hA = __floats2bfloat162_rn(v0, v1);
        __nv_bfloat162 hB = __floats2bfloat162_rn(v2, v3);
        float2 fA = __bfloat1622float2(hA);
        float2 fB = __bfloat1622float2(hB);
        __nv_bfloat162 lA = __floats2bfloat162_rn(v0 - fA.x, v1 - fA.y);
        __nv_bfloat162 lB = __floats2bfloat162_rn(v2 - fB.x, v3 - fB.y);
        *reinterpret_cast<uint32_t*>(atth + (size_t)rowA * D_ + col) = *(uint32_t*)&hA;
        *reinterpret_cast<uint32_t*>(attl + (size_t)rowA * D_ + col) = *(uint32_t*)&lA;
        *reinterpret_cast<uint32_t*>(atth + (size_t)(rowA + 8) * D_ + col) = *(uint32_t*)&hB;
        *reinterpret_cast<uint32_t*>(attl + (size_t)(rowA + 8) * D_ + col) = *(uint32_t*)&lB;
    }
}

// =============================================================================
// launch
// =============================================================================
extern "C" void kernel_launch(void* const* d_in, const int* in_sizes, int n_in,
                              void* d_out, int out_size)
{
    const float* x     = (const float*)d_in[0];
    const float* query = (const float*)d_in[1];
    const float* Wq    = (const float*)d_in[2];
    const float* bq    = (const float*)d_in[3];
    const float* Wkv   = (const float*)d_in[4];
    const float* bkv   = (const float*)d_in[5];
    const float* Wproj = (const float*)d_in[6];
    const float* bproj = (const float*)d_in[7];
    float* out = (float*)d_out;

    __nv_bfloat16 *xh, *xl, *qih, *qil, *qh, *ql, *kvh, *kvl, *ath, *atl;
    __nv_bfloat16 *wkvh, *wkvl, *wqh, *wql, *wph, *wpl;
    cudaGetSymbolAddress((void**)&xh,  g_xh);   cudaGetSymbolAddress((void**)&xl,  g_xl);
    cudaGetSymbolAddress((void**)&qih, g_qih);  cudaGetSymbolAddress((void**)&qil, g_qil);
    cudaGetSymbolAddress((void**)&qh,  g_qh);   cudaGetSymbolAddress((void**)&ql,  g_ql);
    cudaGetSymbolAddress((void**)&kvh, g_kvh);  cudaGetSymbolAddress((void**)&kvl, g_kvl);
    cudaGetSymbolAddress((void**)&ath, g_ath);  cudaGetSymbolAddress((void**)&atl, g_atl);
    cudaGetSymbolAddress((void**)&wkvh, g_wkv_h); cudaGetSymbolAddress((void**)&wkvl, g_wkv_l);
    cudaGetSymbolAddress((void**)&wqh,  g_wq_h);  cudaGetSymbolAddress((void**)&wql,  g_wq_l);
    cudaGetSymbolAddress((void**)&wph,  g_wp_h);  cudaGetSymbolAddress((void**)&wpl,  g_wp_l);

    cudaFuncSetAttribute(gemm2, cudaFuncAttributeMaxDynamicSharedMemorySize, GEMM_SMEM);
    cudaFuncSetAttribute(attn2, cudaFuncAttributeMaxDynamicSharedMemorySize, ATTN_SMEM);

    const float cscale = 0.125f * 1.4426950408889634f;

    split_w<<<(512 * 1024 + 255) / 256, 256>>>(Wkv,   wkvh, wkvl, 512, 1024);
    split_w<<<(512 * 512  + 255) / 256, 256>>>(Wq,    wqh,  wql,  512, 512);
    split_w<<<(512 * 512  + 255) / 256, 256>>>(Wproj, wph,  wpl,  512, 512);
    split_a<<<(B_ * T_ * D_ / 4 + 255) / 256, 256>>>(x,     xh,  xl,  B_ * T_ * D_ / 4);
    split_a<<<(B_ * L_ * D_ / 4 + 255) / 256, 256>>>(query, qih, qil, B_ * L_ * D_ / 4);

    // kv = x @ Wkv + bkv : [65536, 1024] -> bf16 hi/lo
    gemm2<<<dim3(1024 / 256, (B_ * T_) / 128), 256, GEMM_SMEM>>>(
        xh, xl, wkvh, wkvl, bkv, nullptr, kvh, kvl, 1.0f, B_ * T_, 2 * D_, D_, 1);
    // q = cscale*(query @ Wq + bq) : [2048, 512] -> bf16 hi/lo
    gemm2<<<dim3(D_ / 256, (B_ * L_) / 128), 256, GEMM_SMEM>>>(
        qih, qil, wqh, wql, bq, nullptr, qh, ql, cscale, B_ * L_, D_, D_, 1);
    // attention -> att bf16 hi/lo
    attn2<<<B_ * H_ * (L_ / 128), 256, ATTN_SMEM>>>(qh, ql, kvh, kvl, ath, atl);
    // out = att @ Wproj + bproj : [2048, 512] fp32
    gemm2<<<dim3(D_ / 256, (B_ * L_) / 128), 256, GEMM_SMEM>>>(
        ath, atl, wph, wpl, bproj, out, nullptr, nullptr, 1.0f, B_ * L_, D_, D_, 0);
}

// round 9
// speedup vs baseline: 1.1531x; 1.1436x over previous
#include <cuda_runtime.h>
#include <cuda_bf16.h>
#include <math_constants.h>
#include <cstdint>

// Problem constants
#define B_ 8
#define T_ 8192
#define L_ 256
#define D_ 512
#define H_ 8
// HD = 64, scale = 1/8

// ---------------- scratch (device globals; no allocs allowed) ----------------
__device__ __nv_bfloat16 g_qh [(size_t)B_ * L_ * D_],  g_ql [(size_t)B_ * L_ * D_];
__device__ __nv_bfloat16 g_kvh[(size_t)B_ * T_ * 2 * D_], g_kvl[(size_t)B_ * T_ * 2 * D_];
__device__ float         g_att[(size_t)B_ * L_ * D_];

__device__ __nv_bfloat16 g_wkv_h[1024 * 512], g_wkv_l[1024 * 512];   // Wkv^T split
__device__ __nv_bfloat16 g_wq_h [512 * 512],  g_wq_l [512 * 512];    // Wq^T split
__device__ __nv_bfloat16 g_wp_h [512 * 512],  g_wp_l [512 * 512];    // Wproj^T split

__device__ __forceinline__ uint32_t smem_u32(const void* p) {
    uint32_t a;
    asm("{ .reg .u64 t; cvta.to.shared.u64 t, %1; cvt.u32.u64 %0, t; }"
        : "=r"(a) : "l"(p));
    return a;
}

#define CP16(dst, src) \
    asm volatile("cp.async.cg.shared.global [%0], [%1], 16;" :: "r"(dst), "l"(src))
#define CP_COMMIT() asm volatile("cp.async.commit_group;" ::: "memory")
#define CP_WAIT(n)  asm volatile("cp.async.wait_group %0;" :: "n"(n) : "memory")

#define LDSM4(r, addr) \
    asm volatile("ldmatrix.sync.aligned.m8n8.x4.shared.b16 {%0,%1,%2,%3}, [%4];" \
        : "=r"((r)[0]), "=r"((r)[1]), "=r"((r)[2]), "=r"((r)[3]) : "r"(addr))
#define LDSM4T(r, addr) \
    asm volatile("ldmatrix.sync.aligned.m8n8.x4.trans.shared.b16 {%0,%1,%2,%3}, [%4];" \
        : "=r"((r)[0]), "=r"((r)[1]), "=r"((r)[2]), "=r"((r)[3]) : "r"(addr))

#define MMA16816(d, a, b0r, b1r) \
    asm volatile("mma.sync.aligned.m16n8k16.row.col.f32.bf16.bf16.f32 " \
        "{%0,%1,%2,%3}, {%4,%5,%6,%7}, {%8,%9}, {%0,%1,%2,%3};" \
        : "+f"((d)[0]), "+f"((d)[1]), "+f"((d)[2]), "+f"((d)[3]) \
        : "r"((a)[0]), "r"((a)[1]), "r"((a)[2]), "r"((a)[3]), "r"(b0r), "r"(b1r))

#define SWZ64(o)  ((o) ^ ((((o) >> 7) & 3) << 4))
#define SWZ128(o) ((o) ^ ((((o) >> 7) & 7) << 4))

// =============================================================================
// Weight split/transpose: W[K,N] fp32 -> Wt_hi/Wt_lo [N,K] bf16
// =============================================================================
__global__ void split_w(const float* __restrict__ W, __nv_bfloat16* __restrict__ Th,
                        __nv_bfloat16* __restrict__ Tl, int K, int N)
{
    int idx = blockIdx.x * blockDim.x + threadIdx.x;
    if (idx >= K * N) return;
    int k = idx / N, n = idx % N;
    float w = W[idx];
    __nv_bfloat16 h = __float2bfloat16_rn(w);
    float r = w - __bfloat162float(h);
    Th[(size_t)n * K + k] = h;
    Tl[(size_t)n * K + k] = __float2bfloat16_rn(r);
}

// =============================================================================
// HMMA GEMM (R4-proven config): C = A(fp32) @ Wt^T + bias.
// CTA 128x128, 8 warps (2x4), warp 64x32, K-chunk 32, 2-stage smem,
// A: LDG fp32 prefetch + in-producer hi/lo split; B: bf16 pre-split LDG->STS.
// mode 0: fp32 out. mode 1: bf16 hi/lo out, v = scale*(acc+bias).
// =============================================================================
#define GEMM_SMEM 65536

__global__ __launch_bounds__(256, 1)
void gemm_mma(const float* __restrict__ A,
              const __nv_bfloat16* __restrict__ Bth, const __nv_bfloat16* __restrict__ Btl,
              const float* __restrict__ bias, float* __restrict__ Cf,
              __nv_bfloat16* __restrict__ Ch, __nv_bfloat16* __restrict__ Cl,
              float scale, int M, int N, int K, int mode)
{
    extern __shared__ char smem[];
    const int tid  = threadIdx.x;
    const int lane = tid & 31;
    const int warp = tid >> 5;
    const int wm = warp >> 2;
    const int wn = warp & 3;
    const int bm = blockIdx.y * 128;
    const int bn = blockIdx.x * 128;

    float acc[4][4][4];
    #pragma unroll
    for (int i = 0; i < 4; i++)
        #pragma unroll
        for (int j = 0; j < 4; j++)
            #pragma unroll
            for (int k = 0; k < 4; k++) acc[i][j][k] = 0.f;

    const int nchunk = K >> 5;
    float4 pa[4];
    uint4  pbh[2], pbl[2];

    auto loadg = [&](int c) {
        #pragma unroll
        for (int i = 0; i < 4; i++) {
            int idx = tid + i * 256;
            int r = idx >> 3, k4 = idx & 7;
            pa[i] = *reinterpret_cast<const float4*>(
                A + (size_t)(bm + r) * K + c * 32 + k4 * 4);
        }
        #pragma unroll
        for (int i = 0; i < 2; i++) {
            int idx = tid + i * 256;
            int n = idx >> 2, s = idx & 3;
            const size_t go = (size_t)(bn + n) * K + c * 32 + s * 8;
            pbh[i] = *reinterpret_cast<const uint4*>(Bth + go);
            pbl[i] = *reinterpret_cast<const uint4*>(Btl + go);
        }
    };

    auto storeS = [&](int buf) {
        char* base = smem + buf * 32768;
        #pragma unroll
        for (int i = 0; i < 4; i++) {
            int idx = tid + i * 256;
            int r = idx >> 3, k4 = idx & 7;
            int off = r * 64 + k4 * 8;
            int sw = SWZ64(off);
            float4 v = pa[i];
            __nv_bfloat162 h01 = __floats2bfloat162_rn(v.x, v.y);
            __nv_bfloat162 h23 = __floats2bfloat162_rn(v.z, v.w);
            float2 f01 = __bfloat1622float2(h01);
            float2 f23 = __bfloat1622float2(h23);
            __nv_bfloat162 l01 = __floats2bfloat162_rn(v.x - f01.x, v.y - f01.y);
            __nv_bfloat162 l23 = __floats2bfloat162_rn(v.z - f23.x, v.w - f23.y);
            *reinterpret_cast<uint2*>(base + sw) =
                make_uint2(*(uint32_t*)&h01, *(uint32_t*)&h23);
            *reinterpret_cast<uint2*>(base + 8192 + sw) =
                make_uint2(*(uint32_t*)&l01, *(uint32_t*)&l23);
        }
        #pragma unroll
        for (int i = 0; i < 2; i++) {
            int idx = tid + i * 256;
            int n = idx >> 2, s = idx & 3;
            int off = n * 64 + s * 16;
            int sw = SWZ64(off);
            *reinterpret_cast<uint4*>(base + 16384 + sw) = pbh[i];
            *reinterpret_cast<uint4*>(base + 24576 + sw) = pbl[i];
        }
    };

    const uint32_t sbase = smem_u32(smem);
    const uint32_t arow  = wm * 64 + (lane & 15);
    const uint32_t aoffb = arow * 64 + ((lane >> 4) << 4);
    const uint32_t axor  = ((arow >> 1) & 3) << 4;
    const uint32_t brow  = wn * 32 + (lane & 7) + ((lane >> 4) << 3);
    const uint32_t boffb = brow * 64 + (((lane >> 3) & 1) << 4);
    const uint32_t bxor  = ((brow >> 1) & 3) << 4;

    auto compute = [&](int buf) {
        const uint32_t sa = sbase + buf * 32768;
        #pragma unroll
        for (int ks = 0; ks < 2; ks++) {
            uint32_t Ah[4][4], Al[4][4];
            #pragma unroll
            for (int mt = 0; mt < 4; mt++) {
                uint32_t addr = (sa + aoffb + mt * 1024 + ks * 32) ^ axor;
                LDSM4(Ah[mt], addr);
                LDSM4(Al[mt], addr + 8192);
            }
            uint32_t Bh[2][4], Bl[2][4];
            #pragma unroll
            for (int np = 0; np < 2; np++) {
                uint32_t addr = (sa + 16384 + boffb + np * 1024 + ks * 32) ^ bxor;
                LDSM4(Bh[np], addr);
                LDSM4(Bl[np], addr + 8192);
            }
            #pragma unroll
            for (int mt = 0; mt < 4; mt++)
                #pragma unroll
                for (int nt = 0; nt < 4; nt++) {
                    const int np = nt >> 1, bi = (nt & 1) * 2;
                    MMA16816(acc[mt][nt], Ah[mt], Bh[np][bi], Bh[np][bi + 1]);
                }
            #pragma unroll
            for (int mt = 0; mt < 4; mt++)
                #pragma unroll
                for (int nt = 0; nt < 4; nt++) {
                    const int np = nt >> 1, bi = (nt & 1) * 2;
                    MMA16816(acc[mt][nt], Ah[mt], Bl[np][bi], Bl[np][bi + 1]);
                }
            #pragma unroll
            for (int mt = 0; mt < 4; mt++)
                #pragma unroll
                for (int nt = 0; nt < 4; nt++) {
                    const int np = nt >> 1, bi = (nt & 1) * 2;
                    MMA16816(acc[mt][nt], Al[mt], Bh[np][bi], Bh[np][bi + 1]);
                }
        }
    };

    loadg(0);
    storeS(0);
    __syncthreads();
    for (int c = 0; c < nchunk; c++) {
        if (c + 1 < nchunk) loadg(c + 1);
        compute(c & 1);
        if (c + 1 < nchunk) {
            storeS((c + 1) & 1);
            __syncthreads();
        }
    }

    // ---- epilogue ----
    #pragma unroll
    for (int nt = 0; nt < 4; nt++) {
        const int ncol = bn + wn * 32 + nt * 8 + 2 * (lane & 3);
        const float2 bb = *reinterpret_cast<const float2*>(bias + ncol);
        #pragma unroll
        for (int mt = 0; mt < 4; mt++) {
            const int m0 = bm + wm * 64 + mt * 16 + (lane >> 2);
            float v0 = acc[mt][nt][0] + bb.x, v1 = acc[mt][nt][1] + bb.y;
            float v2 = acc[mt][nt][2] + bb.x, v3 = acc[mt][nt][3] + bb.y;
            if (mode == 0) {
                *reinterpret_cast<float2*>(Cf + (size_t)m0 * N + ncol) =
                    make_float2(v0, v1);
                *reinterpret_cast<float2*>(Cf + (size_t)(m0 + 8) * N + ncol) =
                    make_float2(v2, v3);
            } else {
                v0 *= scale; v1 *= scale; v2 *= scale; v3 *= scale;
                __nv_bfloat162 h01 = __floats2bfloat162_rn(v0, v1);
                __nv_bfloat162 h23 = __floats2bfloat162_rn(v2, v3);
                float2 f01 = __bfloat1622float2(h01);
                float2 f23 = __bfloat1622float2(h23);
                __nv_bfloat162 l01 = __floats2bfloat162_rn(v0 - f01.x, v1 - f01.y);
                __nv_bfloat162 l23 = __floats2bfloat162_rn(v2 - f23.x, v3 - f23.y);
                *reinterpret_cast<uint32_t*>(Ch + (size_t)m0 * N + ncol) = *(uint32_t*)&h01;
                *reinterpret_cast<uint32_t*>(Cl + (size_t)m0 * N + ncol) = *(uint32_t*)&l01;
                *reinterpret_cast<uint32_t*>(Ch + (size_t)(m0 + 8) * N + ncol) = *(uint32_t*)&h23;
                *reinterpret_cast<uint32_t*>(Cl + (size_t)(m0 + 8) * N + ncol) = *(uint32_t*)&l23;
            }
        }
    }
}

// =============================================================================
// HMMA flash attention. 128 threads / 4 warps / 64 Q-rows per CTA; grid 256;
// 2 CTAs per SM (softmax of one CTA overlaps MMA of the other).
// QK = (Qh+Ql)*Kh (2-term); PV = 3-term. Stage = 24KB (Kh|Vh|Vl), 3-stage ring
// @0/24K/48K; Q hi @72K, Q lo @80K. smem = 88KB.
// =============================================================================
#define ATTN_SMEM 90112

__global__ __launch_bounds__(128, 2)
void attn2(const __nv_bfloat16* __restrict__ qsh, const __nv_bfloat16* __restrict__ qsl,
           const __nv_bfloat16* __restrict__ kvh, const __nv_bfloat16* __restrict__ kvl,
           float* __restrict__ attf)
{
    extern __shared__ char smem[];
    const uint32_t sb = smem_u32(smem);
    const int tid = threadIdx.x, lane = tid & 31, warp = tid >> 5;
    const int bid = blockIdx.x;        // b*32 + h*4 + lt
    const int lt = bid & 3;
    const int h  = (bid >> 2) & 7;
    const int b  = bid >> 5;
    const int l0 = lt * 64;

    // ---- Q staging: hi @73728, lo @81920 (64 rows x 64 dims each) ----
    #pragma unroll
    for (int i = 0; i < 4; i++) {
        int idx = tid + i * 128;            // 0..511
        int r = idx >> 3, sg = idx & 7;
        uint32_t sw = SWZ128(r * 128 + sg * 16);
        size_t g = (size_t)(b * L_ + l0 + r) * 512 + h * 64 + sg * 8;
        CP16(sb + 73728 + sw, qsh + g);
        CP16(sb + 81920 + sw, qsl + g);
    }
    CP_COMMIT();
    CP_WAIT(0);
    __syncthreads();

    uint32_t Qh[4][4], Ql[4][4];
    {
        const int arow = warp * 16 + (lane & 15);
        const uint32_t abase = sb + 73728 + arow * 128;
        const uint32_t axor = (arow & 7) << 4;
        #pragma unroll
        for (int kc = 0; kc < 4; kc++) {
            uint32_t o = ((((uint32_t)(lane >> 4) << 4) + kc * 32)) ^ axor;
            LDSM4(Qh[kc], abase + o);
            LDSM4(Ql[kc], abase + 8192 + o);
        }
    }
    __syncthreads();

    auto produce = [&](int c, int s) {
        const uint32_t base = sb + (uint32_t)s * 24576;
        #pragma unroll
        for (int i = 0; i < 4; i++) {
            int idx = tid + i * 128;        // 0..511
            int r = idx >> 3, sg = idx & 7;
            uint32_t sw = SWZ128(r * 128 + sg * 16);
            size_t g = (size_t)(b * T_ + c * 64 + r) * 1024 + h * 64 + sg * 8;
            CP16(base + sw,         kvh + g);          // Kh
            CP16(base + 8192 + sw,  kvh + g + 512);    // Vh
            CP16(base + 16384 + sw, kvl + g + 512);    // Vl
        }
    };
    produce(0, 0); CP_COMMIT();
    produce(1, 1); CP_COMMIT();

    float mrow[2] = { -CUDART_INF_F, -CUDART_INF_F };
    float lsum[2] = { 0.f, 0.f };
    float O[8][4];
    #pragma unroll
    for (int i = 0; i < 8; i++)
        #pragma unroll
        for (int j = 0; j < 4; j++) O[i][j] = 0.f;

    const int klrow = (lane & 7) + ((lane >> 4) << 3);
    const uint32_t kseg = ((uint32_t)((lane >> 3) & 1)) << 4;
    const int vlrow = (lane & 7) + (((lane >> 3) & 1) << 3);
    const int vseg_half = lane >> 4;

    int bufc = 0;
    for (int c = 0; c < T_ / 64; c++) {
        CP_WAIT(1);
        __syncthreads();
        const uint32_t kb = sb + (uint32_t)bufc * 24576;

        // ---- S = (Qh + Ql) * Kh  (2-term) ----
        float S[8][4];
        #pragma unroll
        for (int i = 0; i < 8; i++)
            #pragma unroll
            for (int j = 0; j < 4; j++) S[i][j] = 0.f;

        #pragma unroll
        for (int npp = 0; npp < 2; npp++) {
            #pragma unroll
            for (int kc = 0; kc < 4; kc++) {
                const int brow0 = (2 * npp) * 16 + klrow;
                const int brow1 = (2 * npp + 1) * 16 + klrow;
                uint32_t a0 = kb + brow0 * 128 + ((kseg + kc * 32) ^ ((brow0 & 7) << 4));
                uint32_t a1 = kb + brow1 * 128 + ((kseg + kc * 32) ^ ((brow1 & 7) << 4));
                uint32_t Bh0[4], Bh1[4];
                LDSM4(Bh0, a0);
                LDSM4(Bh1, a1);
                float* s0 = S[4 * npp];     float* s1 = S[4 * npp + 1];
                float* s2 = S[4 * npp + 2]; float* s3 = S[4 * npp + 3];
                MMA16816(s0, Qh[kc], Bh0[0], Bh0[1]);
                MMA16816(s1, Qh[kc], Bh0[2], Bh0[3]);
                MMA16816(s2, Qh[kc], Bh1[0], Bh1[1]);
                MMA16816(s3, Qh[kc], Bh1[2], Bh1[3]);
                MMA16816(s0, Ql[kc], Bh0[0], Bh0[1]);
                MMA16816(s1, Ql[kc], Bh0[2], Bh0[3]);
                MMA16816(s2, Ql[kc], Bh1[0], Bh1[1]);
                MMA16816(s3, Ql[kc], Bh1[2], Bh1[3]);
            }
        }

        // ---- online softmax ----
        float mxA = -CUDART_INF_F, mxB = -CUDART_INF_F;
        #pragma unroll
        for (int nt = 0; nt < 8; nt++) {
            mxA = fmaxf(mxA, fmaxf(S[nt][0], S[nt][1]));
            mxB = fmaxf(mxB, fmaxf(S[nt][2], S[nt][3]));
        }
        #pragma unroll
        for (int o = 1; o <= 2; o <<= 1) {
            mxA = fmaxf(mxA, __shfl_xor_sync(0xffffffffu, mxA, o));
            mxB = fmaxf(mxB, __shfl_xor_sync(0xffffffffu, mxB, o));
        }
        const float mnA = fmaxf(mrow[0], mxA);
        const float mnB = fmaxf(mrow[1], mxB);
        const float alphaA = exp2f(mrow[0] - mnA);
        const float alphaB = exp2f(mrow[1] - mnB);
        mrow[0] = mnA; mrow[1] = mnB;

        uint32_t Ph[4][4], Pl[4][4];
        float sumA = 0.f, sumB = 0.f;
        #pragma unroll
        for (int nt = 0; nt < 8; nt++) {
            float p0 = exp2f(S[nt][0] - mnA);
            float p1 = exp2f(S[nt][1] - mnA);
            float p2 = exp2f(S[nt][2] - mnB);
            float p3 = exp2f(S[nt][3] - mnB);
            sumA += p0 + p1; sumB += p2 + p3;
            __nv_bfloat162 hA = __floats2bfloat162_rn(p0, p1);
            __nv_bfloat162 hB = __floats2bfloat162_rn(p2, p3);
            float2 fA = __bfloat1622float2(hA);
            float2 fB = __bfloat1622float2(hB);
            __nv_bfloat162 lA = __floats2bfloat162_rn(p0 - fA.x, p1 - fA.y);
            __nv_bfloat162 lB = __floats2bfloat162_rn(p2 - fB.x, p3 - fB.y);
            const int kc = nt >> 1, ri = (nt & 1) * 2;
            Ph[kc][ri]     = *(uint32_t*)&hA;
            Ph[kc][ri + 1] = *(uint32_t*)&hB;
            Pl[kc][ri]     = *(uint32_t*)&lA;
            Pl[kc][ri + 1] = *(uint32_t*)&lB;
        }
        #pragma unroll
        for (int o = 1; o <= 2; o <<= 1) {
            sumA += __shfl_xor_sync(0xffffffffu, sumA, o);
            sumB += __shfl_xor_sync(0xffffffffu, sumB, o);
        }
        lsum[0] = lsum[0] * alphaA + sumA;
        lsum[1] = lsum[1] * alphaB + sumB;
        #pragma unroll
        for (int nt = 0; nt < 8; nt++) {
            O[nt][0] *= alphaA; O[nt][1] *= alphaA;
            O[nt][2] *= alphaB; O[nt][3] *= alphaB;
        }

        // ---- O += P V (3-term), V via ldmatrix.trans (Vh @+8192, Vl @+16384) ----
        #pragma unroll
        for (int kc = 0; kc < 4; kc++) {
            const int vrow = kc * 16 + vlrow;
            const uint32_t vbase = kb + 8192 + vrow * 128;
            const uint32_t vxor = (vrow & 7) << 4;
            #pragma unroll
            for (int ngp = 0; ngp < 2; ngp++) {
                uint32_t o0 = ((uint32_t)((4 * ngp + vseg_half) << 4)) ^ vxor;
                uint32_t o1 = ((uint32_t)((4 * ngp + 2 + vseg_half) << 4)) ^ vxor;
                uint32_t Vh0[4], Vl0[4], Vh1[4], Vl1[4];
                LDSM4T(Vh0, vbase + o0); LDSM4T(Vl0, vbase + 8192 + o0);
                LDSM4T(Vh1, vbase + o1); LDSM4T(Vl1, vbase + 8192 + o1);
                float* d0 = O[4 * ngp];     float* d1 = O[4 * ngp + 1];
                float* d2 = O[4 * ngp + 2]; float* d3 = O[4 * ngp + 3];
                MMA16816(d0, Ph[kc], Vh0[0], Vh0[1]);
                MMA16816(d1, Ph[kc], Vh0[2], Vh0[3]);
                MMA16816(d2, Ph[kc], Vh1[0], Vh1[1]);
                MMA16816(d3, Ph[kc], Vh1[2], Vh1[3]);
                MMA16816(d0, Ph[kc], Vl0[0], Vl0[1]);
                MMA16816(d1, Ph[kc], Vl0[2], Vl0[3]);
                MMA16816(d2, Ph[kc], Vl1[0], Vl1[1]);
                MMA16816(d3, Ph[kc], Vl1[2], Vl1[3]);
                MMA16816(d0, Pl[kc], Vh0[0], Vh0[1]);
                MMA16816(d1, Pl[kc], Vh0[2], Vh0[3]);
                MMA16816(d2, Pl[kc], Vh1[0], Vh1[1]);
                MMA16816(d3, Pl[kc], Vh1[2], Vh1[3]);
            }
        }

        if (c + 2 < T_ / 64) produce(c + 2, (bufc + 2) % 3);
        CP_COMMIT();
        bufc = (bufc + 1) % 3;
    }
    CP_WAIT(0);

    // ---- epilogue: normalize, store fp32 ----
    const float invA = 1.0f / lsum[0];
    const float invB = 1.0f / lsum[1];
    const int rowA = b * L_ + l0 + warp * 16 + (lane >> 2);
    #pragma unroll
    for (int nt = 0; nt < 8; nt++) {
        const int col = h * 64 + nt * 8 + (lane & 3) * 2;
        *reinterpret_cast<float2*>(attf + (size_t)rowA * D_ + col) =
            make_float2(O[nt][0] * invA, O[nt][1] * invA);
        *reinterpret_cast<float2*>(attf + (size_t)(rowA + 8) * D_ + col) =
            make_float2(O[nt][2] * invB, O[nt][3] * invB);
    }
}

// =============================================================================
// launch
// =============================================================================
extern "C" void kernel_launch(void* const* d_in, const int* in_sizes, int n_in,
                              void* d_out, int out_size)
{
    const float* x     = (const float*)d_in[0];
    const float* query = (const float*)d_in[1];
    const float* Wq    = (const float*)d_in[2];
    const float* bq    = (const float*)d_in[3];
    const float* Wkv   = (const float*)d_in[4];
    const float* bkv   = (const float*)d_in[5];
    const float* Wproj = (const float*)d_in[6];
    const float* bproj = (const float*)d_in[7];
    float* out = (float*)d_out;

    __nv_bfloat16 *qh, *ql, *kvh, *kvl;
    float* att;
    __nv_bfloat16 *wkvh, *wkvl, *wqh, *wql, *wph, *wpl;
    cudaGetSymbolAddress((void**)&qh,  g_qh);   cudaGetSymbolAddress((void**)&ql,  g_ql);
    cudaGetSymbolAddress((void**)&kvh, g_kvh);  cudaGetSymbolAddress((void**)&kvl, g_kvl);
    cudaGetSymbolAddress((void**)&att, g_att);
    cudaGetSymbolAddress((void**)&wkvh, g_wkv_h); cudaGetSymbolAddress((void**)&wkvl, g_wkv_l);
    cudaGetSymbolAddress((void**)&wqh,  g_wq_h);  cudaGetSymbolAddress((void**)&wql,  g_wq_l);
    cudaGetSymbolAddress((void**)&wph,  g_wp_h);  cudaGetSymbolAddress((void**)&wpl,  g_wp_l);

    cudaFuncSetAttribute(gemm_mma, cudaFuncAttributeMaxDynamicSharedMemorySize, GEMM_SMEM);
    cudaFuncSetAttribute(attn2, cudaFuncAttributeMaxDynamicSharedMemorySize, ATTN_SMEM);

    const float cscale = 0.125f * 1.4426950408889634f;

    split_w<<<(512 * 1024 + 255) / 256, 256>>>(Wkv,   wkvh, wkvl, 512, 1024);
    split_w<<<(512 * 512  + 255) / 256, 256>>>(Wq,    wqh,  wql,  512, 512);
    split_w<<<(512 * 512  + 255) / 256, 256>>>(Wproj, wph,  wpl,  512, 512);

    // kv = x @ Wkv + bkv : [65536, 1024] -> bf16 hi/lo
    gemm_mma<<<dim3(1024 / 128, (B_ * T_) / 128), 256, GEMM_SMEM>>>(
        x, wkvh, wkvl, bkv, nullptr, kvh, kvl, 1.0f, B_ * T_, 2 * D_, D_, 1);
    // q = cscale*(query @ Wq + bq) : [2048, 512] -> bf16 hi/lo
    gemm_mma<<<dim3(D_ / 128, (B_ * L_) / 128), 256, GEMM_SMEM>>>(
        query, wqh, wql, bq, nullptr, qh, ql, cscale, B_ * L_, D_, D_, 1);
    // attention -> att fp32 (grid 256, 128 threads, 2 CTAs/SM)
    attn2<<<B_ * H_ * (L_ / 64), 128, ATTN_SMEM>>>(qh, ql, kvh, kvl, att);
    // out = att @ Wproj + bproj : [2048, 512] fp32
    gemm_mma<<<dim3(D_ / 128, (B_ * L_) / 128), 256, GEMM_SMEM>>>(
        att, wph, wpl, bproj, out, nullptr, nullptr, 1.0f, B_ * L_, D_, D_, 0);
}

// round 10
// speedup vs baseline: 1.1641x; 1.0095x over previous
#include <cuda_runtime.h>
#include <cuda_bf16.h>
#include <math_constants.h>
#include <cstdint>

// Problem constants
#define B_ 8
#define T_ 8192
#define L_ 256
#define D_ 512
#define H_ 8
// HD = 64, scale = 1/8

// ---------------- scratch (device globals; no allocs allowed) ----------------
__device__ __nv_bfloat16 g_qh [(size_t)B_ * L_ * D_],  g_ql [(size_t)B_ * L_ * D_];
__device__ __nv_bfloat16 g_kvh[(size_t)B_ * T_ * 2 * D_], g_kvl[(size_t)B_ * T_ * 2 * D_];
__device__ float         g_att[(size_t)B_ * L_ * D_];

__device__ __nv_bfloat16 g_wkv_h[1024 * 512], g_wkv_l[1024 * 512];   // Wkv^T split
__device__ __nv_bfloat16 g_wq_h [512 * 512],  g_wq_l [512 * 512];    // Wq^T split
__device__ __nv_bfloat16 g_wp_h [512 * 512],  g_wp_l [512 * 512];    // Wproj^T split

__device__ __forceinline__ uint32_t smem_u32(const void* p) {
    uint32_t a;
    asm("{ .reg .u64 t; cvta.to.shared.u64 t, %1; cvt.u32.u64 %0, t; }"
        : "=r"(a) : "l"(p));
    return a;
}

#define CP16(dst, src) \
    asm volatile("cp.async.cg.shared.global [%0], [%1], 16;" :: "r"(dst), "l"(src))
#define CP_COMMIT() asm volatile("cp.async.commit_group;" ::: "memory")
#define CP_WAIT(n)  asm volatile("cp.async.wait_group %0;" :: "n"(n) : "memory")

#define LDSM4(r, addr) \
    asm volatile("ldmatrix.sync.aligned.m8n8.x4.shared.b16 {%0,%1,%2,%3}, [%4];" \
        : "=r"((r)[0]), "=r"((r)[1]), "=r"((r)[2]), "=r"((r)[3]) : "r"(addr))
#define LDSM4T(r, addr) \
    asm volatile("ldmatrix.sync.aligned.m8n8.x4.trans.shared.b16 {%0,%1,%2,%3}, [%4];" \
        : "=r"((r)[0]), "=r"((r)[1]), "=r"((r)[2]), "=r"((r)[3]) : "r"(addr))

#define MMA16816(d, a, b0r, b1r) \
    asm volatile("mma.sync.aligned.m16n8k16.row.col.f32.bf16.bf16.f32 " \
        "{%0,%1,%2,%3}, {%4,%5,%6,%7}, {%8,%9}, {%0,%1,%2,%3};" \
        : "+f"((d)[0]), "+f"((d)[1]), "+f"((d)[2]), "+f"((d)[3]) \
        : "r"((a)[0]), "r"((a)[1]), "r"((a)[2]), "r"((a)[3]), "r"(b0r), "r"(b1r))

#define SWZ64(o)  ((o) ^ ((((o) >> 7) & 3) << 4))
#define SWZ128(o) ((o) ^ ((((o) >> 7) & 7) << 4))

// =============================================================================
// Weight split/transpose: W[K,N] fp32 -> Wt_hi/Wt_lo [N,K] bf16
// =============================================================================
__global__ void split_w(const float* __restrict__ W, __nv_bfloat16* __restrict__ Th,
                        __nv_bfloat16* __restrict__ Tl, int K, int N)
{
    int idx = blockIdx.x * blockDim.x + threadIdx.x;
    if (idx >= K * N) return;
    int k = idx / N, n = idx % N;
    float w = W[idx];
    __nv_bfloat16 h = __float2bfloat16_rn(w);
    float r = w - __bfloat162float(h);
    Th[(size_t)n * K + k] = h;
    Tl[(size_t)n * K + k] = __float2bfloat16_rn(r);
}

// =============================================================================
// Fused kv+q GEMM (R4-proven 128x128 structure, 8 warps, warp 64x32, Kc=32).
// grid (8, 528): by<512 -> kv rows (N=1024); by>=512 -> q rows (N=512, bx<4).
// kv K-columns (bx<4): 2-term compute, Ch only (Kl never consumed).
// kv V-columns & q: 3-term, Ch+Cl. Output v = scale*(acc+bias) -> bf16 hi/lo.
// =============================================================================
#define GEMM_SMEM 65536

__global__ __launch_bounds__(256, 1)
void gemm_kvq(const float* __restrict__ x, const float* __restrict__ query,
              const __nv_bfloat16* __restrict__ wkvh, const __nv_bfloat16* __restrict__ wkvl,
              const __nv_bfloat16* __restrict__ wqh,  const __nv_bfloat16* __restrict__ wql,
              const float* __restrict__ bkv, const float* __restrict__ bq,
              __nv_bfloat16* __restrict__ kvh, __nv_bfloat16* __restrict__ kvl,
              __nv_bfloat16* __restrict__ qh,  __nv_bfloat16* __restrict__ ql,
              float cscale)
{
    const bool isQ = (blockIdx.y >= 512);
    if (isQ && blockIdx.x >= 4) return;

    const float* A               = isQ ? query : x;
    const __nv_bfloat16* Bth     = isQ ? wqh : wkvh;
    const __nv_bfloat16* Btl     = isQ ? wql : wkvl;
    const float* bias            = isQ ? bq : bkv;
    __nv_bfloat16* Ch            = isQ ? qh : kvh;
    __nv_bfloat16* Cl            = isQ ? ql : kvl;
    const float scale            = isQ ? cscale : 1.0f;
    const int N                  = isQ ? 512 : 1024;
    const int K                  = 512;
    const int bm = (isQ ? (blockIdx.y - 512) : blockIdx.y) * 128;
    const int bn = blockIdx.x * 128;
    const bool two_term = (!isQ) && (blockIdx.x < 4);   // kv K-columns

    extern __shared__ char smem[];
    const int tid  = threadIdx.x;
    const int lane = tid & 31;
    const int warp = tid >> 5;
    const int wm = warp >> 2;
    const int wn = warp & 3;

    float acc[4][4][4];
    #pragma unroll
    for (int i = 0; i < 4; i++)
        #pragma unroll
        for (int j = 0; j < 4; j++)
            #pragma unroll
            for (int k = 0; k < 4; k++) acc[i][j][k] = 0.f;

    const int nchunk = K >> 5;
    float4 pa[4];
    uint4  pbh[2], pbl[2];

    auto loadg = [&](int c) {
        #pragma unroll
        for (int i = 0; i < 4; i++) {
            int idx = tid + i * 256;
            int r = idx >> 3, k4 = idx & 7;
            pa[i] = *reinterpret_cast<const float4*>(
                A + (size_t)(bm + r) * K + c * 32 + k4 * 4);
        }
        #pragma unroll
        for (int i = 0; i < 2; i++) {
            int idx = tid + i * 256;
            int n = idx >> 2, s = idx & 3;
            const size_t go = (size_t)(bn + n) * K + c * 32 + s * 8;
            pbh[i] = *reinterpret_cast<const uint4*>(Bth + go);
            pbl[i] = *reinterpret_cast<const uint4*>(Btl + go);
        }
    };

    auto storeS = [&](int buf) {
        char* base = smem + buf * 32768;
        #pragma unroll
        for (int i = 0; i < 4; i++) {
            int idx = tid + i * 256;
            int r = idx >> 3, k4 = idx & 7;
            int off = r * 64 + k4 * 8;
            int sw = SWZ64(off);
            float4 v = pa[i];
            __nv_bfloat162 h01 = __floats2bfloat162_rn(v.x, v.y);
            __nv_bfloat162 h23 = __floats2bfloat162_rn(v.z, v.w);
            float2 f01 = __bfloat1622float2(h01);
            float2 f23 = __bfloat1622float2(h23);
            __nv_bfloat162 l01 = __floats2bfloat162_rn(v.x - f01.x, v.y - f01.y);
            __nv_bfloat162 l23 = __floats2bfloat162_rn(v.z - f23.x, v.w - f23.y);
            *reinterpret_cast<uint2*>(base + sw) =
                make_uint2(*(uint32_t*)&h01, *(uint32_t*)&h23);
            *reinterpret_cast<uint2*>(base + 8192 + sw) =
                make_uint2(*(uint32_t*)&l01, *(uint32_t*)&l23);
        }
        #pragma unroll
        for (int i = 0; i < 2; i++) {
            int idx = tid + i * 256;
            int n = idx >> 2, s = idx & 3;
            int off = n * 64 + s * 16;
            int sw = SWZ64(off);
            *reinterpret_cast<uint4*>(base + 16384 + sw) = pbh[i];
            *reinterpret_cast<uint4*>(base + 24576 + sw) = pbl[i];
        }
    };

    const uint32_t sbase = smem_u32(smem);
    const uint32_t arow  = wm * 64 + (lane & 15);
    const uint32_t aoffb = arow * 64 + ((lane >> 4) << 4);
    const uint32_t axor  = ((arow >> 1) & 3) << 4;
    const uint32_t brow  = wn * 32 + (lane & 7) + ((lane >> 4) << 3);
    const uint32_t boffb = brow * 64 + (((lane >> 3) & 1) << 4);
    const uint32_t bxor  = ((brow >> 1) & 3) << 4;

    auto compute = [&](int buf) {
        const uint32_t sa = sbase + buf * 32768;
        #pragma unroll
        for (int ks = 0; ks < 2; ks++) {
            uint32_t Ah[4][4], Al[4][4];
            #pragma unroll
            for (int mt = 0; mt < 4; mt++) {
                uint32_t addr = (sa + aoffb + mt * 1024 + ks * 32) ^ axor;
                LDSM4(Ah[mt], addr);
                LDSM4(Al[mt], addr + 8192);
            }
            uint32_t Bh[2][4], Bl[2][4];
            #pragma unroll
            for (int np = 0; np < 2; np++) {
                uint32_t addr = (sa + 16384 + boffb + np * 1024 + ks * 32) ^ bxor;
                LDSM4(Bh[np], addr);
                LDSM4(Bl[np], addr + 8192);
            }
            #pragma unroll
            for (int mt = 0; mt < 4; mt++)
                #pragma unroll
                for (int nt = 0; nt < 4; nt++) {
                    const int np = nt >> 1, bi = (nt & 1) * 2;
                    MMA16816(acc[mt][nt], Ah[mt], Bh[np][bi], Bh[np][bi + 1]);
                }
            #pragma unroll
            for (int mt = 0; mt < 4; mt++)
                #pragma unroll
                for (int nt = 0; nt < 4; nt++) {
                    const int np = nt >> 1, bi = (nt & 1) * 2;
                    MMA16816(acc[mt][nt], Ah[mt], Bl[np][bi], Bl[np][bi + 1]);
                }
            if (!two_term) {
                #pragma unroll
                for (int mt = 0; mt < 4; mt++)
                    #pragma unroll
                    for (int nt = 0; nt < 4; nt++) {
                        const int np = nt >> 1, bi = (nt & 1) * 2;
                        MMA16816(acc[mt][nt], Al[mt], Bh[np][bi], Bh[np][bi + 1]);
                    }
            }
        }
    };

    loadg(0);
    storeS(0);
    __syncthreads();
    for (int c = 0; c < nchunk; c++) {
        if (c + 1 < nchunk) loadg(c + 1);
        compute(c & 1);
        if (c + 1 < nchunk) {
            storeS((c + 1) & 1);
            __syncthreads();
        }
    }

    // ---- epilogue: bf16 hi/lo (Cl skipped for kv K-columns) ----
    #pragma unroll
    for (int nt = 0; nt < 4; nt++) {
        const int ncol = bn + wn * 32 + nt * 8 + 2 * (lane & 3);
        const float2 bb = *reinterpret_cast<const float2*>(bias + ncol);
        #pragma unroll
        for (int mt = 0; mt < 4; mt++) {
            const int m0 = bm + wm * 64 + mt * 16 + (lane >> 2);
            float v0 = (acc[mt][nt][0] + bb.x) * scale;
            float v1 = (acc[mt][nt][1] + bb.y) * scale;
            float v2 = (acc[mt][nt][2] + bb.x) * scale;
            float v3 = (acc[mt][nt][3] + bb.y) * scale;
            __nv_bfloat162 h01 = __floats2bfloat162_rn(v0, v1);
            __nv_bfloat162 h23 = __floats2bfloat162_rn(v2, v3);
            *reinterpret_cast<uint32_t*>(Ch + (size_t)m0 * N + ncol) = *(uint32_t*)&h01;
            *reinterpret_cast<uint32_t*>(Ch + (size_t)(m0 + 8) * N + ncol) = *(uint32_t*)&h23;
            if (!two_term) {
                float2 f01 = __bfloat1622float2(h01);
                float2 f23 = __bfloat1622float2(h23);
                __nv_bfloat162 l01 = __floats2bfloat162_rn(v0 - f01.x, v1 - f01.y);
                __nv_bfloat162 l23 = __floats2bfloat162_rn(v2 - f23.x, v3 - f23.y);
                *reinterpret_cast<uint32_t*>(Cl + (size_t)m0 * N + ncol) = *(uint32_t*)&l01;
                *reinterpret_cast<uint32_t*>(Cl + (size_t)(m0 + 8) * N + ncol) = *(uint32_t*)&l23;
            }
        }
    }
}

// =============================================================================
// proj GEMM (R9 gemm_mma, mode-0 path only): out = att(fp32) @ Wp^T + bias.
// =============================================================================
__global__ __launch_bounds__(256, 1)
void gemm_proj(const float* __restrict__ A,
               const __nv_bfloat16* __restrict__ Bth, const __nv_bfloat16* __restrict__ Btl,
               const float* __restrict__ bias, float* __restrict__ Cf,
               int M, int N, int K)
{
    extern __shared__ char smem[];
    const int tid  = threadIdx.x;
    const int lane = tid & 31;
    const int warp = tid >> 5;
    const int wm = warp >> 2;
    const int wn = warp & 3;
    const int bm = blockIdx.y * 128;
    const int bn = blockIdx.x * 128;

    float acc[4][4][4];
    #pragma unroll
    for (int i = 0; i < 4; i++)
        #pragma unroll
        for (int j = 0; j < 4; j++)
            #pragma unroll
            for (int k = 0; k < 4; k++) acc[i][j][k] = 0.f;

    const int nchunk = K >> 5;
    float4 pa[4];
    uint4  pbh[2], pbl[2];

    auto loadg = [&](int c) {
        #pragma unroll
        for (int i = 0; i < 4; i++) {
            int idx = tid + i * 256;
            int r = idx >> 3, k4 = idx & 7;
            pa[i] = *reinterpret_cast<const float4*>(
                A + (size_t)(bm + r) * K + c * 32 + k4 * 4);
        }
        #pragma unroll
        for (int i = 0; i < 2; i++) {
            int idx = tid + i * 256;
            int n = idx >> 2, s = idx & 3;
            const size_t go = (size_t)(bn + n) * K + c * 32 + s * 8;
            pbh[i] = *reinterpret_cast<const uint4*>(Bth + go);
            pbl[i] = *reinterpret_cast<const uint4*>(Btl + go);
        }
    };

    auto storeS = [&](int buf) {
        char* base = smem + buf * 32768;
        #pragma unroll
        for (int i = 0; i < 4; i++) {
            int idx = tid + i * 256;
            int r = idx >> 3, k4 = idx & 7;
            int off = r * 64 + k4 * 8;
            int sw = SWZ64(off);
            float4 v = pa[i];
            __nv_bfloat162 h01 = __floats2bfloat162_rn(v.x, v.y);
            __nv_bfloat162 h23 = __floats2bfloat162_rn(v.z, v.w);
            float2 f01 = __bfloat1622float2(h01);
            float2 f23 = __bfloat1622float2(h23);
            __nv_bfloat162 l01 = __floats2bfloat162_rn(v.x - f01.x, v.y - f01.y);
            __nv_bfloat162 l23 = __floats2bfloat162_rn(v.z - f23.x, v.w - f23.y);
            *reinterpret_cast<uint2*>(base + sw) =
                make_uint2(*(uint32_t*)&h01, *(uint32_t*)&h23);
            *reinterpret_cast<uint2*>(base + 8192 + sw) =
                make_uint2(*(uint32_t*)&l01, *(uint32_t*)&l23);
        }
        #pragma unroll
        for (int i = 0; i < 2; i++) {
            int idx = tid + i * 256;
            int n = idx >> 2, s = idx & 3;
            int off = n * 64 + s * 16;
            int sw = SWZ64(off);
            *reinterpret_cast<uint4*>(base + 16384 + sw) = pbh[i];
            *reinterpret_cast<uint4*>(base + 24576 + sw) = pbl[i];
        }
    };

    const uint32_t sbase = smem_u32(smem);
    const uint32_t arow  = wm * 64 + (lane & 15);
    const uint32_t aoffb = arow * 64 + ((lane >> 4) << 4);
    const uint32_t axor  = ((arow >> 1) & 3) << 4;
    const uint32_t brow  = wn * 32 + (lane & 7) + ((lane >> 4) << 3);
    const uint32_t boffb = brow * 64 + (((lane >> 3) & 1) << 4);
    const uint32_t bxor  = ((brow >> 1) & 3) << 4;

    auto compute = [&](int buf) {
        const uint32_t sa = sbase + buf * 32768;
        #pragma unroll
        for (int ks = 0; ks < 2; ks++) {
            uint32_t Ah[4][4], Al[4][4];
            #pragma unroll
            for (int mt = 0; mt < 4; mt++) {
                uint32_t addr = (sa + aoffb + mt * 1024 + ks * 32) ^ axor;
                LDSM4(Ah[mt], addr);
                LDSM4(Al[mt], addr + 8192);
            }
            uint32_t Bh[2][4], Bl[2][4];
            #pragma unroll
            for (int np = 0; np < 2; np++) {
                uint32_t addr = (sa + 16384 + boffb + np * 1024 + ks * 32) ^ bxor;
                LDSM4(Bh[np], addr);
                LDSM4(Bl[np], addr + 8192);
            }
            #pragma unroll
            for (int mt = 0; mt < 4; mt++)
                #pragma unroll
                for (int nt = 0; nt < 4; nt++) {
                    const int np = nt >> 1, bi = (nt & 1) * 2;
                    MMA16816(acc[mt][nt], Ah[mt], Bh[np][bi], Bh[np][bi + 1]);
                }
            #pragma unroll
            for (int mt = 0; mt < 4; mt++)
                #pragma unroll
                for (int nt = 0; nt < 4; nt++) {
                    const int np = nt >> 1, bi = (nt & 1) * 2;
                    MMA16816(acc[mt][nt], Ah[mt], Bl[np][bi], Bl[np][bi + 1]);
                }
            #pragma unroll
            for (int mt = 0; mt < 4; mt++)
                #pragma unroll
                for (int nt = 0; nt < 4; nt++) {
                    const int np = nt >> 1, bi = (nt & 1) * 2;
                    MMA16816(acc[mt][nt], Al[mt], Bh[np][bi], Bh[np][bi + 1]);
                }
        }
    };

    loadg(0);
    storeS(0);
    __syncthreads();
    for (int c = 0; c < nchunk; c++) {
        if (c + 1 < nchunk) loadg(c + 1);
        compute(c & 1);
        if (c + 1 < nchunk) {
            storeS((c + 1) & 1);
            __syncthreads();
        }
    }

    #pragma unroll
    for (int nt = 0; nt < 4; nt++) {
        const int ncol = bn + wn * 32 + nt * 8 + 2 * (lane & 3);
        const float2 bb = *reinterpret_cast<const float2*>(bias + ncol);
        #pragma unroll
        for (int mt = 0; mt < 4; mt++) {
            const int m0 = bm + wm * 64 + mt * 16 + (lane >> 2);
            *reinterpret_cast<float2*>(Cf + (size_t)m0 * N + ncol) =
                make_float2(acc[mt][nt][0] + bb.x, acc[mt][nt][1] + bb.y);
            *reinterpret_cast<float2*>(Cf + (size_t)(m0 + 8) * N + ncol) =
                make_float2(acc[mt][nt][2] + bb.x, acc[mt][nt][3] + bb.y);
        }
    }
}

// =============================================================================
// HMMA flash attention (R9-proven). 128 threads / 4 warps / 64 Q-rows; grid 256;
// 2 CTAs per SM. QK = (Qh+Ql)*Kh; PV = 3-term. Stage 24KB (Kh|Vh|Vl), ring @0/24K/48K;
// Q hi @73728, lo @81920. smem = 88KB.
// =============================================================================
#define ATTN_SMEM 90112

__global__ __launch_bounds__(128, 2)
void attn2(const __nv_bfloat16* __restrict__ qsh, const __nv_bfloat16* __restrict__ qsl,
           const __nv_bfloat16* __restrict__ kvh, const __nv_bfloat16* __restrict__ kvl,
           float* __restrict__ attf)
{
    extern __shared__ char smem[];
    const uint32_t sb = smem_u32(smem);
    const int tid = threadIdx.x, lane = tid & 31, warp = tid >> 5;
    const int bid = blockIdx.x;        // b*32 + h*4 + lt
    const int lt = bid & 3;
    const int h  = (bid >> 2) & 7;
    const int b  = bid >> 5;
    const int l0 = lt * 64;

    #pragma unroll
    for (int i = 0; i < 4; i++) {
        int idx = tid + i * 128;
        int r = idx >> 3, sg = idx & 7;
        uint32_t sw = SWZ128(r * 128 + sg * 16);
        size_t g = (size_t)(b * L_ + l0 + r) * 512 + h * 64 + sg * 8;
        CP16(sb + 73728 + sw, qsh + g);
        CP16(sb + 81920 + sw, qsl + g);
    }
    CP_COMMIT();
    CP_WAIT(0);
    __syncthreads();

    uint32_t Qh[4][4], Ql[4][4];
    {
        const int arow = warp * 16 + (lane & 15);
        const uint32_t abase = sb + 73728 + arow * 128;
        const uint32_t axor = (arow & 7) << 4;
        #pragma unroll
        for (int kc = 0; kc < 4; kc++) {
            uint32_t o = ((((uint32_t)(lane >> 4) << 4) + kc * 32)) ^ axor;
            LDSM4(Qh[kc], abase + o);
            LDSM4(Ql[kc], abase + 8192 + o);
        }
    }
    __syncthreads();

    auto produce = [&](int c, int s) {
        const uint32_t base = sb + (uint32_t)s * 24576;
        #pragma unroll
        for (int i = 0; i < 4; i++) {
            int idx = tid + i * 128;
            int r = idx >> 3, sg = idx & 7;
            uint32_t sw = SWZ128(r * 128 + sg * 16);
            size_t g = (size_t)(b * T_ + c * 64 + r) * 1024 + h * 64 + sg * 8;
            CP16(base + sw,         kvh + g);          // Kh
            CP16(base + 8192 + sw,  kvh + g + 512);    // Vh
            CP16(base + 16384 + sw, kvl + g + 512);    // Vl
        }
    };
    produce(0, 0); CP_COMMIT();
    produce(1, 1); CP_COMMIT();

    float mrow[2] = { -CUDART_INF_F, -CUDART_INF_F };
    float lsum[2] = { 0.f, 0.f };
    float O[8][4];
    #pragma unroll
    for (int i = 0; i < 8; i++)
        #pragma unroll
        for (int j = 0; j < 4; j++) O[i][j] = 0.f;

    const int klrow = (lane & 7) + ((lane >> 4) << 3);
    const uint32_t kseg = ((uint32_t)((lane >> 3) & 1)) << 4;
    const int vlrow = (lane & 7) + (((lane >> 3) & 1) << 3);
    const int vseg_half = lane >> 4;

    int bufc = 0;
    for (int c = 0; c < T_ / 64; c++) {
        CP_WAIT(1);
        __syncthreads();
        const uint32_t kb = sb + (uint32_t)bufc * 24576;

        float S[8][4];
        #pragma unroll
        for (int i = 0; i < 8; i++)
            #pragma unroll
            for (int j = 0; j < 4; j++) S[i][j] = 0.f;

        #pragma unroll
        for (int npp = 0; npp < 2; npp++) {
            #pragma unroll
            for (int kc = 0; kc < 4; kc++) {
                const int brow0 = (2 * npp) * 16 + klrow;
                const int brow1 = (2 * npp + 1) * 16 + klrow;
                uint32_t a0 = kb + brow0 * 128 + ((kseg + kc * 32) ^ ((brow0 & 7) << 4));
                uint32_t a1 = kb + brow1 * 128 + ((kseg + kc * 32) ^ ((brow1 & 7) << 4));
                uint32_t Bh0[4], Bh1[4];
                LDSM4(Bh0, a0);
                LDSM4(Bh1, a1);
                float* s0 = S[4 * npp];     float* s1 = S[4 * npp + 1];
                float* s2 = S[4 * npp + 2]; float* s3 = S[4 * npp + 3];
                MMA16816(s0, Qh[kc], Bh0[0], Bh0[1]);
                MMA16816(s1, Qh[kc], Bh0[2], Bh0[3]);
                MMA16816(s2, Qh[kc], Bh1[0], Bh1[1]);
                MMA16816(s3, Qh[kc], Bh1[2], Bh1[3]);
                MMA16816(s0, Ql[kc], Bh0[0], Bh0[1]);
                MMA16816(s1, Ql[kc], Bh0[2], Bh0[3]);
                MMA16816(s2, Ql[kc], Bh1[0], Bh1[1]);
                MMA16816(s3, Ql[kc], Bh1[2], Bh1[3]);
            }
        }

        float mxA = -CUDART_INF_F, mxB = -CUDART_INF_F;
        #pragma unroll
        for (int nt = 0; nt < 8; nt++) {
            mxA = fmaxf(mxA, fmaxf(S[nt][0], S[nt][1]));
            mxB = fmaxf(mxB, fmaxf(S[nt][2], S[nt][3]));
        }
        #pragma unroll
        for (int o = 1; o <= 2; o <<= 1) {
            mxA = fmaxf(mxA, __shfl_xor_sync(0xffffffffu, mxA, o));
            mxB = fmaxf(mxB, __shfl_xor_sync(0xffffffffu, mxB, o));
        }
        const float mnA = fmaxf(mrow[0], mxA);
        const float mnB = fmaxf(mrow[1], mxB);
        const float alphaA = exp2f(mrow[0] - mnA);
        const float alphaB = exp2f(mrow[1] - mnB);
        mrow[0] = mnA; mrow[1] = mnB;

        uint32_t Ph[4][4], Pl[4][4];
        float sumA = 0.f, sumB = 0.f;
        #pragma unroll
        for (int nt = 0; nt < 8; nt++) {
            float p0 = exp2f(S[nt][0] - mnA);
            float p1 = exp2f(S[nt][1] - mnA);
            float p2 = exp2f(S[nt][2] - mnB);
            float p3 = exp2f(S[nt][3] - mnB);
            sumA += p0 + p1; sumB += p2 + p3;
            __nv_bfloat162 hA = __floats2bfloat162_rn(p0, p1);
            __nv_bfloat162 hB = __floats2bfloat162_rn(p2, p3);
            float2 fA = __bfloat1622float2(hA);
            float2 fB = __bfloat1622float2(hB);
            __nv_bfloat162 lA = __floats2bfloat162_rn(p0 - fA.x, p1 - fA.y);
            __nv_bfloat162 lB = __floats2bfloat162_rn(p2 - fB.x, p3 - fB.y);
            const int kc = nt >> 1, ri = (nt & 1) * 2;
            Ph[kc][ri]     = *(uint32_t*)&hA;
            Ph[kc][ri + 1] = *(uint32_t*)&hB;
            Pl[kc][ri]     = *(uint32_t*)&lA;
            Pl[kc][ri + 1] = *(uint32_t*)&lB;
        }
        #pragma unroll
        for (int o = 1; o <= 2; o <<= 1) {
            sumA += __shfl_xor_sync(0xffffffffu, sumA, o);
            sumB += __shfl_xor_sync(0xffffffffu, sumB, o);
        }
        lsum[0] = lsum[0] * alphaA + sumA;
        lsum[1] = lsum[1] * alphaB + sumB;
        #pragma unroll
        for (int nt = 0; nt < 8; nt++) {
            O[nt][0] *= alphaA; O[nt][1] *= alphaA;
            O[nt][2] *= alphaB; O[nt][3] *= alphaB;
        }

        #pragma unroll
        for (int kc = 0; kc < 4; kc++) {
            const int vrow = kc * 16 + vlrow;
            const uint32_t vbase = kb + 8192 + vrow * 128;
            const uint32_t vxor = (vrow & 7) << 4;
            #pragma unroll
            for (int ngp = 0; ngp < 2; ngp++) {
                uint32_t o0 = ((uint32_t)((4 * ngp + vseg_half) << 4)) ^ vxor;
                uint32_t o1 = ((uint32_t)((4 * ngp + 2 + vseg_half) << 4)) ^ vxor;
                uint32_t Vh0[4], Vl0[4], Vh1[4], Vl1[4];
                LDSM4T(Vh0, vbase + o0); LDSM4T(Vl0, vbase + 8192 + o0);
                LDSM4T(Vh1, vbase + o1); LDSM4T(Vl1, vbase + 8192 + o1);
                float* d0 = O[4 * ngp];     float* d1 = O[4 * ngp + 1];
                float* d2 = O[4 * ngp + 2]; float* d3 = O[4 * ngp + 3];
                MMA16816(d0, Ph[kc], Vh0[0], Vh0[1]);
                MMA16816(d1, Ph[kc], Vh0[2], Vh0[3]);
                MMA16816(d2, Ph[kc], Vh1[0], Vh1[1]);
                MMA16816(d3, Ph[kc], Vh1[2], Vh1[3]);
                MMA16816(d0, Ph[kc], Vl0[0], Vl0[1]);
                MMA16816(d1, Ph[kc], Vl0[2], Vl0[3]);
                MMA16816(d2, Ph[kc], Vl1[0], Vl1[1]);
                MMA16816(d3, Ph[kc], Vl1[2], Vl1[3]);
                MMA16816(d0, Pl[kc], Vh0[0], Vh0[1]);
                MMA16816(d1, Pl[kc], Vh0[2], Vh0[3]);
                MMA16816(d2, Pl[kc], Vh1[0], Vh1[1]);
                MMA16816(d3, Pl[kc], Vh1[2], Vh1[3]);
            }
        }

        if (c + 2 < T_ / 64) produce(c + 2, (bufc + 2) % 3);
        CP_COMMIT();
        bufc = (bufc + 1) % 3;
    }
    CP_WAIT(0);

    const float invA = 1.0f / lsum[0];
    const float invB = 1.0f / lsum[1];
    const int rowA = b * L_ + l0 + warp * 16 + (lane >> 2);
    #pragma unroll
    for (int nt = 0; nt < 8; nt++) {
        const int col = h * 64 + nt * 8 + (lane & 3) * 2;
        *reinterpret_cast<float2*>(attf + (size_t)rowA * D_ + col) =
            make_float2(O[nt][0] * invA, O[nt][1] * invA);
        *reinterpret_cast<float2*>(attf + (size_t)(rowA + 8) * D_ + col) =
            make_float2(O[nt][2] * invB, O[nt][3] * invB);
    }
}

// =============================================================================
// launch
// =============================================================================
extern "C" void kernel_launch(void* const* d_in, const int* in_sizes, int n_in,
                              void* d_out, int out_size)
{
    const float* x     = (const float*)d_in[0];
    const float* query = (const float*)d_in[1];
    const float* Wq    = (const float*)d_in[2];
    const float* bq    = (const float*)d_in[3];
    const float* Wkv   = (const float*)d_in[4];
    const float* bkv   = (const float*)d_in[5];
    const float* Wproj = (const float*)d_in[6];
    const float* bproj = (const float*)d_in[7];
    float* out = (float*)d_out;

    __nv_bfloat16 *qh, *ql, *kvh, *kvl;
    float* att;
    __nv_bfloat16 *wkvh, *wkvl, *wqh, *wql, *wph, *wpl;
    cudaGetSymbolAddress((void**)&qh,  g_qh);   cudaGetSymbolAddress((void**)&ql,  g_ql);
    cudaGetSymbolAddress((void**)&kvh, g_kvh);  cudaGetSymbolAddress((void**)&kvl, g_kvl);
    cudaGetSymbolAddress((void**)&att, g_att);
    cudaGetSymbolAddress((void**)&wkvh, g_wkv_h); cudaGetSymbolAddress((void**)&wkvl, g_wkv_l);
    cudaGetSymbolAddress((void**)&wqh,  g_wq_h);  cudaGetSymbolAddress((void**)&wql,  g_wq_l);
    cudaGetSymbolAddress((void**)&wph,  g_wp_h);  cudaGetSymbolAddress((void**)&wpl,  g_wp_l);

    cudaFuncSetAttribute(gemm_kvq,  cudaFuncAttributeMaxDynamicSharedMemorySize, GEMM_SMEM);
    cudaFuncSetAttribute(gemm_proj, cudaFuncAttributeMaxDynamicSharedMemorySize, GEMM_SMEM);
    cudaFuncSetAttribute(attn2,     cudaFuncAttributeMaxDynamicSharedMemorySize, ATTN_SMEM);

    const float cscale = 0.125f * 1.4426950408889634f;

    split_w<<<(512 * 1024 + 255) / 256, 256>>>(Wkv,   wkvh, wkvl, 512, 1024);
    split_w<<<(512 * 512  + 255) / 256, 256>>>(Wq,    wqh,  wql,  512, 512);
    split_w<<<(512 * 512  + 255) / 256, 256>>>(Wproj, wph,  wpl,  512, 512);

    // fused: kv = x@Wkv+bkv (K cols 2-term, hi only; V cols 3-term hi/lo)
    //        q  = cscale*(query@Wq+bq) (3-term hi/lo)
    gemm_kvq<<<dim3(8, 528), 256, GEMM_SMEM>>>(
        x, query, wkvh, wkvl, wqh, wql, bkv, bq, kvh, kvl, qh, ql, cscale);
    // attention -> att fp32 (grid 256, 128 threads, 2 CTAs/SM)
    attn2<<<B_ * H_ * (L_ / 64), 128, ATTN_SMEM>>>(qh, ql, kvh, kvl, att);
    // out = att @ Wproj + bproj : [2048, 512] fp32
    gemm_proj<<<dim3(D_ / 128, (B_ * L_) / 128), 256, GEMM_SMEM>>>(
        att, wph, wpl, bproj, out, B_ * L_, D_, D_);
}

// round 11
// speedup vs baseline: 1.1783x; 1.0122x over previous
#include <cuda_runtime.h>
#include <cuda_bf16.h>
#include <math_constants.h>
#include <cstdint>

// Problem constants
#define B_ 8
#define T_ 8192
#define L_ 256
#define D_ 512
#define H_ 8
// HD = 64, scale = 1/8

// ---------------- scratch (device globals; no allocs allowed) ----------------
__device__ __nv_bfloat16 g_qh [(size_t)B_ * L_ * D_],  g_ql [(size_t)B_ * L_ * D_];
__device__ __nv_bfloat16 g_kvh[(size_t)B_ * T_ * 2 * D_], g_kvl[(size_t)B_ * T_ * 2 * D_];
__device__ float         g_att[(size_t)B_ * L_ * D_];

__device__ __nv_bfloat16 g_wkv_h[1024 * 512], g_wkv_l[1024 * 512];   // Wkv^T split
__device__ __nv_bfloat16 g_wq_h [512 * 512],  g_wq_l [512 * 512];    // Wq^T split
__device__ __nv_bfloat16 g_wp_h [512 * 512],  g_wp_l [512 * 512];    // Wproj^T split

__device__ __forceinline__ uint32_t smem_u32(const void* p) {
    uint32_t a;
    asm("{ .reg .u64 t; cvta.to.shared.u64 t, %1; cvt.u32.u64 %0, t; }"
        : "=r"(a) : "l"(p));
    return a;
}

#define CP16(dst, src) \
    asm volatile("cp.async.cg.shared.global [%0], [%1], 16;" :: "r"(dst), "l"(src))
#define CP_COMMIT() asm volatile("cp.async.commit_group;" ::: "memory")
#define CP_WAIT(n)  asm volatile("cp.async.wait_group %0;" :: "n"(n) : "memory")

#define LDSM4(r, addr) \
    asm volatile("ldmatrix.sync.aligned.m8n8.x4.shared.b16 {%0,%1,%2,%3}, [%4];" \
        : "=r"((r)[0]), "=r"((r)[1]), "=r"((r)[2]), "=r"((r)[3]) : "r"(addr))
#define LDSM4T(r, addr) \
    asm volatile("ldmatrix.sync.aligned.m8n8.x4.trans.shared.b16 {%0,%1,%2,%3}, [%4];" \
        : "=r"((r)[0]), "=r"((r)[1]), "=r"((r)[2]), "=r"((r)[3]) : "r"(addr))

#define MMA16816(d, a, b0r, b1r) \
    asm volatile("mma.sync.aligned.m16n8k16.row.col.f32.bf16.bf16.f32 " \
        "{%0,%1,%2,%3}, {%4,%5,%6,%7}, {%8,%9}, {%0,%1,%2,%3};" \
        : "+f"((d)[0]), "+f"((d)[1]), "+f"((d)[2]), "+f"((d)[3]) \
        : "r"((a)[0]), "r"((a)[1]), "r"((a)[2]), "r"((a)[3]), "r"(b0r), "r"(b1r))

#define SWZ64(o)  ((o) ^ ((((o) >> 7) & 3) << 4))
#define SWZ128(o) ((o) ^ ((((o) >> 7) & 7) << 4))

// =============================================================================
// Weight split/transpose: W[K,N] fp32 -> Wt_hi/Wt_lo [N,K] bf16
// =============================================================================
__global__ void split_w(const float* __restrict__ W, __nv_bfloat16* __restrict__ Th,
                        __nv_bfloat16* __restrict__ Tl, int K, int N)
{
    int idx = blockIdx.x * blockDim.x + threadIdx.x;
    if (idx >= K * N) return;
    int k = idx / N, n = idx % N;
    float w = W[idx];
    __nv_bfloat16 h = __float2bfloat16_rn(w);
    float r = w - __bfloat162float(h);
    Th[(size_t)n * K + k] = h;
    Tl[(size_t)n * K + k] = __float2bfloat16_rn(r);
}

// =============================================================================
// Fused kv+q GEMM. grid (8, 528): by<512 -> kv rows; by>=512 -> q rows (bx<4).
// kv K-columns (bx<4): 2-term compute (Ah*Bh + Ah*Bl); NO A-lo STS/LDSM (dead),
// Ch only. kv V-columns & q: 3-term, Ch+Cl. v = scale*(acc+bias) -> bf16 hi/lo.
// =============================================================================
#define GEMM_SMEM 65536

__global__ __launch_bounds__(256, 1)
void gemm_kvq(const float* __restrict__ x, const float* __restrict__ query,
              const __nv_bfloat16* __restrict__ wkvh, const __nv_bfloat16* __restrict__ wkvl,
              const __nv_bfloat16* __restrict__ wqh,  const __nv_bfloat16* __restrict__ wql,
              const float* __restrict__ bkv, const float* __restrict__ bq,
              __nv_bfloat16* __restrict__ kvh, __nv_bfloat16* __restrict__ kvl,
              __nv_bfloat16* __restrict__ qh,  __nv_bfloat16* __restrict__ ql,
              float cscale)
{
    const bool isQ = (blockIdx.y >= 512);
    if (isQ && blockIdx.x >= 4) return;

    const float* A               = isQ ? query : x;
    const __nv_bfloat16* Bth     = isQ ? wqh : wkvh;
    const __nv_bfloat16* Btl     = isQ ? wql : wkvl;
    const float* bias            = isQ ? bq : bkv;
    __nv_bfloat16* Ch            = isQ ? qh : kvh;
    __nv_bfloat16* Cl            = isQ ? ql : kvl;
    const float scale            = isQ ? cscale : 1.0f;
    const int N                  = isQ ? 512 : 1024;
    const int K                  = 512;
    const int bm = (isQ ? (blockIdx.y - 512) : blockIdx.y) * 128;
    const int bn = blockIdx.x * 128;
    const bool two_term = (!isQ) && (blockIdx.x < 4);   // kv K-columns

    extern __shared__ char smem[];
    const int tid  = threadIdx.x;
    const int lane = tid & 31;
    const int warp = tid >> 5;
    const int wm = warp >> 2;
    const int wn = warp & 3;

    float acc[4][4][4];
    #pragma unroll
    for (int i = 0; i < 4; i++)
        #pragma unroll
        for (int j = 0; j < 4; j++)
            #pragma unroll
            for (int k = 0; k < 4; k++) acc[i][j][k] = 0.f;

    const int nchunk = K >> 5;
    float4 pa[4];
    uint4  pbh[2], pbl[2];

    auto loadg = [&](int c) {
        #pragma unroll
        for (int i = 0; i < 4; i++) {
            int idx = tid + i * 256;
            int r = idx >> 3, k4 = idx & 7;
            pa[i] = *reinterpret_cast<const float4*>(
                A + (size_t)(bm + r) * K + c * 32 + k4 * 4);
        }
        #pragma unroll
        for (int i = 0; i < 2; i++) {
            int idx = tid + i * 256;
            int n = idx >> 2, s = idx & 3;
            const size_t go = (size_t)(bn + n) * K + c * 32 + s * 8;
            pbh[i] = *reinterpret_cast<const uint4*>(Bth + go);
            pbl[i] = *reinterpret_cast<const uint4*>(Btl + go);
        }
    };

    auto storeS = [&](int buf) {
        char* base = smem + buf * 32768;
        #pragma unroll
        for (int i = 0; i < 4; i++) {
            int idx = tid + i * 256;
            int r = idx >> 3, k4 = idx & 7;
            int off = r * 64 + k4 * 8;
            int sw = SWZ64(off);
            float4 v = pa[i];
            __nv_bfloat162 h01 = __floats2bfloat162_rn(v.x, v.y);
            __nv_bfloat162 h23 = __floats2bfloat162_rn(v.z, v.w);
            *reinterpret_cast<uint2*>(base + sw) =
                make_uint2(*(uint32_t*)&h01, *(uint32_t*)&h23);
            if (!two_term) {
                float2 f01 = __bfloat1622float2(h01);
                float2 f23 = __bfloat1622float2(h23);
                __nv_bfloat162 l01 = __floats2bfloat162_rn(v.x - f01.x, v.y - f01.y);
                __nv_bfloat162 l23 = __floats2bfloat162_rn(v.z - f23.x, v.w - f23.y);
                *reinterpret_cast<uint2*>(base + 8192 + sw) =
                    make_uint2(*(uint32_t*)&l01, *(uint32_t*)&l23);
            }
        }
        #pragma unroll
        for (int i = 0; i < 2; i++) {
            int idx = tid + i * 256;
            int n = idx >> 2, s = idx & 3;
            int off = n * 64 + s * 16;
            int sw = SWZ64(off);
            *reinterpret_cast<uint4*>(base + 16384 + sw) = pbh[i];
            *reinterpret_cast<uint4*>(base + 24576 + sw) = pbl[i];
        }
    };

    const uint32_t sbase = smem_u32(smem);
    const uint32_t arow  = wm * 64 + (lane & 15);
    const uint32_t aoffb = arow * 64 + ((lane >> 4) << 4);
    const uint32_t axor  = ((arow >> 1) & 3) << 4;
    const uint32_t brow  = wn * 32 + (lane & 7) + ((lane >> 4) << 3);
    const uint32_t boffb = brow * 64 + (((lane >> 3) & 1) << 4);
    const uint32_t bxor  = ((brow >> 1) & 3) << 4;

    auto compute = [&](int buf) {
        const uint32_t sa = sbase + buf * 32768;
        #pragma unroll
        for (int ks = 0; ks < 2; ks++) {
            uint32_t Ah[4][4], Al[4][4];
            #pragma unroll
            for (int mt = 0; mt < 4; mt++) {
                uint32_t addr = (sa + aoffb + mt * 1024 + ks * 32) ^ axor;
                LDSM4(Ah[mt], addr);
                if (!two_term) LDSM4(Al[mt], addr + 8192);
            }
            uint32_t Bh[2][4], Bl[2][4];
            #pragma unroll
            for (int np = 0; np < 2; np++) {
                uint32_t addr = (sa + 16384 + boffb + np * 1024 + ks * 32) ^ bxor;
                LDSM4(Bh[np], addr);
                LDSM4(Bl[np], addr + 8192);
            }
            #pragma unroll
            for (int mt = 0; mt < 4; mt++)
                #pragma unroll
                for (int nt = 0; nt < 4; nt++) {
                    const int np = nt >> 1, bi = (nt & 1) * 2;
                    MMA16816(acc[mt][nt], Ah[mt], Bh[np][bi], Bh[np][bi + 1]);
                }
            #pragma unroll
            for (int mt = 0; mt < 4; mt++)
                #pragma unroll
                for (int nt = 0; nt < 4; nt++) {
                    const int np = nt >> 1, bi = (nt & 1) * 2;
                    MMA16816(acc[mt][nt], Ah[mt], Bl[np][bi], Bl[np][bi + 1]);
                }
            if (!two_term) {
                #pragma unroll
                for (int mt = 0; mt < 4; mt++)
                    #pragma unroll
                    for (int nt = 0; nt < 4; nt++) {
                        const int np = nt >> 1, bi = (nt & 1) * 2;
                        MMA16816(acc[mt][nt], Al[mt], Bh[np][bi], Bh[np][bi + 1]);
                    }
            }
        }
    };

    loadg(0);
    storeS(0);
    __syncthreads();
    for (int c = 0; c < nchunk; c++) {
        if (c + 1 < nchunk) loadg(c + 1);
        compute(c & 1);
        if (c + 1 < nchunk) {
            storeS((c + 1) & 1);
            __syncthreads();
        }
    }

    // ---- epilogue: bf16 hi/lo (Cl skipped for kv K-columns) ----
    #pragma unroll
    for (int nt = 0; nt < 4; nt++) {
        const int ncol = bn + wn * 32 + nt * 8 + 2 * (lane & 3);
        const float2 bb = *reinterpret_cast<const float2*>(bias + ncol);
        #pragma unroll
        for (int mt = 0; mt < 4; mt++) {
            const int m0 = bm + wm * 64 + mt * 16 + (lane >> 2);
            float v0 = (acc[mt][nt][0] + bb.x) * scale;
            float v1 = (acc[mt][nt][1] + bb.y) * scale;
            float v2 = (acc[mt][nt][2] + bb.x) * scale;
            float v3 = (acc[mt][nt][3] + bb.y) * scale;
            __nv_bfloat162 h01 = __floats2bfloat162_rn(v0, v1);
            __nv_bfloat162 h23 = __floats2bfloat162_rn(v2, v3);
            *reinterpret_cast<uint32_t*>(Ch + (size_t)m0 * N + ncol) = *(uint32_t*)&h01;
            *reinterpret_cast<uint32_t*>(Ch + (size_t)(m0 + 8) * N + ncol) = *(uint32_t*)&h23;
            if (!two_term) {
                float2 f01 = __bfloat1622float2(h01);
                float2 f23 = __bfloat1622float2(h23);
                __nv_bfloat162 l01 = __floats2bfloat162_rn(v0 - f01.x, v1 - f01.y);
                __nv_bfloat162 l23 = __floats2bfloat162_rn(v2 - f23.x, v3 - f23.y);
                *reinterpret_cast<uint32_t*>(Cl + (size_t)m0 * N + ncol) = *(uint32_t*)&l01;
                *reinterpret_cast<uint32_t*>(Cl + (size_t)(m0 + 8) * N + ncol) = *(uint32_t*)&l23;
            }
        }
    }
}

// =============================================================================
// proj GEMM: out = att(fp32) @ Wp^T + bias (3-term, fp32 out). R9-proven.
// =============================================================================
__global__ __launch_bounds__(256, 1)
void gemm_proj(const float* __restrict__ A,
               const __nv_bfloat16* __restrict__ Bth, const __nv_bfloat16* __restrict__ Btl,
               const float* __restrict__ bias, float* __restrict__ Cf,
               int M, int N, int K)
{
    extern __shared__ char smem[];
    const int tid  = threadIdx.x;
    const int lane = tid & 31;
    const int warp = tid >> 5;
    const int wm = warp >> 2;
    const int wn = warp & 3;
    const int bm = blockIdx.y * 128;
    const int bn = blockIdx.x * 128;

    float acc[4][4][4];
    #pragma unroll
    for (int i = 0; i < 4; i++)
        #pragma unroll
        for (int j = 0; j < 4; j++)
            #pragma unroll
            for (int k = 0; k < 4; k++) acc[i][j][k] = 0.f;

    const int nchunk = K >> 5;
    float4 pa[4];
    uint4  pbh[2], pbl[2];

    auto loadg = [&](int c) {
        #pragma unroll
        for (int i = 0; i < 4; i++) {
            int idx = tid + i * 256;
            int r = idx >> 3, k4 = idx & 7;
            pa[i] = *reinterpret_cast<const float4*>(
                A + (size_t)(bm + r) * K + c * 32 + k4 * 4);
        }
        #pragma unroll
        for (int i = 0; i < 2; i++) {
            int idx = tid + i * 256;
            int n = idx >> 2, s = idx & 3;
            const size_t go = (size_t)(bn + n) * K + c * 32 + s * 8;
            pbh[i] = *reinterpret_cast<const uint4*>(Bth + go);
            pbl[i] = *reinterpret_cast<const uint4*>(Btl + go);
        }
    };

    auto storeS = [&](int buf) {
        char* base = smem + buf * 32768;
        #pragma unroll
        for (int i = 0; i < 4; i++) {
            int idx = tid + i * 256;
            int r = idx >> 3, k4 = idx & 7;
            int off = r * 64 + k4 * 8;
            int sw = SWZ64(off);
            float4 v = pa[i];
            __nv_bfloat162 h01 = __floats2bfloat162_rn(v.x, v.y);
            __nv_bfloat162 h23 = __floats2bfloat162_rn(v.z, v.w);
            float2 f01 = __bfloat1622float2(h01);
            float2 f23 = __bfloat1622float2(h23);
            __nv_bfloat162 l01 = __floats2bfloat162_rn(v.x - f01.x, v.y - f01.y);
            __nv_bfloat162 l23 = __floats2bfloat162_rn(v.z - f23.x, v.w - f23.y);
            *reinterpret_cast<uint2*>(base + sw) =
                make_uint2(*(uint32_t*)&h01, *(uint32_t*)&h23);
            *reinterpret_cast<uint2*>(base + 8192 + sw) =
                make_uint2(*(uint32_t*)&l01, *(uint32_t*)&l23);
        }
        #pragma unroll
        for (int i = 0; i < 2; i++) {
            int idx = tid + i * 256;
            int n = idx >> 2, s = idx & 3;
            int off = n * 64 + s * 16;
            int sw = SWZ64(off);
            *reinterpret_cast<uint4*>(base + 16384 + sw) = pbh[i];
            *reinterpret_cast<uint4*>(base + 24576 + sw) = pbl[i];
        }
    };

    const uint32_t sbase = smem_u32(smem);
    const uint32_t arow  = wm * 64 + (lane & 15);
    const uint32_t aoffb = arow * 64 + ((lane >> 4) << 4);
    const uint32_t axor  = ((arow >> 1) & 3) << 4;
    const uint32_t brow  = wn * 32 + (lane & 7) + ((lane >> 4) << 3);
    const uint32_t boffb = brow * 64 + (((lane >> 3) & 1) << 4);
    const uint32_t bxor  = ((brow >> 1) & 3) << 4;

    auto compute = [&](int buf) {
        const uint32_t sa = sbase + buf * 32768;
        #pragma unroll
        for (int ks = 0; ks < 2; ks++) {
            uint32_t Ah[4][4], Al[4][4];
            #pragma unroll
            for (int mt = 0; mt < 4; mt++) {
                uint32_t addr = (sa + aoffb + mt * 1024 + ks * 32) ^ axor;
                LDSM4(Ah[mt], addr);
                LDSM4(Al[mt], addr + 8192);
            }
            uint32_t Bh[2][4], Bl[2][4];
            #pragma unroll
            for (int np = 0; np < 2; np++) {
                uint32_t addr = (sa + 16384 + boffb + np * 1024 + ks * 32) ^ bxor;
                LDSM4(Bh[np], addr);
                LDSM4(Bl[np], addr + 8192);
            }
            #pragma unroll
            for (int mt = 0; mt < 4; mt++)
                #pragma unroll
                for (int nt = 0; nt < 4; nt++) {
                    const int np = nt >> 1, bi = (nt & 1) * 2;
                    MMA16816(acc[mt][nt], Ah[mt], Bh[np][bi], Bh[np][bi + 1]);
                }
            #pragma unroll
            for (int mt = 0; mt < 4; mt++)
                #pragma unroll
                for (int nt = 0; nt < 4; nt++) {
                    const int np = nt >> 1, bi = (nt & 1) * 2;
                    MMA16816(acc[mt][nt], Ah[mt], Bl[np][bi], Bl[np][bi + 1]);
                }
            #pragma unroll
            for (int mt = 0; mt < 4; mt++)
                #pragma unroll
                for (int nt = 0; nt < 4; nt++) {
                    const int np = nt >> 1, bi = (nt & 1) * 2;
                    MMA16816(acc[mt][nt], Al[mt], Bh[np][bi], Bh[np][bi + 1]);
                }
        }
    };

    loadg(0);
    storeS(0);
    __syncthreads();
    for (int c = 0; c < nchunk; c++) {
        if (c + 1 < nchunk) loadg(c + 1);
        compute(c & 1);
        if (c + 1 < nchunk) {
            storeS((c + 1) & 1);
            __syncthreads();
        }
    }

    #pragma unroll
    for (int nt = 0; nt < 4; nt++) {
        const int ncol = bn + wn * 32 + nt * 8 + 2 * (lane & 3);
        const float2 bb = *reinterpret_cast<const float2*>(bias + ncol);
        #pragma unroll
        for (int mt = 0; mt < 4; mt++) {
            const int m0 = bm + wm * 64 + mt * 16 + (lane >> 2);
            *reinterpret_cast<float2*>(Cf + (size_t)m0 * N + ncol) =
                make_float2(acc[mt][nt][0] + bb.x, acc[mt][nt][1] + bb.y);
            *reinterpret_cast<float2*>(Cf + (size_t)(m0 + 8) * N + ncol) =
                make_float2(acc[mt][nt][2] + bb.x, acc[mt][nt][3] + bb.y);
        }
    }
}

// =============================================================================
// HMMA flash attention (R9-proven). 128 threads / 4 warps / 64 Q-rows; grid 256;
// 2 CTAs per SM. QK = (Qh+Ql)*Kh; PV = 3-term. Stage 24KB (Kh|Vh|Vl), ring @0/24K/48K;
// Q hi @73728, lo @81920. smem = 88KB.
// =============================================================================
#define ATTN_SMEM 90112

__global__ __launch_bounds__(128, 2)
void attn2(const __nv_bfloat16* __restrict__ qsh, const __nv_bfloat16* __restrict__ qsl,
           const __nv_bfloat16* __restrict__ kvh, const __nv_bfloat16* __restrict__ kvl,
           float* __restrict__ attf)
{
    extern __shared__ char smem[];
    const uint32_t sb = smem_u32(smem);
    const int tid = threadIdx.x, lane = tid & 31, warp = tid >> 5;
    const int bid = blockIdx.x;        // b*32 + h*4 + lt
    const int lt = bid & 3;
    const int h  = (bid >> 2) & 7;
    const int b  = bid >> 5;
    const int l0 = lt * 64;

    #pragma unroll
    for (int i = 0; i < 4; i++) {
        int idx = tid + i * 128;
        int r = idx >> 3, sg = idx & 7;
        uint32_t sw = SWZ128(r * 128 + sg * 16);
        size_t g = (size_t)(b * L_ + l0 + r) * 512 + h * 64 + sg * 8;
        CP16(sb + 73728 + sw, qsh + g);
        CP16(sb + 81920 + sw, qsl + g);
    }
    CP_COMMIT();
    CP_WAIT(0);
    __syncthreads();

    uint32_t Qh[4][4], Ql[4][4];
    {
        const int arow = warp * 16 + (lane & 15);
        const uint32_t abase = sb + 73728 + arow * 128;
        const uint32_t axor = (arow & 7) << 4;
        #pragma unroll
        for (int kc = 0; kc < 4; kc++) {
            uint32_t o = ((((uint32_t)(lane >> 4) << 4) + kc * 32)) ^ axor;
            LDSM4(Qh[kc], abase + o);
            LDSM4(Ql[kc], abase + 8192 + o);
        }
    }
    __syncthreads();

    auto produce = [&](int c, int s) {
        const uint32_t base = sb + (uint32_t)s * 24576;
        #pragma unroll
        for (int i = 0; i < 4; i++) {
            int idx = tid + i * 128;
            int r = idx >> 3, sg = idx & 7;
            uint32_t sw = SWZ128(r * 128 + sg * 16);
            size_t g = (size_t)(b * T_ + c * 64 + r) * 1024 + h * 64 + sg * 8;
            CP16(base + sw,         kvh + g);          // Kh
            CP16(base + 8192 + sw,  kvh + g + 512);    // Vh
            CP16(base + 16384 + sw, kvl + g + 512);    // Vl
        }
    };
    produce(0, 0); CP_COMMIT();
    produce(1, 1); CP_COMMIT();

    float mrow[2] = { -CUDART_INF_F, -CUDART_INF_F };
    float lsum[2] = { 0.f, 0.f };
    float O[8][4];
    #pragma unroll
    for (int i = 0; i < 8; i++)
        #pragma unroll
        for (int j = 0; j < 4; j++) O[i][j] = 0.f;

    const int klrow = (lane & 7) + ((lane >> 4) << 3);
    const uint32_t kseg = ((uint32_t)((lane >> 3) & 1)) << 4;
    const int vlrow = (lane & 7) + (((lane >> 3) & 1) << 3);
    const int vseg_half = lane >> 4;

    int bufc = 0;
    for (int c = 0; c < T_ / 64; c++) {
        CP_WAIT(1);
        __syncthreads();
        const uint32_t kb = sb + (uint32_t)bufc * 24576;

        float S[8][4];
        #pragma unroll
        for (int i = 0; i < 8; i++)
            #pragma unroll
            for (int j = 0; j < 4; j++) S[i][j] = 0.f;

        #pragma unroll
        for (int npp = 0; npp < 2; npp++) {
            #pragma unroll
            for (int kc = 0; kc < 4; kc++) {
                const int brow0 = (2 * npp) * 16 + klrow;
                const int brow1 = (2 * npp + 1) * 16 + klrow;
                uint32_t a0 = kb + brow0 * 128 + ((kseg + kc * 32) ^ ((brow0 & 7) << 4));
                uint32_t a1 = kb + brow1 * 128 + ((kseg + kc * 32) ^ ((brow1 & 7) << 4));
                uint32_t Bh0[4], Bh1[4];
                LDSM4(Bh0, a0);
                LDSM4(Bh1, a1);
                float* s0 = S[4 * npp];     float* s1 = S[4 * npp + 1];
                float* s2 = S[4 * npp + 2]; float* s3 = S[4 * npp + 3];
                MMA16816(s0, Qh[kc], Bh0[0], Bh0[1]);
                MMA16816(s1, Qh[kc], Bh0[2], Bh0[3]);
                MMA16816(s2, Qh[kc], Bh1[0], Bh1[1]);
                MMA16816(s3, Qh[kc], Bh1[2], Bh1[3]);
                MMA16816(s0, Ql[kc], Bh0[0], Bh0[1]);
                MMA16816(s1, Ql[kc], Bh0[2], Bh0[3]);
                MMA16816(s2, Ql[kc], Bh1[0], Bh1[1]);
                MMA16816(s3, Ql[kc], Bh1[2], Bh1[3]);
            }
        }

        float mxA = -CUDART_INF_F, mxB = -CUDART_INF_F;
        #pragma unroll
        for (int nt = 0; nt < 8; nt++) {
            mxA = fmaxf(mxA, fmaxf(S[nt][0], S[nt][1]));
            mxB = fmaxf(mxB, fmaxf(S[nt][2], S[nt][3]));
        }
        #pragma unroll
        for (int o = 1; o <= 2; o <<= 1) {
            mxA = fmaxf(mxA, __shfl_xor_sync(0xffffffffu, mxA, o));
            mxB = fmaxf(mxB, __shfl_xor_sync(0xffffffffu, mxB, o));
        }
        const float mnA = fmaxf(mrow[0], mxA);
        const float mnB = fmaxf(mrow[1], mxB);
        const float alphaA = exp2f(mrow[0] - mnA);
        const float alphaB = exp2f(mrow[1] - mnB);
        mrow[0] = mnA; mrow[1] = mnB;

        uint32_t Ph[4][4], Pl[4][4];
        float sumA = 0.f, sumB = 0.f;
        #pragma unroll
        for (int nt = 0; nt < 8; nt++) {
            float p0 = exp2f(S[nt][0] - mnA);
            float p1 = exp2f(S[nt][1] - mnA);
            float p2 = exp2f(S[nt][2] - mnB);
            float p3 = exp2f(S[nt][3] - mnB);
            sumA += p0 + p1; sumB += p2 + p3;
            __nv_bfloat162 hA = __floats2bfloat162_rn(p0, p1);
            __nv_bfloat162 hB = __floats2bfloat162_rn(p2, p3);
            float2 fA = __bfloat1622float2(hA);
            float2 fB = __bfloat1622float2(hB);
            __nv_bfloat162 lA = __floats2bfloat162_rn(p0 - fA.x, p1 - fA.y);
            __nv_bfloat162 lB = __floats2bfloat162_rn(p2 - fB.x, p3 - fB.y);
            const int kc = nt >> 1, ri = (nt & 1) * 2;
            Ph[kc][ri]     = *(uint32_t*)&hA;
            Ph[kc][ri + 1] = *(uint32_t*)&hB;
            Pl[kc][ri]     = *(uint32_t*)&lA;
            Pl[kc][ri + 1] = *(uint32_t*)&lB;
        }
        #pragma unroll
        for (int o = 1; o <= 2; o <<= 1) {
            sumA += __shfl_xor_sync(0xffffffffu, sumA, o);
            sumB += __shfl_xor_sync(0xffffffffu, sumB, o);
        }
        lsum[0] = lsum[0] * alphaA + sumA;
        lsum[1] = lsum[1] * alphaB + sumB;
        #pragma unroll
        for (int nt = 0; nt < 8; nt++) {
            O[nt][0] *= alphaA; O[nt][1] *= alphaA;
            O[nt][2] *= alphaB; O[nt][3] *= alphaB;
        }

        #pragma unroll
        for (int kc = 0; kc < 4; kc++) {
            const int vrow = kc * 16 + vlrow;
            const uint32_t vbase = kb + 8192 + vrow * 128;
            const uint32_t vxor = (vrow & 7) << 4;
            #pragma unroll
            for (int ngp = 0; ngp < 2; ngp++) {
                uint32_t o0 = ((uint32_t)((4 * ngp + vseg_half) << 4)) ^ vxor;
                uint32_t o1 = ((uint32_t)((4 * ngp + 2 + vseg_half) << 4)) ^ vxor;
                uint32_t Vh0[4], Vl0[4], Vh1[4], Vl1[4];
                LDSM4T(Vh0, vbase + o0); LDSM4T(Vl0, vbase + 8192 + o0);
                LDSM4T(Vh1, vbase + o1); LDSM4T(Vl1, vbase + 8192 + o1);
                float* d0 = O[4 * ngp];     float* d1 = O[4 * ngp + 1];
                float* d2 = O[4 * ngp + 2]; float* d3 = O[4 * ngp + 3];
                MMA16816(d0, Ph[kc], Vh0[0], Vh0[1]);
                MMA16816(d1, Ph[kc], Vh0[2], Vh0[3]);
                MMA16816(d2, Ph[kc], Vh1[0], Vh1[1]);
                MMA16816(d3, Ph[kc], Vh1[2], Vh1[3]);
                MMA16816(d0, Ph[kc], Vl0[0], Vl0[1]);
                MMA16816(d1, Ph[kc], Vl0[2], Vl0[3]);
                MMA16816(d2, Ph[kc], Vl1[0], Vl1[1]);
                MMA16816(d3, Ph[kc], Vl1[2], Vl1[3]);
                MMA16816(d0, Pl[kc], Vh0[0], Vh0[1]);
                MMA16816(d1, Pl[kc], Vh0[2], Vh0[3]);
                MMA16816(d2, Pl[kc], Vh1[0], Vh1[1]);
                MMA16816(d3, Pl[kc], Vh1[2], Vh1[3]);
            }
        }

        if (c + 2 < T_ / 64) produce(c + 2, (bufc + 2) % 3);
        CP_COMMIT();
        bufc = (bufc + 1) % 3;
    }
    CP_WAIT(0);

    const float invA = 1.0f / lsum[0];
    const float invB = 1.0f / lsum[1];
    const int rowA = b * L_ + l0 + warp * 16 + (lane >> 2);
    #pragma unroll
    for (int nt = 0; nt < 8; nt++) {
        const int col = h * 64 + nt * 8 + (lane & 3) * 2;
        *reinterpret_cast<float2*>(attf + (size_t)rowA * D_ + col) =
            make_float2(O[nt][0] * invA, O[nt][1] * invA);
        *reinterpret_cast<float2*>(attf + (size_t)(rowA + 8) * D_ + col) =
            make_float2(O[nt][2] * invB, O[nt][3] * invB);
    }
}

// =============================================================================
// launch
// =============================================================================
extern "C" void kernel_launch(void* const* d_in, const int* in_sizes, int n_in,
                              void* d_out, int out_size)
{
    const float* x     = (const float*)d_in[0];
    const float* query = (const float*)d_in[1];
    const float* Wq    = (const float*)d_in[2];
    const float* bq    = (const float*)d_in[3];
    const float* Wkv   = (const float*)d_in[4];
    const float* bkv   = (const float*)d_in[5];
    const float* Wproj = (const float*)d_in[6];
    const float* bproj = (const float*)d_in[7];
    float* out = (float*)d_out;

    __nv_bfloat16 *qh, *ql, *kvh, *kvl;
    float* att;
    __nv_bfloat16 *wkvh, *wkvl, *wqh, *wql, *wph, *wpl;
    cudaGetSymbolAddress((void**)&qh,  g_qh);   cudaGetSymbolAddress((void**)&ql,  g_ql);
    cudaGetSymbolAddress((void**)&kvh, g_kvh);  cudaGetSymbolAddress((void**)&kvl, g_kvl);
    cudaGetSymbolAddress((void**)&att, g_att);
    cudaGetSymbolAddress((void**)&wkvh, g_wkv_h); cudaGetSymbolAddress((void**)&wkvl, g_wkv_l);
    cudaGetSymbolAddress((void**)&wqh,  g_wq_h);  cudaGetSymbolAddress((void**)&wql,  g_wq_l);
    cudaGetSymbolAddress((void**)&wph,  g_wp_h);  cudaGetSymbolAddress((void**)&wpl,  g_wp_l);

    cudaFuncSetAttribute(gemm_kvq,  cudaFuncAttributeMaxDynamicSharedMemorySize, GEMM_SMEM);
    cudaFuncSetAttribute(gemm_proj, cudaFuncAttributeMaxDynamicSharedMemorySize, GEMM_SMEM);
    cudaFuncSetAttribute(attn2,     cudaFuncAttributeMaxDynamicSharedMemorySize, ATTN_SMEM);

    const float cscale = 0.125f * 1.4426950408889634f;

    split_w<<<(512 * 1024 + 255) / 256, 256>>>(Wkv,   wkvh, wkvl, 512, 1024);
    split_w<<<(512 * 512  + 255) / 256, 256>>>(Wq,    wqh,  wql,  512, 512);
    split_w<<<(512 * 512  + 255) / 256, 256>>>(Wproj, wph,  wpl,  512, 512);

    // fused: kv = x@Wkv+bkv (K cols 2-term, no A-lo traffic, hi only;
    //        V cols 3-term hi/lo); q = cscale*(query@Wq+bq) (3-term hi/lo)
    gemm_kvq<<<dim3(8, 528), 256, GEMM_SMEM>>>(
        x, query, wkvh, wkvl, wqh, wql, bkv, bq, kvh, kvl, qh, ql, cscale);
    // attention -> att fp32 (grid 256, 128 threads, 2 CTAs/SM)
    attn2<<<B_ * H_ * (L_ / 64), 128, ATTN_SMEM>>>(qh, ql, kvh, kvl, att);
    // out = att @ Wproj + bproj : [2048, 512] fp32
    gemm_proj<<<dim3(D_ / 128, (B_ * L_) / 128), 256, GEMM_SMEM>>>(
        att, wph, wpl, bproj, out, B_ * L_, D_, D_);
}

// round 12
// speedup vs baseline: 1.2070x; 1.0243x over previous
#include <cuda_runtime.h>
#include <cuda_bf16.h>
#include <math_constants.h>
#include <cstdint>

// Problem constants
#define B_ 8
#define T_ 8192
#define L_ 256
#define D_ 512
#define H_ 8
// HD = 64, scale = 1/8

// ---------------- scratch (device globals; no allocs allowed) ----------------
__device__ __nv_bfloat16 g_qh [(size_t)B_ * L_ * D_],  g_ql [(size_t)B_ * L_ * D_];
__device__ __nv_bfloat16 g_kvh[(size_t)B_ * T_ * 2 * D_], g_kvl[(size_t)B_ * T_ * 2 * D_];
__device__ float         g_att[(size_t)B_ * L_ * D_];

__device__ __nv_bfloat16 g_wkv_h[1024 * 512], g_wkv_l[1024 * 512];   // Wkv^T split
__device__ __nv_bfloat16 g_wq_h [512 * 512],  g_wq_l [512 * 512];    // Wq^T split
__device__ __nv_bfloat16 g_wp_h [512 * 512],  g_wp_l [512 * 512];    // Wproj^T split

__device__ __forceinline__ uint32_t smem_u32(const void* p) {
    uint32_t a;
    asm("{ .reg .u64 t; cvta.to.shared.u64 t, %1; cvt.u32.u64 %0, t; }"
        : "=r"(a) : "l"(p));
    return a;
}

#define CP16(dst, src) \
    asm volatile("cp.async.cg.shared.global [%0], [%1], 16;" :: "r"(dst), "l"(src))
#define CP_COMMIT() asm volatile("cp.async.commit_group;" ::: "memory")
#define CP_WAIT(n)  asm volatile("cp.async.wait_group %0;" :: "n"(n) : "memory")

#define LDSM4(r, addr) \
    asm volatile("ldmatrix.sync.aligned.m8n8.x4.shared.b16 {%0,%1,%2,%3}, [%4];" \
        : "=r"((r)[0]), "=r"((r)[1]), "=r"((r)[2]), "=r"((r)[3]) : "r"(addr))
#define LDSM4T(r, addr) \
    asm volatile("ldmatrix.sync.aligned.m8n8.x4.trans.shared.b16 {%0,%1,%2,%3}, [%4];" \
        : "=r"((r)[0]), "=r"((r)[1]), "=r"((r)[2]), "=r"((r)[3]) : "r"(addr))

#define MMA16816(d, a, b0r, b1r) \
    asm volatile("mma.sync.aligned.m16n8k16.row.col.f32.bf16.bf16.f32 " \
        "{%0,%1,%2,%3}, {%4,%5,%6,%7}, {%8,%9}, {%0,%1,%2,%3};" \
        : "+f"((d)[0]), "+f"((d)[1]), "+f"((d)[2]), "+f"((d)[3]) \
        : "r"((a)[0]), "r"((a)[1]), "r"((a)[2]), "r"((a)[3]), "r"(b0r), "r"(b1r))

#define SWZ64(o)  ((o) ^ ((((o) >> 7) & 3) << 4))
#define SWZ128(o) ((o) ^ ((((o) >> 7) & 7) << 4))

// =============================================================================
// Weight split/transpose: W[K,N] fp32 -> Wt_hi/Wt_lo [N,K] bf16
// =============================================================================
__global__ void split_w(const float* __restrict__ W, __nv_bfloat16* __restrict__ Th,
                        __nv_bfloat16* __restrict__ Tl, int K, int N)
{
    int idx = blockIdx.x * blockDim.x + threadIdx.x;
    if (idx >= K * N) return;
    int k = idx / N, n = idx % N;
    float w = W[idx];
    __nv_bfloat16 h = __float2bfloat16_rn(w);
    float r = w - __bfloat162float(h);
    Th[(size_t)n * K + k] = h;
    Tl[(size_t)n * K + k] = __float2bfloat16_rn(r);
}

// =============================================================================
// Fused kv+q GEMM, 128 threads / 4 warps, CTA tile 64x128, 2 CTAs/SM.
// grid (8, 1056): by<1024 -> kv rows (64 each); by>=1024 -> q rows (bx<4).
// kv K-columns (bx<4): 2-term (Ah*Bh + Ah*Bl), no A-lo traffic, Ch only.
// kv V-columns & q: 3-term, Ch+Cl. v = scale*(acc+bias) -> bf16 hi/lo.
// Stage = 24KB: Ah@0(4K) Al@4096(4K) Bh@8192(8K) Bl@16384(8K); 2 stages = 48KB.
// =============================================================================
#define GEMM_SMEM 49152

__global__ __launch_bounds__(128, 2)
void gemm_kvq(const float* __restrict__ x, const float* __restrict__ query,
              const __nv_bfloat16* __restrict__ wkvh, const __nv_bfloat16* __restrict__ wkvl,
              const __nv_bfloat16* __restrict__ wqh,  const __nv_bfloat16* __restrict__ wql,
              const float* __restrict__ bkv, const float* __restrict__ bq,
              __nv_bfloat16* __restrict__ kvh, __nv_bfloat16* __restrict__ kvl,
              __nv_bfloat16* __restrict__ qh,  __nv_bfloat16* __restrict__ ql,
              float cscale)
{
    const bool isQ = (blockIdx.y >= 1024);
    if (isQ && blockIdx.x >= 4) return;

    const float* A               = isQ ? query : x;
    const __nv_bfloat16* Bth     = isQ ? wqh : wkvh;
    const __nv_bfloat16* Btl     = isQ ? wql : wkvl;
    const float* bias            = isQ ? bq : bkv;
    __nv_bfloat16* Ch            = isQ ? qh : kvh;
    __nv_bfloat16* Cl            = isQ ? ql : kvl;
    const float scale            = isQ ? cscale : 1.0f;
    const int N                  = isQ ? 512 : 1024;
    const int K                  = 512;
    const int bm = (isQ ? (blockIdx.y - 1024) : blockIdx.y) * 64;
    const int bn = blockIdx.x * 128;
    const bool two_term = (!isQ) && (blockIdx.x < 4);   // kv K-columns

    extern __shared__ char smem[];
    const int tid  = threadIdx.x;
    const int lane = tid & 31;
    const int wn   = tid >> 5;           // 4 warps, 1x4: warp tile 64x32

    float acc[4][4][4];
    #pragma unroll
    for (int i = 0; i < 4; i++)
        #pragma unroll
        for (int j = 0; j < 4; j++)
            #pragma unroll
            for (int k = 0; k < 4; k++) acc[i][j][k] = 0.f;

    const int nchunk = K >> 5;
    float4 pa[4];
    uint4  pbh[4], pbl[4];

    auto loadg = [&](int c) {
        #pragma unroll
        for (int i = 0; i < 4; i++) {
            int idx = tid + i * 128;          // 0..511 = 64 rows x 8 float4
            int r = idx >> 3, k4 = idx & 7;
            pa[i] = *reinterpret_cast<const float4*>(
                A + (size_t)(bm + r) * K + c * 32 + k4 * 4);
        }
        #pragma unroll
        for (int i = 0; i < 4; i++) {
            int idx = tid + i * 128;          // 0..511 = 128 rows x 4 uint4
            int n = idx >> 2, s = idx & 3;
            const size_t go = (size_t)(bn + n) * K + c * 32 + s * 8;
            pbh[i] = *reinterpret_cast<const uint4*>(Bth + go);
            pbl[i] = *reinterpret_cast<const uint4*>(Btl + go);
        }
    };

    auto storeS = [&](int buf) {
        char* base = smem + buf * 24576;
        #pragma unroll
        for (int i = 0; i < 4; i++) {
            int idx = tid + i * 128;
            int r = idx >> 3, k4 = idx & 7;
            int off = r * 64 + k4 * 8;
            int sw = SWZ64(off);
            float4 v = pa[i];
            __nv_bfloat162 h01 = __floats2bfloat162_rn(v.x, v.y);
            __nv_bfloat162 h23 = __floats2bfloat162_rn(v.z, v.w);
            *reinterpret_cast<uint2*>(base + sw) =
                make_uint2(*(uint32_t*)&h01, *(uint32_t*)&h23);
            if (!two_term) {
                float2 f01 = __bfloat1622float2(h01);
                float2 f23 = __bfloat1622float2(h23);
                __nv_bfloat162 l01 = __floats2bfloat162_rn(v.x - f01.x, v.y - f01.y);
                __nv_bfloat162 l23 = __floats2bfloat162_rn(v.z - f23.x, v.w - f23.y);
                *reinterpret_cast<uint2*>(base + 4096 + sw) =
                    make_uint2(*(uint32_t*)&l01, *(uint32_t*)&l23);
            }
        }
        #pragma unroll
        for (int i = 0; i < 4; i++) {
            int idx = tid + i * 128;
            int n = idx >> 2, s = idx & 3;
            int off = n * 64 + s * 16;
            int sw = SWZ64(off);
            *reinterpret_cast<uint4*>(base + 8192 + sw)  = pbh[i];
            *reinterpret_cast<uint4*>(base + 16384 + sw) = pbl[i];
        }
    };

    const uint32_t sbase = smem_u32(smem);
    const uint32_t arow  = (lane & 15);                 // wm == 0
    const uint32_t aoffb = arow * 64 + ((lane >> 4) << 4);
    const uint32_t axor  = ((arow >> 1) & 3) << 4;
    const uint32_t brow  = wn * 32 + (lane & 7) + ((lane >> 4) << 3);
    const uint32_t boffb = brow * 64 + (((lane >> 3) & 1) << 4);
    const uint32_t bxor  = ((brow >> 1) & 3) << 4;

    auto compute = [&](int buf) {
        const uint32_t sa = sbase + buf * 24576;
        #pragma unroll
        for (int ks = 0; ks < 2; ks++) {
            uint32_t Ah[4][4], Al[4][4];
            #pragma unroll
            for (int mt = 0; mt < 4; mt++) {
                uint32_t addr = (sa + aoffb + mt * 1024 + ks * 32) ^ axor;
                LDSM4(Ah[mt], addr);
                if (!two_term) LDSM4(Al[mt], addr + 4096);
            }
            uint32_t Bh[2][4], Bl[2][4];
            #pragma unroll
            for (int np = 0; np < 2; np++) {
                uint32_t addr = (sa + 8192 + boffb + np * 1024 + ks * 32) ^ bxor;
                LDSM4(Bh[np], addr);
                LDSM4(Bl[np], addr + 8192);
            }
            #pragma unroll
            for (int mt = 0; mt < 4; mt++)
                #pragma unroll
                for (int nt = 0; nt < 4; nt++) {
                    const int np = nt >> 1, bi = (nt & 1) * 2;
                    MMA16816(acc[mt][nt], Ah[mt], Bh[np][bi], Bh[np][bi + 1]);
                }
            #pragma unroll
            for (int mt = 0; mt < 4; mt++)
                #pragma unroll
                for (int nt = 0; nt < 4; nt++) {
                    const int np = nt >> 1, bi = (nt & 1) * 2;
                    MMA16816(acc[mt][nt], Ah[mt], Bl[np][bi], Bl[np][bi + 1]);
                }
            if (!two_term) {
                #pragma unroll
                for (int mt = 0; mt < 4; mt++)
                    #pragma unroll
                    for (int nt = 0; nt < 4; nt++) {
                        const int np = nt >> 1, bi = (nt & 1) * 2;
                        MMA16816(acc[mt][nt], Al[mt], Bh[np][bi], Bh[np][bi + 1]);
                    }
            }
        }
    };

    loadg(0);
    storeS(0);
    __syncthreads();
    for (int c = 0; c < nchunk; c++) {
        if (c + 1 < nchunk) loadg(c + 1);
        compute(c & 1);
        if (c + 1 < nchunk) {
            storeS((c + 1) & 1);
            __syncthreads();
        }
    }

    // ---- epilogue: bf16 hi/lo (Cl skipped for kv K-columns) ----
    #pragma unroll
    for (int nt = 0; nt < 4; nt++) {
        const int ncol = bn + wn * 32 + nt * 8 + 2 * (lane & 3);
        const float2 bb = *reinterpret_cast<const float2*>(bias + ncol);
        #pragma unroll
        for (int mt = 0; mt < 4; mt++) {
            const int m0 = bm + mt * 16 + (lane >> 2);
            float v0 = (acc[mt][nt][0] + bb.x) * scale;
            float v1 = (acc[mt][nt][1] + bb.y) * scale;
            float v2 = (acc[mt][nt][2] + bb.x) * scale;
            float v3 = (acc[mt][nt][3] + bb.y) * scale;
            __nv_bfloat162 h01 = __floats2bfloat162_rn(v0, v1);
            __nv_bfloat162 h23 = __floats2bfloat162_rn(v2, v3);
            *reinterpret_cast<uint32_t*>(Ch + (size_t)m0 * N + ncol) = *(uint32_t*)&h01;
            *reinterpret_cast<uint32_t*>(Ch + (size_t)(m0 + 8) * N + ncol) = *(uint32_t*)&h23;
            if (!two_term) {
                float2 f01 = __bfloat1622float2(h01);
                float2 f23 = __bfloat1622float2(h23);
                __nv_bfloat162 l01 = __floats2bfloat162_rn(v0 - f01.x, v1 - f01.y);
                __nv_bfloat162 l23 = __floats2bfloat162_rn(v2 - f23.x, v3 - f23.y);
                *reinterpret_cast<uint32_t*>(Cl + (size_t)m0 * N + ncol) = *(uint32_t*)&l01;
                *reinterpret_cast<uint32_t*>(Cl + (size_t)(m0 + 8) * N + ncol) = *(uint32_t*)&l23;
            }
        }
    }
}

// =============================================================================
// proj GEMM: out = att(fp32) @ Wp^T + bias (3-term, fp32 out). R9-proven.
// =============================================================================
#define PROJ_SMEM 65536

__global__ __launch_bounds__(256, 1)
void gemm_proj(const float* __restrict__ A,
               const __nv_bfloat16* __restrict__ Bth, const __nv_bfloat16* __restrict__ Btl,
               const float* __restrict__ bias, float* __restrict__ Cf,
               int M, int N, int K)
{
    extern __shared__ char smem[];
    const int tid  = threadIdx.x;
    const int lane = tid & 31;
    const int warp = tid >> 5;
    const int wm = warp >> 2;
    const int wn = warp & 3;
    const int bm = blockIdx.y * 128;
    const int bn = blockIdx.x * 128;

    float acc[4][4][4];
    #pragma unroll
    for (int i = 0; i < 4; i++)
        #pragma unroll
        for (int j = 0; j < 4; j++)
            #pragma unroll
            for (int k = 0; k < 4; k++) acc[i][j][k] = 0.f;

    const int nchunk = K >> 5;
    float4 pa[4];
    uint4  pbh[2], pbl[2];

    auto loadg = [&](int c) {
        #pragma unroll
        for (int i = 0; i < 4; i++) {
            int idx = tid + i * 256;
            int r = idx >> 3, k4 = idx & 7;
            pa[i] = *reinterpret_cast<const float4*>(
                A + (size_t)(bm + r) * K + c * 32 + k4 * 4);
        }
        #pragma unroll
        for (int i = 0; i < 2; i++) {
            int idx = tid + i * 256;
            int n = idx >> 2, s = idx & 3;
            const size_t go = (size_t)(bn + n) * K + c * 32 + s * 8;
            pbh[i] = *reinterpret_cast<const uint4*>(Bth + go);
            pbl[i] = *reinterpret_cast<const uint4*>(Btl + go);
        }
    };

    auto storeS = [&](int buf) {
        char* base = smem + buf * 32768;
        #pragma unroll
        for (int i = 0; i < 4; i++) {
            int idx = tid + i * 256;
            int r = idx >> 3, k4 = idx & 7;
            int off = r * 64 + k4 * 8;
            int sw = SWZ64(off);
            float4 v = pa[i];
            __nv_bfloat162 h01 = __floats2bfloat162_rn(v.x, v.y);
            __nv_bfloat162 h23 = __floats2bfloat162_rn(v.z, v.w);
            float2 f01 = __bfloat1622float2(h01);
            float2 f23 = __bfloat1622float2(h23);
            __nv_bfloat162 l01 = __floats2bfloat162_rn(v.x - f01.x, v.y - f01.y);
            __nv_bfloat162 l23 = __floats2bfloat162_rn(v.z - f23.x, v.w - f23.y);
            *reinterpret_cast<uint2*>(base + sw) =
                make_uint2(*(uint32_t*)&h01, *(uint32_t*)&h23);
            *reinterpret_cast<uint2*>(base + 8192 + sw) =
                make_uint2(*(uint32_t*)&l01, *(uint32_t*)&l23);
        }
        #pragma unroll
        for (int i = 0; i < 2; i++) {
            int idx = tid + i * 256;
            int n = idx >> 2, s = idx & 3;
            int off = n * 64 + s * 16;
            int sw = SWZ64(off);
            *reinterpret_cast<uint4*>(base + 16384 + sw) = pbh[i];
            *reinterpret_cast<uint4*>(base + 24576 + sw) = pbl[i];
        }
    };

    const uint32_t sbase = smem_u32(smem);
    const uint32_t arow  = wm * 64 + (lane & 15);
    const uint32_t aoffb = arow * 64 + ((lane >> 4) << 4);
    const uint32_t axor  = ((arow >> 1) & 3) << 4;
    const uint32_t brow  = wn * 32 + (lane & 7) + ((lane >> 4) << 3);
    const uint32_t boffb = brow * 64 + (((lane >> 3) & 1) << 4);
    const uint32_t bxor  = ((brow >> 1) & 3) << 4;

    auto compute = [&](int buf) {
        const uint32_t sa = sbase + buf * 32768;
        #pragma unroll
        for (int ks = 0; ks < 2; ks++) {
            uint32_t Ah[4][4], Al[4][4];
            #pragma unroll
            for (int mt = 0; mt < 4; mt++) {
                uint32_t addr = (sa + aoffb + mt * 1024 + ks * 32) ^ axor;
                LDSM4(Ah[mt], addr);
                LDSM4(Al[mt], addr + 8192);
            }
            uint32_t Bh[2][4], Bl[2][4];
            #pragma unroll
            for (int np = 0; np < 2; np++) {
                uint32_t addr = (sa + 16384 + boffb + np * 1024 + ks * 32) ^ bxor;
                LDSM4(Bh[np], addr);
                LDSM4(Bl[np], addr + 8192);
            }
            #pragma unroll
            for (int mt = 0; mt < 4; mt++)
                #pragma unroll
                for (int nt = 0; nt < 4; nt++) {
                    const int np = nt >> 1, bi = (nt & 1) * 2;
                    MMA16816(acc[mt][nt], Ah[mt], Bh[np][bi], Bh[np][bi + 1]);
                }
            #pragma unroll
            for (int mt = 0; mt < 4; mt++)
                #pragma unroll
                for (int nt = 0; nt < 4; nt++) {
                    const int np = nt >> 1, bi = (nt & 1) * 2;
                    MMA16816(acc[mt][nt], Ah[mt], Bl[np][bi], Bl[np][bi + 1]);
                }
            #pragma unroll
            for (int mt = 0; mt < 4; mt++)
                #pragma unroll
                for (int nt = 0; nt < 4; nt++) {
                    const int np = nt >> 1, bi = (nt & 1) * 2;
                    MMA16816(acc[mt][nt], Al[mt], Bh[np][bi], Bh[np][bi + 1]);
                }
        }
    };

    loadg(0);
    storeS(0);
    __syncthreads();
    for (int c = 0; c < nchunk; c++) {
        if (c + 1 < nchunk) loadg(c + 1);
        compute(c & 1);
        if (c + 1 < nchunk) {
            storeS((c + 1) & 1);
            __syncthreads();
        }
    }

    #pragma unroll
    for (int nt = 0; nt < 4; nt++) {
        const int ncol = bn + wn * 32 + nt * 8 + 2 * (lane & 3);
        const float2 bb = *reinterpret_cast<const float2*>(bias + ncol);
        #pragma unroll
        for (int mt = 0; mt < 4; mt++) {
            const int m0 = bm + wm * 64 + mt * 16 + (lane >> 2);
            *reinterpret_cast<float2*>(Cf + (size_t)m0 * N + ncol) =
                make_float2(acc[mt][nt][0] + bb.x, acc[mt][nt][1] + bb.y);
            *reinterpret_cast<float2*>(Cf + (size_t)(m0 + 8) * N + ncol) =
                make_float2(acc[mt][nt][2] + bb.x, acc[mt][nt][3] + bb.y);
        }
    }
}

// =============================================================================
// HMMA flash attention (R9-proven). 128 threads / 4 warps / 64 Q-rows; grid 256;
// 2 CTAs per SM. QK = (Qh+Ql)*Kh; PV = 3-term. Stage 24KB (Kh|Vh|Vl), ring @0/24K/48K;
// Q hi @73728, lo @81920. smem = 88KB.
// =============================================================================
#define ATTN_SMEM 90112

__global__ __launch_bounds__(128, 2)
void attn2(const __nv_bfloat16* __restrict__ qsh, const __nv_bfloat16* __restrict__ qsl,
           const __nv_bfloat16* __restrict__ kvh, const __nv_bfloat16* __restrict__ kvl,
           float* __restrict__ attf)
{
    extern __shared__ char smem[];
    const uint32_t sb = smem_u32(smem);
    const int tid = threadIdx.x, lane = tid & 31, warp = tid >> 5;
    const int bid = blockIdx.x;        // b*32 + h*4 + lt
    const int lt = bid & 3;
    const int h  = (bid >> 2) & 7;
    const int b  = bid >> 5;
    const int l0 = lt * 64;

    #pragma unroll
    for (int i = 0; i < 4; i++) {
        int idx = tid + i * 128;
        int r = idx >> 3, sg = idx & 7;
        uint32_t sw = SWZ128(r * 128 + sg * 16);
        size_t g = (size_t)(b * L_ + l0 + r) * 512 + h * 64 + sg * 8;
        CP16(sb + 73728 + sw, qsh + g);
        CP16(sb + 81920 + sw, qsl + g);
    }
    CP_COMMIT();
    CP_WAIT(0);
    __syncthreads();

    uint32_t Qh[4][4], Ql[4][4];
    {
        const int arow = warp * 16 + (lane & 15);
        const uint32_t abase = sb + 73728 + arow * 128;
        const uint32_t axor = (arow & 7) << 4;
        #pragma unroll
        for (int kc = 0; kc < 4; kc++) {
            uint32_t o = ((((uint32_t)(lane >> 4) << 4) + kc * 32)) ^ axor;
            LDSM4(Qh[kc], abase + o);
            LDSM4(Ql[kc], abase + 8192 + o);
        }
    }
    __syncthreads();

    auto produce = [&](int c, int s) {
        const uint32_t base = sb + (uint32_t)s * 24576;
        #pragma unroll
        for (int i = 0; i < 4; i++) {
            int idx = tid + i * 128;
            int r = idx >> 3, sg = idx & 7;
            uint32_t sw = SWZ128(r * 128 + sg * 16);
            size_t g = (size_t)(b * T_ + c * 64 + r) * 1024 + h * 64 + sg * 8;
            CP16(base + sw,         kvh + g);          // Kh
            CP16(base + 8192 + sw,  kvh + g + 512);    // Vh
            CP16(base + 16384 + sw, kvl + g + 512);    // Vl
        }
    };
    produce(0, 0); CP_COMMIT();
    produce(1, 1); CP_COMMIT();

    float mrow[2] = { -CUDART_INF_F, -CUDART_INF_F };
    float lsum[2] = { 0.f, 0.f };
    float O[8][4];
    #pragma unroll
    for (int i = 0; i < 8; i++)
        #pragma unroll
        for (int j = 0; j < 4; j++) O[i][j] = 0.f;

    const int klrow = (lane & 7) + ((lane >> 4) << 3);
    const uint32_t kseg = ((uint32_t)((lane >> 3) & 1)) << 4;
    const int vlrow = (lane & 7) + (((lane >> 3) & 1) << 3);
    const int vseg_half = lane >> 4;

    int bufc = 0;
    for (int c = 0; c < T_ / 64; c++) {
        CP_WAIT(1);
        __syncthreads();
        const uint32_t kb = sb + (uint32_t)bufc * 24576;

        float S[8][4];
        #pragma unroll
        for (int i = 0; i < 8; i++)
            #pragma unroll
            for (int j = 0; j < 4; j++) S[i][j] = 0.f;

        #pragma unroll
        for (int npp = 0; npp < 2; npp++) {
            #pragma unroll
            for (int kc = 0; kc < 4; kc++) {
                const int brow0 = (2 * npp) * 16 + klrow;
                const int brow1 = (2 * npp + 1) * 16 + klrow;
                uint32_t a0 = kb + brow0 * 128 + ((kseg + kc * 32) ^ ((brow0 & 7) << 4));
                uint32_t a1 = kb + brow1 * 128 + ((kseg + kc * 32) ^ ((brow1 & 7) << 4));
                uint32_t Bh0[4], Bh1[4];
                LDSM4(Bh0, a0);
                LDSM4(Bh1, a1);
                float* s0 = S[4 * npp];     float* s1 = S[4 * npp + 1];
                float* s2 = S[4 * npp + 2]; float* s3 = S[4 * npp + 3];
                MMA16816(s0, Qh[kc], Bh0[0], Bh0[1]);
                MMA16816(s1, Qh[kc], Bh0[2], Bh0[3]);
                MMA16816(s2, Qh[kc], Bh1[0], Bh1[1]);
                MMA16816(s3, Qh[kc], Bh1[2], Bh1[3]);
                MMA16816(s0, Ql[kc], Bh0[0], Bh0[1]);
                MMA16816(s1, Ql[kc], Bh0[2], Bh0[3]);
                MMA16816(s2, Ql[kc], Bh1[0], Bh1[1]);
                MMA16816(s3, Ql[kc], Bh1[2], Bh1[3]);
            }
        }

        float mxA = -CUDART_INF_F, mxB = -CUDART_INF_F;
        #pragma unroll
        for (int nt = 0; nt < 8; nt++) {
            mxA = fmaxf(mxA, fmaxf(S[nt][0], S[nt][1]));
            mxB = fmaxf(mxB, fmaxf(S[nt][2], S[nt][3]));
        }
        #pragma unroll
        for (int o = 1; o <= 2; o <<= 1) {
            mxA = fmaxf(mxA, __shfl_xor_sync(0xffffffffu, mxA, o));
            mxB = fmaxf(mxB, __shfl_xor_sync(0xffffffffu, mxB, o));
        }
        const float mnA = fmaxf(mrow[0], mxA);
        const float mnB = fmaxf(mrow[1], mxB);
        const float alphaA = exp2f(mrow[0] - mnA);
        const float alphaB = exp2f(mrow[1] - mnB);
        mrow[0] = mnA; mrow[1] = mnB;

        uint32_t Ph[4][4], Pl[4][4];
        float sumA = 0.f, sumB = 0.f;
        #pragma unroll
        for (int nt = 0; nt < 8; nt++) {
            float p0 = exp2f(S[nt][0] - mnA);
            float p1 = exp2f(S[nt][1] - mnA);
            float p2 = exp2f(S[nt][2] - mnB);
            float p3 = exp2f(S[nt][3] - mnB);
            sumA += p0 + p1; sumB += p2 + p3;
            __nv_bfloat162 hA = __floats2bfloat162_rn(p0, p1);
            __nv_bfloat162 hB = __floats2bfloat162_rn(p2, p3);
            float2 fA = __bfloat1622float2(hA);
            float2 fB = __bfloat1622float2(hB);
            __nv_bfloat162 lA = __floats2bfloat162_rn(p0 - fA.x, p1 - fA.y);
            __nv_bfloat162 lB = __floats2bfloat162_rn(p2 - fB.x, p3 - fB.y);
            const int kc = nt >> 1, ri = (nt & 1) * 2;
            Ph[kc][ri]     = *(uint32_t*)&hA;
            Ph[kc][ri + 1] = *(uint32_t*)&hB;
            Pl[kc][ri]     = *(uint32_t*)&lA;
            Pl[kc][ri + 1] = *(uint32_t*)&lB;
        }
        #pragma unroll
        for (int o = 1; o <= 2; o <<= 1) {
            sumA += __shfl_xor_sync(0xffffffffu, sumA, o);
            sumB += __shfl_xor_sync(0xffffffffu, sumB, o);
        }
        lsum[0] = lsum[0] * alphaA + sumA;
        lsum[1] = lsum[1] * alphaB + sumB;
        #pragma unroll
        for (int nt = 0; nt < 8; nt++) {
            O[nt][0] *= alphaA; O[nt][1] *= alphaA;
            O[nt][2] *= alphaB; O[nt][3] *= alphaB;
        }

        #pragma unroll
        for (int kc = 0; kc < 4; kc++) {
            const int vrow = kc * 16 + vlrow;
            const uint32_t vbase = kb + 8192 + vrow * 128;
            const uint32_t vxor = (vrow & 7) << 4;
            #pragma unroll
            for (int ngp = 0; ngp < 2; ngp++) {
                uint32_t o0 = ((uint32_t)((4 * ngp + vseg_half) << 4)) ^ vxor;
                uint32_t o1 = ((uint32_t)((4 * ngp + 2 + vseg_half) << 4)) ^ vxor;
                uint32_t Vh0[4], Vl0[4], Vh1[4], Vl1[4];
                LDSM4T(Vh0, vbase + o0); LDSM4T(Vl0, vbase + 8192 + o0);
                LDSM4T(Vh1, vbase + o1); LDSM4T(Vl1, vbase + 8192 + o1);
                float* d0 = O[4 * ngp];     float* d1 = O[4 * ngp + 1];
                float* d2 = O[4 * ngp + 2]; float* d3 = O[4 * ngp + 3];
                MMA16816(d0, Ph[kc], Vh0[0], Vh0[1]);
                MMA16816(d1, Ph[kc], Vh0[2], Vh0[3]);
                MMA16816(d2, Ph[kc], Vh1[0], Vh1[1]);
                MMA16816(d3, Ph[kc], Vh1[2], Vh1[3]);
                MMA16816(d0, Ph[kc], Vl0[0], Vl0[1]);
                MMA16816(d1, Ph[kc], Vl0[2], Vl0[3]);
                MMA16816(d2, Ph[kc], Vl1[0], Vl1[1]);
                MMA16816(d3, Ph[kc], Vl1[2], Vl1[3]);
                MMA16816(d0, Pl[kc], Vh0[0], Vh0[1]);
                MMA16816(d1, Pl[kc], Vh0[2], Vh0[3]);
                MMA16816(d2, Pl[kc], Vh1[0], Vh1[1]);
                MMA16816(d3, Pl[kc], Vh1[2], Vh1[3]);
            }
        }

        if (c + 2 < T_ / 64) produce(c + 2, (bufc + 2) % 3);
        CP_COMMIT();
        bufc = (bufc + 1) % 3;
    }
    CP_WAIT(0);

    const float invA = 1.0f / lsum[0];
    const float invB = 1.0f / lsum[1];
    const int rowA = b * L_ + l0 + warp * 16 + (lane >> 2);
    #pragma unroll
    for (int nt = 0; nt < 8; nt++) {
        const int col = h * 64 + nt * 8 + (lane & 3) * 2;
        *reinterpret_cast<float2*>(attf + (size_t)rowA * D_ + col) =
            make_float2(O[nt][0] * invA, O[nt][1] * invA);
        *reinterpret_cast<float2*>(attf + (size_t)(rowA + 8) * D_ + col) =
            make_float2(O[nt][2] * invB, O[nt][3] * invB);
    }
}

// =============================================================================
// launch
// =============================================================================
extern "C" void kernel_launch(void* const* d_in, const int* in_sizes, int n_in,
                              void* d_out, int out_size)
{
    const float* x     = (const float*)d_in[0];
    const float* query = (const float*)d_in[1];
    const float* Wq    = (const float*)d_in[2];
    const float* bq    = (const float*)d_in[3];
    const float* Wkv   = (const float*)d_in[4];
    const float* bkv   = (const float*)d_in[5];
    const float* Wproj = (const float*)d_in[6];
    const float* bproj = (const float*)d_in[7];
    float* out = (float*)d_out;

    __nv_bfloat16 *qh, *ql, *kvh, *kvl;
    float* att;
    __nv_bfloat16 *wkvh, *wkvl, *wqh, *wql, *wph, *wpl;
    cudaGetSymbolAddress((void**)&qh,  g_qh);   cudaGetSymbolAddress((void**)&ql,  g_ql);
    cudaGetSymbolAddress((void**)&kvh, g_kvh);  cudaGetSymbolAddress((void**)&kvl, g_kvl);
    cudaGetSymbolAddress((void**)&att, g_att);
    cudaGetSymbolAddress((void**)&wkvh, g_wkv_h); cudaGetSymbolAddress((void**)&wkvl, g_wkv_l);
    cudaGetSymbolAddress((void**)&wqh,  g_wq_h);  cudaGetSymbolAddress((void**)&wql,  g_wq_l);
    cudaGetSymbolAddress((void**)&wph,  g_wp_h);  cudaGetSymbolAddress((void**)&wpl,  g_wp_l);

    cudaFuncSetAttribute(gemm_kvq,  cudaFuncAttributeMaxDynamicSharedMemorySize, GEMM_SMEM);
    cudaFuncSetAttribute(gemm_proj, cudaFuncAttributeMaxDynamicSharedMemorySize, PROJ_SMEM);
    cudaFuncSetAttribute(attn2,     cudaFuncAttributeMaxDynamicSharedMemorySize, ATTN_SMEM);

    const float cscale = 0.125f * 1.4426950408889634f;

    split_w<<<(512 * 1024 + 255) / 256, 256>>>(Wkv,   wkvh, wkvl, 512, 1024);
    split_w<<<(512 * 512  + 255) / 256, 256>>>(Wq,    wqh,  wql,  512, 512);
    split_w<<<(512 * 512  + 255) / 256, 256>>>(Wproj, wph,  wpl,  512, 512);

    // fused kv+q GEMM: 64x128 CTAs, 2 per SM
    gemm_kvq<<<dim3(8, 1056), 128, GEMM_SMEM>>>(
        x, query, wkvh, wkvl, wqh, wql, bkv, bq, kvh, kvl, qh, ql, cscale);
    // attention -> att fp32 (grid 256, 128 threads, 2 CTAs/SM)
    attn2<<<B_ * H_ * (L_ / 64), 128, ATTN_SMEM>>>(qh, ql, kvh, kvl, att);
    // out = att @ Wproj + bproj : [2048, 512] fp32
    gemm_proj<<<dim3(D_ / 128, (B_ * L_) / 128), 256, PROJ_SMEM>>>(
        att, wph, wpl, bproj, out, B_ * L_, D_, D_);
}

// round 13
// speedup vs baseline: 1.2844x; 1.0642x over previous
#include <cuda_runtime.h>
#include <cuda_bf16.h>
#include <math_constants.h>
#include <cstdint>

// Problem constants
#define B_ 8
#define T_ 8192
#define L_ 256
#define D_ 512
#define H_ 8
// HD = 64, scale = 1/8

// ---------------- scratch (device globals; no allocs allowed) ----------------
__device__ __nv_bfloat16 g_qh [(size_t)B_ * L_ * D_],  g_ql [(size_t)B_ * L_ * D_];
__device__ __nv_bfloat16 g_kvh[(size_t)B_ * T_ * 2 * D_], g_kvl[(size_t)B_ * T_ * 2 * D_];
__device__ float         g_att[(size_t)B_ * L_ * D_];

__device__ __nv_bfloat16 g_wkv_h[1024 * 512], g_wkv_l[1024 * 512];   // Wkv^T split
__device__ __nv_bfloat16 g_wq_h [512 * 512],  g_wq_l [512 * 512];    // Wq^T split
__device__ __nv_bfloat16 g_wp_h [512 * 512],  g_wp_l [512 * 512];    // Wproj^T split

__device__ __forceinline__ uint32_t smem_u32(const void* p) {
    uint32_t a;
    asm("{ .reg .u64 t; cvta.to.shared.u64 t, %1; cvt.u32.u64 %0, t; }"
        : "=r"(a) : "l"(p));
    return a;
}

#define CP16(dst, src) \
    asm volatile("cp.async.cg.shared.global [%0], [%1], 16;" :: "r"(dst), "l"(src))
#define CP_COMMIT() asm volatile("cp.async.commit_group;" ::: "memory")
#define CP_WAIT(n)  asm volatile("cp.async.wait_group %0;" :: "n"(n) : "memory")

#define LDSM4(r, addr) \
    asm volatile("ldmatrix.sync.aligned.m8n8.x4.shared.b16 {%0,%1,%2,%3}, [%4];" \
        : "=r"((r)[0]), "=r"((r)[1]), "=r"((r)[2]), "=r"((r)[3]) : "r"(addr))
#define LDSM4T(r, addr) \
    asm volatile("ldmatrix.sync.aligned.m8n8.x4.trans.shared.b16 {%0,%1,%2,%3}, [%4];" \
        : "=r"((r)[0]), "=r"((r)[1]), "=r"((r)[2]), "=r"((r)[3]) : "r"(addr))

#define MMA16816(d, a, b0r, b1r) \
    asm volatile("mma.sync.aligned.m16n8k16.row.col.f32.bf16.bf16.f32 " \
        "{%0,%1,%2,%3}, {%4,%5,%6,%7}, {%8,%9}, {%0,%1,%2,%3};" \
        : "+f"((d)[0]), "+f"((d)[1]), "+f"((d)[2]), "+f"((d)[3]) \
        : "r"((a)[0]), "r"((a)[1]), "r"((a)[2]), "r"((a)[3]), "r"(b0r), "r"(b1r))

#define SWZ64(o)  ((o) ^ ((((o) >> 7) & 3) << 4))
#define SWZ128(o) ((o) ^ ((((o) >> 7) & 7) << 4))

// =============================================================================
// Weight split/transpose: W[K,N] fp32 -> Wt_hi/Wt_lo [N,K] bf16
// =============================================================================
__global__ void split_w(const float* __restrict__ W, __nv_bfloat16* __restrict__ Th,
                        __nv_bfloat16* __restrict__ Tl, int K, int N)
{
    int idx = blockIdx.x * blockDim.x + threadIdx.x;
    if (idx >= K * N) return;
    int k = idx / N, n = idx % N;
    float w = W[idx];
    __nv_bfloat16 h = __float2bfloat16_rn(w);
    float r = w - __bfloat162float(h);
    Th[(size_t)n * K + k] = h;
    Tl[(size_t)n * K + k] = __float2bfloat16_rn(r);
}

// =============================================================================
// Fused kv+q GEMM, 128 threads / 4 warps, CTA tile 64x256, warp tile 64x64,
// 2 CTAs/SM. B via 3-stage cp.async (weights already bf16); A via LDG fp32
// register-prefetch + in-producer hi/lo split (2 bufs).
// grid (4, 1056): by<1024 -> kv rows; by>=1024 -> q rows (bx<2).
// kv K-columns (bx<2): 2-term (Ah*Bh + Ah*Bl), no A-lo traffic, Ch only.
// smem: A bufs @0,@8192 (Ah 4K|Al 4K); B stages @16384+s*32768 (Bh 16K|Bl 16K).
// Total 112KB.
// =============================================================================
#define GEMM_SMEM 114688

__global__ __launch_bounds__(128, 2)
void gemm_kvq(const float* __restrict__ x, const float* __restrict__ query,
              const __nv_bfloat16* __restrict__ wkvh, const __nv_bfloat16* __restrict__ wkvl,
              const __nv_bfloat16* __restrict__ wqh,  const __nv_bfloat16* __restrict__ wql,
              const float* __restrict__ bkv, const float* __restrict__ bq,
              __nv_bfloat16* __restrict__ kvh, __nv_bfloat16* __restrict__ kvl,
              __nv_bfloat16* __restrict__ qh,  __nv_bfloat16* __restrict__ ql,
              float cscale)
{
    const bool isQ = (blockIdx.y >= 1024);
    if (isQ && blockIdx.x >= 2) return;

    const float* A               = isQ ? query : x;
    const __nv_bfloat16* Bth     = isQ ? wqh : wkvh;
    const __nv_bfloat16* Btl     = isQ ? wql : wkvl;
    const float* bias            = isQ ? bq : bkv;
    __nv_bfloat16* Ch            = isQ ? qh : kvh;
    __nv_bfloat16* Cl            = isQ ? ql : kvl;
    const float scale            = isQ ? cscale : 1.0f;
    const int N                  = isQ ? 512 : 1024;
    const int K                  = 512;
    const int bm = (isQ ? (blockIdx.y - 1024) : blockIdx.y) * 64;
    const int bn = blockIdx.x * 256;
    const bool two_term = (!isQ) && (blockIdx.x < 2);   // kv K-columns

    extern __shared__ char smem[];
    const uint32_t sbase = smem_u32(smem);
    const int tid  = threadIdx.x;
    const int lane = tid & 31;
    const int wn   = tid >> 5;           // 4 warps, warp tile 64x64

    float acc[4][8][4];
    #pragma unroll
    for (int i = 0; i < 4; i++)
        #pragma unroll
        for (int j = 0; j < 8; j++)
            #pragma unroll
            for (int k = 0; k < 4; k++) acc[i][j][k] = 0.f;

    const int nchunk = K >> 5;

    // ---- B producer: cp.async (256 rows x 4 segs = 1024 per h/l) ----
    auto produceB = [&](int c, int s) {
        const uint32_t base = sbase + 16384 + (uint32_t)s * 32768;
        #pragma unroll
        for (int i = 0; i < 8; i++) {
            int idx = tid + i * 128;              // 0..1023
            int n = idx >> 2, sg = idx & 3;
            uint32_t sw = SWZ64(n * 64 + sg * 16);
            const size_t gb = (size_t)(bn + n) * K + c * 32 + sg * 8;
            CP16(base + sw,         Bth + gb);
            CP16(base + 16384 + sw, Btl + gb);
        }
    };

    // ---- A producer: LDG fp32 prefetch -> split -> STS ----
    float4 pa[4];
    auto loadA = [&](int c) {
        #pragma unroll
        for (int i = 0; i < 4; i++) {
            int idx = tid + i * 128;              // 0..511 = 64 rows x 8 float4
            int r = idx >> 3, k4 = idx & 7;
            pa[i] = *reinterpret_cast<const float4*>(
                A + (size_t)(bm + r) * K + c * 32 + k4 * 4);
        }
    };
    auto storeA = [&](int buf) {
        char* base = smem + buf * 8192;
        #pragma unroll
        for (int i = 0; i < 4; i++) {
            int idx = tid + i * 128;
            int r = idx >> 3, k4 = idx & 7;
            uint32_t sw = SWZ64(r * 64 + k4 * 8);
            float4 v = pa[i];
            __nv_bfloat162 h01 = __floats2bfloat162_rn(v.x, v.y);
            __nv_bfloat162 h23 = __floats2bfloat162_rn(v.z, v.w);
            *reinterpret_cast<uint2*>(base + sw) =
                make_uint2(*(uint32_t*)&h01, *(uint32_t*)&h23);
            if (!two_term) {
                float2 f01 = __bfloat1622float2(h01);
                float2 f23 = __bfloat1622float2(h23);
                __nv_bfloat162 l01 = __floats2bfloat162_rn(v.x - f01.x, v.y - f01.y);
                __nv_bfloat162 l23 = __floats2bfloat162_rn(v.z - f23.x, v.w - f23.y);
                *reinterpret_cast<uint2*>(base + 4096 + sw) =
                    make_uint2(*(uint32_t*)&l01, *(uint32_t*)&l23);
            }
        }
    };

    // fragment addressing
    const uint32_t arow  = (lane & 15);
    const uint32_t aoffb = arow * 64 + ((lane >> 4) << 4);
    const uint32_t axor  = ((arow >> 1) & 3) << 4;
    const uint32_t blrow = (lane & 7) + ((lane >> 4) << 3);
    const uint32_t bseg  = ((uint32_t)((lane >> 3) & 1)) << 4;

    auto compute = [&](int c) {
        const uint32_t sa = sbase + (uint32_t)(c & 1) * 8192;
        const uint32_t sbB = sbase + 16384 + (uint32_t)(c % 3) * 32768;
        #pragma unroll
        for (int ks = 0; ks < 2; ks++) {
            uint32_t Ah[4][4], Al[4][4];
            #pragma unroll
            for (int mt = 0; mt < 4; mt++) {
                uint32_t addr = (sa + aoffb + mt * 1024 + ks * 32) ^ axor;
                LDSM4(Ah[mt], addr);
                if (!two_term) LDSM4(Al[mt], addr + 4096);
            }
            #pragma unroll
            for (int np = 0; np < 4; np++) {
                const uint32_t brow = wn * 64 + np * 16 + blrow;
                uint32_t off = brow * 64 + bseg + ks * 32;
                uint32_t addr = sbB + (off ^ (((brow >> 1) & 3) << 4));
                uint32_t Bh[4], Bl[4];
                LDSM4(Bh, addr);
                LDSM4(Bl, addr + 16384);
                float* d0;
                #pragma unroll
                for (int mt = 0; mt < 4; mt++) {
                    d0 = acc[mt][2 * np];
                    MMA16816(d0, Ah[mt], Bh[0], Bh[1]);
                    d0 = acc[mt][2 * np + 1];
                    MMA16816(d0, Ah[mt], Bh[2], Bh[3]);
                }
                #pragma unroll
                for (int mt = 0; mt < 4; mt++) {
                    d0 = acc[mt][2 * np];
                    MMA16816(d0, Ah[mt], Bl[0], Bl[1]);
                    d0 = acc[mt][2 * np + 1];
                    MMA16816(d0, Ah[mt], Bl[2], Bl[3]);
                }
                if (!two_term) {
                    #pragma unroll
                    for (int mt = 0; mt < 4; mt++) {
                        d0 = acc[mt][2 * np];
                        MMA16816(d0, Al[mt], Bh[0], Bh[1]);
                        d0 = acc[mt][2 * np + 1];
                        MMA16816(d0, Al[mt], Bh[2], Bh[3]);
                    }
                }
            }
        }
    };

    produceB(0, 0); CP_COMMIT();
    produceB(1, 1); CP_COMMIT();
    loadA(0);
    storeA(0);
    for (int c = 0; c < nchunk; c++) {
        CP_WAIT(1);
        __syncthreads();   // publishes storeA(c) and B stage c; guards reuse
        if (c + 1 < nchunk) loadA(c + 1);
        if (c + 2 < nchunk) { produceB(c + 2, (c + 2) % 3); CP_COMMIT(); }
        compute(c);
        if (c + 1 < nchunk) storeA((c + 1) & 1);
    }

    // ---- epilogue: bf16 hi/lo (Cl skipped for kv K-columns) ----
    #pragma unroll
    for (int nt = 0; nt < 8; nt++) {
        const int ncol = bn + wn * 64 + nt * 8 + 2 * (lane & 3);
        const float2 bb = *reinterpret_cast<const float2*>(bias + ncol);
        #pragma unroll
        for (int mt = 0; mt < 4; mt++) {
            const int m0 = bm + mt * 16 + (lane >> 2);
            float v0 = (acc[mt][nt][0] + bb.x) * scale;
            float v1 = (acc[mt][nt][1] + bb.y) * scale;
            float v2 = (acc[mt][nt][2] + bb.x) * scale;
            float v3 = (acc[mt][nt][3] + bb.y) * scale;
            __nv_bfloat162 h01 = __floats2bfloat162_rn(v0, v1);
            __nv_bfloat162 h23 = __floats2bfloat162_rn(v2, v3);
            *reinterpret_cast<uint32_t*>(Ch + (size_t)m0 * N + ncol) = *(uint32_t*)&h01;
            *reinterpret_cast<uint32_t*>(Ch + (size_t)(m0 + 8) * N + ncol) = *(uint32_t*)&h23;
            if (!two_term) {
                float2 f01 = __bfloat1622float2(h01);
                float2 f23 = __bfloat1622float2(h23);
                __nv_bfloat162 l01 = __floats2bfloat162_rn(v0 - f01.x, v1 - f01.y);
                __nv_bfloat162 l23 = __floats2bfloat162_rn(v2 - f23.x, v3 - f23.y);
                *reinterpret_cast<uint32_t*>(Cl + (size_t)m0 * N + ncol) = *(uint32_t*)&l01;
                *reinterpret_cast<uint32_t*>(Cl + (size_t)(m0 + 8) * N + ncol) = *(uint32_t*)&l23;
            }
        }
    }
}

// =============================================================================
// proj GEMM: out = att(fp32) @ Wp^T + bias (3-term, fp32 out). R9-proven.
// =============================================================================
#define PROJ_SMEM 65536

__global__ __launch_bounds__(256, 1)
void gemm_proj(const float* __restrict__ A,
               const __nv_bfloat16* __restrict__ Bth, const __nv_bfloat16* __restrict__ Btl,
               const float* __restrict__ bias, float* __restrict__ Cf,
               int M, int N, int K)
{
    extern __shared__ char smem[];
    const int tid  = threadIdx.x;
    const int lane = tid & 31;
    const int warp = tid >> 5;
    const int wm = warp >> 2;
    const int wn = warp & 3;
    const int bm = blockIdx.y * 128;
    const int bn = blockIdx.x * 128;

    float acc[4][4][4];
    #pragma unroll
    for (int i = 0; i < 4; i++)
        #pragma unroll
        for (int j = 0; j < 4; j++)
            #pragma unroll
            for (int k = 0; k < 4; k++) acc[i][j][k] = 0.f;

    const int nchunk = K >> 5;
    float4 pa[4];
    uint4  pbh[2], pbl[2];

    auto loadg = [&](int c) {
        #pragma unroll
        for (int i = 0; i < 4; i++) {
            int idx = tid + i * 256;
            int r = idx >> 3, k4 = idx & 7;
            pa[i] = *reinterpret_cast<const float4*>(
                A + (size_t)(bm + r) * K + c * 32 + k4 * 4);
        }
        #pragma unroll
        for (int i = 0; i < 2; i++) {
            int idx = tid + i * 256;
            int n = idx >> 2, s = idx & 3;
            const size_t go = (size_t)(bn + n) * K + c * 32 + s * 8;
            pbh[i] = *reinterpret_cast<const uint4*>(Bth + go);
            pbl[i] = *reinterpret_cast<const uint4*>(Btl + go);
        }
    };

    auto storeS = [&](int buf) {
        char* base = smem + buf * 32768;
        #pragma unroll
        for (int i = 0; i < 4; i++) {
            int idx = tid + i * 256;
            int r = idx >> 3, k4 = idx & 7;
            int off = r * 64 + k4 * 8;
            int sw = SWZ64(off);
            float4 v = pa[i];
            __nv_bfloat162 h01 = __floats2bfloat162_rn(v.x, v.y);
            __nv_bfloat162 h23 = __floats2bfloat162_rn(v.z, v.w);
            float2 f01 = __bfloat1622float2(h01);
            float2 f23 = __bfloat1622float2(h23);
            __nv_bfloat162 l01 = __floats2bfloat162_rn(v.x - f01.x, v.y - f01.y);
            __nv_bfloat162 l23 = __floats2bfloat162_rn(v.z - f23.x, v.w - f23.y);
            *reinterpret_cast<uint2*>(base + sw) =
                make_uint2(*(uint32_t*)&h01, *(uint32_t*)&h23);
            *reinterpret_cast<uint2*>(base + 8192 + sw) =
                make_uint2(*(uint32_t*)&l01, *(uint32_t*)&l23);
        }
        #pragma unroll
        for (int i = 0; i < 2; i++) {
            int idx = tid + i * 256;
            int n = idx >> 2, s = idx & 3;
            int off = n * 64 + s * 16;
            int sw = SWZ64(off);
            *reinterpret_cast<uint4*>(base + 16384 + sw) = pbh[i];
            *reinterpret_cast<uint4*>(base + 24576 + sw) = pbl[i];
        }
    };

    const uint32_t sbase = smem_u32(smem);
    const uint32_t arow  = wm * 64 + (lane & 15);
    const uint32_t aoffb = arow * 64 + ((lane >> 4) << 4);
    const uint32_t axor  = ((arow >> 1) & 3) << 4;
    const uint32_t brow  = wn * 32 + (lane & 7) + ((lane >> 4) << 3);
    const uint32_t boffb = brow * 64 + (((lane >> 3) & 1) << 4);
    const uint32_t bxor  = ((brow >> 1) & 3) << 4;

    auto compute = [&](int buf) {
        const uint32_t sa = sbase + buf * 32768;
        #pragma unroll
        for (int ks = 0; ks < 2; ks++) {
            uint32_t Ah[4][4], Al[4][4];
            #pragma unroll
            for (int mt = 0; mt < 4; mt++) {
                uint32_t addr = (sa + aoffb + mt * 1024 + ks * 32) ^ axor;
                LDSM4(Ah[mt], addr);
                LDSM4(Al[mt], addr + 8192);
            }
            uint32_t Bh[2][4], Bl[2][4];
            #pragma unroll
            for (int np = 0; np < 2; np++) {
                uint32_t addr = (sa + 16384 + boffb + np * 1024 + ks * 32) ^ bxor;
                LDSM4(Bh[np], addr);
                LDSM4(Bl[np], addr + 8192);
            }
            #pragma unroll
            for (int mt = 0; mt < 4; mt++)
                #pragma unroll
                for (int nt = 0; nt < 4; nt++) {
                    const int np = nt >> 1, bi = (nt & 1) * 2;
                    MMA16816(acc[mt][nt], Ah[mt], Bh[np][bi], Bh[np][bi + 1]);
                }
            #pragma unroll
            for (int mt = 0; mt < 4; mt++)
                #pragma unroll
                for (int nt = 0; nt < 4; nt++) {
                    const int np = nt >> 1, bi = (nt & 1) * 2;
                    MMA16816(acc[mt][nt], Ah[mt], Bl[np][bi], Bl[np][bi + 1]);
                }
            #pragma unroll
            for (int mt = 0; mt < 4; mt++)
                #pragma unroll
                for (int nt = 0; nt < 4; nt++) {
                    const int np = nt >> 1, bi = (nt & 1) * 2;
                    MMA16816(acc[mt][nt], Al[mt], Bh[np][bi], Bh[np][bi + 1]);
                }
        }
    };

    loadg(0);
    storeS(0);
    __syncthreads();
    for (int c = 0; c < nchunk; c++) {
        if (c + 1 < nchunk) loadg(c + 1);
        compute(c & 1);
        if (c + 1 < nchunk) {
            storeS((c + 1) & 1);
            __syncthreads();
        }
    }

    #pragma unroll
    for (int nt = 0; nt < 4; nt++) {
        const int ncol = bn + wn * 32 + nt * 8 + 2 * (lane & 3);
        const float2 bb = *reinterpret_cast<const float2*>(bias + ncol);
        #pragma unroll
        for (int mt = 0; mt < 4; mt++) {
            const int m0 = bm + wm * 64 + mt * 16 + (lane >> 2);
            *reinterpret_cast<float2*>(Cf + (size_t)m0 * N + ncol) =
                make_float2(acc[mt][nt][0] + bb.x, acc[mt][nt][1] + bb.y);
            *reinterpret_cast<float2*>(Cf + (size_t)(m0 + 8) * N + ncol) =
                make_float2(acc[mt][nt][2] + bb.x, acc[mt][nt][3] + bb.y);
        }
    }
}

// =============================================================================
// HMMA flash attention (R9-proven). 128 threads / 4 warps / 64 Q-rows; grid 256;
// 2 CTAs per SM. QK = (Qh+Ql)*Kh; PV = 3-term. Stage 24KB (Kh|Vh|Vl), ring @0/24K/48K;
// Q hi @73728, lo @81920. smem = 88KB.
// =============================================================================
#define ATTN_SMEM 90112

__global__ __launch_bounds__(128, 2)
void attn2(const __nv_bfloat16* __restrict__ qsh, const __nv_bfloat16* __restrict__ qsl,
           const __nv_bfloat16* __restrict__ kvh, const __nv_bfloat16* __restrict__ kvl,
           float* __restrict__ attf)
{
    extern __shared__ char smem[];
    const uint32_t sb = smem_u32(smem);
    const int tid = threadIdx.x, lane = tid & 31, warp = tid >> 5;
    const int bid = blockIdx.x;        // b*32 + h*4 + lt
    const int lt = bid & 3;
    const int h  = (bid >> 2) & 7;
    const int b  = bid >> 5;
    const int l0 = lt * 64;

    #pragma unroll
    for (int i = 0; i < 4; i++) {
        int idx = tid + i * 128;
        int r = idx >> 3, sg = idx & 7;
        uint32_t sw = SWZ128(r * 128 + sg * 16);
        size_t g = (size_t)(b * L_ + l0 + r) * 512 + h * 64 + sg * 8;
        CP16(sb + 73728 + sw, qsh + g);
        CP16(sb + 81920 + sw, qsl + g);
    }
    CP_COMMIT();
    CP_WAIT(0);
    __syncthreads();

    uint32_t Qh[4][4], Ql[4][4];
    {
        const int arow = warp * 16 + (lane & 15);
        const uint32_t abase = sb + 73728 + arow * 128;
        const uint32_t axor = (arow & 7) << 4;
        #pragma unroll
        for (int kc = 0; kc < 4; kc++) {
            uint32_t o = ((((uint32_t)(lane >> 4) << 4) + kc * 32)) ^ axor;
            LDSM4(Qh[kc], abase + o);
            LDSM4(Ql[kc], abase + 8192 + o);
        }
    }
    __syncthreads();

    auto produce = [&](int c, int s) {
        const uint32_t base = sb + (uint32_t)s * 24576;
        #pragma unroll
        for (int i = 0; i < 4; i++) {
            int idx = tid + i * 128;
            int r = idx >> 3, sg = idx & 7;
            uint32_t sw = SWZ128(r * 128 + sg * 16);
            size_t g = (size_t)(b * T_ + c * 64 + r) * 1024 + h * 64 + sg * 8;
            CP16(base + sw,         kvh + g);          // Kh
            CP16(base + 8192 + sw,  kvh + g + 512);    // Vh
            CP16(base + 16384 + sw, kvl + g + 512);    // Vl
        }
    };
    produce(0, 0); CP_COMMIT();
    produce(1, 1); CP_COMMIT();

    float mrow[2] = { -CUDART_INF_F, -CUDART_INF_F };
    float lsum[2] = { 0.f, 0.f };
    float O[8][4];
    #pragma unroll
    for (int i = 0; i < 8; i++)
        #pragma unroll
        for (int j = 0; j < 4; j++) O[i][j] = 0.f;

    const int klrow = (lane & 7) + ((lane >> 4) << 3);
    const uint32_t kseg = ((uint32_t)((lane >> 3) & 1)) << 4;
    const int vlrow = (lane & 7) + (((lane >> 3) & 1) << 3);
    const int vseg_half = lane >> 4;

    int bufc = 0;
    for (int c = 0; c < T_ / 64; c++) {
        CP_WAIT(1);
        __syncthreads();
        const uint32_t kb = sb + (uint32_t)bufc * 24576;

        float S[8][4];
        #pragma unroll
        for (int i = 0; i < 8; i++)
            #pragma unroll
            for (int j = 0; j < 4; j++) S[i][j] = 0.f;

        #pragma unroll
        for (int npp = 0; npp < 2; npp++) {
            #pragma unroll
            for (int kc = 0; kc < 4; kc++) {
                const int brow0 = (2 * npp) * 16 + klrow;
                const int brow1 = (2 * npp + 1) * 16 + klrow;
                uint32_t a0 = kb + brow0 * 128 + ((kseg + kc * 32) ^ ((brow0 & 7) << 4));
                uint32_t a1 = kb + brow1 * 128 + ((kseg + kc * 32) ^ ((brow1 & 7) << 4));
                uint32_t Bh0[4], Bh1[4];
                LDSM4(Bh0, a0);
                LDSM4(Bh1, a1);
                float* s0 = S[4 * npp];     float* s1 = S[4 * npp + 1];
                float* s2 = S[4 * npp + 2]; float* s3 = S[4 * npp + 3];
                MMA16816(s0, Qh[kc], Bh0[0], Bh0[1]);
                MMA16816(s1, Qh[kc], Bh0[2], Bh0[3]);
                MMA16816(s2, Qh[kc], Bh1[0], Bh1[1]);
                MMA16816(s3, Qh[kc], Bh1[2], Bh1[3]);
                MMA16816(s0, Ql[kc], Bh0[0], Bh0[1]);
                MMA16816(s1, Ql[kc], Bh0[2], Bh0[3]);
                MMA16816(s2, Ql[kc], Bh1[0], Bh1[1]);
                MMA16816(s3, Ql[kc], Bh1[2], Bh1[3]);
            }
        }

        float mxA = -CUDART_INF_F, mxB = -CUDART_INF_F;
        #pragma unroll
        for (int nt = 0; nt < 8; nt++) {
            mxA = fmaxf(mxA, fmaxf(S[nt][0], S[nt][1]));
            mxB = fmaxf(mxB, fmaxf(S[nt][2], S[nt][3]));
        }
        #pragma unroll
        for (int o = 1; o <= 2; o <<= 1) {
            mxA = fmaxf(mxA, __shfl_xor_sync(0xffffffffu, mxA, o));
            mxB = fmaxf(mxB, __shfl_xor_sync(0xffffffffu, mxB, o));
        }
        const float mnA = fmaxf(mrow[0], mxA);
        const float mnB = fmaxf(mrow[1], mxB);
        const float alphaA = exp2f(mrow[0] - mnA);
        const float alphaB = exp2f(mrow[1] - mnB);
        mrow[0] = mnA; mrow[1] = mnB;

        uint32_t Ph[4][4], Pl[4][4];
        float sumA = 0.f, sumB = 0.f;
        #pragma unroll
        for (int nt = 0; nt < 8; nt++) {
            float p0 = exp2f(S[nt][0] - mnA);
            float p1 = exp2f(S[nt][1] - mnA);
            float p2 = exp2f(S[nt][2] - mnB);
            float p3 = exp2f(S[nt][3] - mnB);
            sumA += p0 + p1; sumB += p2 + p3;
            __nv_bfloat162 hA = __floats2bfloat162_rn(p0, p1);
            __nv_bfloat162 hB = __floats2bfloat162_rn(p2, p3);
            float2 fA = __bfloat1622float2(hA);
            float2 fB = __bfloat1622float2(hB);
            __nv_bfloat162 lA = __floats2bfloat162_rn(p0 - fA.x, p1 - fA.y);
            __nv_bfloat162 lB = __floats2bfloat162_rn(p2 - fB.x, p3 - fB.y);
            const int kc = nt >> 1, ri = (nt & 1) * 2;
            Ph[kc][ri]     = *(uint32_t*)&hA;
            Ph[kc][ri + 1] = *(uint32_t*)&hB;
            Pl[kc][ri]     = *(uint32_t*)&lA;
            Pl[kc][ri + 1] = *(uint32_t*)&lB;
        }
        #pragma unroll
        for (int o = 1; o <= 2; o <<= 1) {
            sumA += __shfl_xor_sync(0xffffffffu, sumA, o);
            sumB += __shfl_xor_sync(0xffffffffu, sumB, o);
        }
        lsum[0] = lsum[0] * alphaA + sumA;
        lsum[1] = lsum[1] * alphaB + sumB;
        #pragma unroll
        for (int nt = 0; nt < 8; nt++) {
            O[nt][0] *= alphaA; O[nt][1] *= alphaA;
            O[nt][2] *= alphaB; O[nt][3] *= alphaB;
        }

        #pragma unroll
        for (int kc = 0; kc < 4; kc++) {
            const int vrow = kc * 16 + vlrow;
            const uint32_t vbase = kb + 8192 + vrow * 128;
            const uint32_t vxor = (vrow & 7) << 4;
            #pragma unroll
            for (int ngp = 0; ngp < 2; ngp++) {
                uint32_t o0 = ((uint32_t)((4 * ngp + vseg_half) << 4)) ^ vxor;
                uint32_t o1 = ((uint32_t)((4 * ngp + 2 + vseg_half) << 4)) ^ vxor;
                uint32_t Vh0[4], Vl0[4], Vh1[4], Vl1[4];
                LDSM4T(Vh0, vbase + o0); LDSM4T(Vl0, vbase + 8192 + o0);
                LDSM4T(Vh1, vbase + o1); LDSM4T(Vl1, vbase + 8192 + o1);
                float* d0 = O[4 * ngp];     float* d1 = O[4 * ngp + 1];
                float* d2 = O[4 * ngp + 2]; float* d3 = O[4 * ngp + 3];
                MMA16816(d0, Ph[kc], Vh0[0], Vh0[1]);
                MMA16816(d1, Ph[kc], Vh0[2], Vh0[3]);
                MMA16816(d2, Ph[kc], Vh1[0], Vh1[1]);
                MMA16816(d3, Ph[kc], Vh1[2], Vh1[3]);
                MMA16816(d0, Ph[kc], Vl0[0], Vl0[1]);
                MMA16816(d1, Ph[kc], Vl0[2], Vl0[3]);
                MMA16816(d2, Ph[kc], Vl1[0], Vl1[1]);
                MMA16816(d3, Ph[kc], Vl1[2], Vl1[3]);
                MMA16816(d0, Pl[kc], Vh0[0], Vh0[1]);
                MMA16816(d1, Pl[kc], Vh0[2], Vh0[3]);
                MMA16816(d2, Pl[kc], Vh1[0], Vh1[1]);
                MMA16816(d3, Pl[kc], Vh1[2], Vh1[3]);
            }
        }

        if (c + 2 < T_ / 64) produce(c + 2, (bufc + 2) % 3);
        CP_COMMIT();
        bufc = (bufc + 1) % 3;
    }
    CP_WAIT(0);

    const float invA = 1.0f / lsum[0];
    const float invB = 1.0f / lsum[1];
    const int rowA = b * L_ + l0 + warp * 16 + (lane >> 2);
    #pragma unroll
    for (int nt = 0; nt < 8; nt++) {
        const int col = h * 64 + nt * 8 + (lane & 3) * 2;
        *reinterpret_cast<float2*>(attf + (size_t)rowA * D_ + col) =
            make_float2(O[nt][0] * invA, O[nt][1] * invA);
        *reinterpret_cast<float2*>(attf + (size_t)(rowA + 8) * D_ + col) =
            make_float2(O[nt][2] * invB, O[nt][3] * invB);
    }
}

// =============================================================================
// launch
// =============================================================================
extern "C" void kernel_launch(void* const* d_in, const int* in_sizes, int n_in,
                              void* d_out, int out_size)
{
    const float* x     = (const float*)d_in[0];
    const float* query = (const float*)d_in[1];
    const float* Wq    = (const float*)d_in[2];
    const float* bq    = (const float*)d_in[3];
    const float* Wkv   = (const float*)d_in[4];
    const float* bkv   = (const float*)d_in[5];
    const float* Wproj = (const float*)d_in[6];
    const float* bproj = (const float*)d_in[7];
    float* out = (float*)d_out;

    __nv_bfloat16 *qh, *ql, *kvh, *kvl;
    float* att;
    __nv_bfloat16 *wkvh, *wkvl, *wqh, *wql, *wph, *wpl;
    cudaGetSymbolAddress((void**)&qh,  g_qh);   cudaGetSymbolAddress((void**)&ql,  g_ql);
    cudaGetSymbolAddress((void**)&kvh, g_kvh);  cudaGetSymbolAddress((void**)&kvl, g_kvl);
    cudaGetSymbolAddress((void**)&att, g_att);
    cudaGetSymbolAddress((void**)&wkvh, g_wkv_h); cudaGetSymbolAddress((void**)&wkvl, g_wkv_l);
    cudaGetSymbolAddress((void**)&wqh,  g_wq_h);  cudaGetSymbolAddress((void**)&wql,  g_wq_l);
    cudaGetSymbolAddress((void**)&wph,  g_wp_h);  cudaGetSymbolAddress((void**)&wpl,  g_wp_l);

    cudaFuncSetAttribute(gemm_kvq,  cudaFuncAttributeMaxDynamicSharedMemorySize, GEMM_SMEM);
    cudaFuncSetAttribute(gemm_proj, cudaFuncAttributeMaxDynamicSharedMemorySize, PROJ_SMEM);
    cudaFuncSetAttribute(attn2,     cudaFuncAttributeMaxDynamicSharedMemorySize, ATTN_SMEM);

    const float cscale = 0.125f * 1.4426950408889634f;

    split_w<<<(512 * 1024 + 255) / 256, 256>>>(Wkv,   wkvh, wkvl, 512, 1024);
    split_w<<<(512 * 512  + 255) / 256, 256>>>(Wq,    wqh,  wql,  512, 512);
    split_w<<<(512 * 512  + 255) / 256, 256>>>(Wproj, wph,  wpl,  512, 512);

    // fused kv+q GEMM: 64x256 CTAs, 2 per SM
    gemm_kvq<<<dim3(4, 1056), 128, GEMM_SMEM>>>(
        x, query, wkvh, wkvl, wqh, wql, bkv, bq, kvh, kvl, qh, ql, cscale);
    // attention -> att fp32 (grid 256, 128 threads, 2 CTAs/SM)
    attn2<<<B_ * H_ * (L_ / 64), 128, ATTN_SMEM>>>(qh, ql, kvh, kvl, att);
    // out = att @ Wproj + bproj : [2048, 512] fp32
    gemm_proj<<<dim3(D_ / 128, (B_ * L_) / 128), 256, PROJ_SMEM>>>(
        att, wph, wpl, bproj, out, B_ * L_, D_, D_);
}